// round 6
// baseline (speedup 1.0000x reference)
#include <cuda_runtime.h>
#include <math.h>

#define NN 2048
#define DD 128
#define KK 16
#define EE 8192
#define ROWS 2064               // 2048 phi rows + 16 beta rows
#define CNT 262144.0

__device__ float g_s[2][ROWS*DD];     // phi_s rows 0..2047, beta_s rows 2048..2063
__device__ float g_h[2][ROWS*DD];
__device__ float g_G[ROWS*512];
__device__ float g_Hm[ROWS*256];
__device__ float g_M[NN*KK];          // n-major, k contiguous
__device__ float g_W1n[512*256], g_W1c[512*256];
__device__ float g_b1n[512],     g_b1c[512];
__device__ float g_W2n[256*DD],  g_W2c[256*DD];
__device__ float g_b2n[256],     g_b2c[256];
__device__ float g_am[DD];
__device__ double g_acc[5];           // nll, kldz, kldb, kldp, kld_alpha
__device__ float g_Mmax;

__device__ __forceinline__ float fsig(float x){ return 1.f/(1.f+__expf(-x)); }
__device__ __forceinline__ float ftanh(float x){
    float e=__expf(fminf(fmaxf(2.f*x,-30.f),30.f)); return (e-1.f)/(e+1.f); }
__device__ __forceinline__ float fsoftplus(float x){
    return fmaxf(x,0.f)+log1pf(__expf(-fabsf(x))); }
__device__ __forceinline__ void atomicMaxF(float* a, float v){
    int cur=__float_as_int(*a);
    while(__int_as_float(cur)<v){ int as=cur;
        cur=atomicCAS((int*)a,as,__float_as_int(v));
        if(cur==as) break; }
}

__global__ void k_init0(const int* sidx,const float* am,const float* as){
    int t=threadIdx.x; int s=sidx[0];
    __shared__ float red[128];
    float m=am[(size_t)s*DD+t];
    float sd=fsoftplus(as[(size_t)s*DD+t]);
    g_am[t]=m;
    red[t]=0.5f*(-2.f*logf(sd)+sd*sd+m*m-1.f);
    __syncthreads();
    for(int o=64;o;o>>=1){ if(t<o) red[t]+=red[t+o]; __syncthreads(); }
    if(t==0){ g_acc[4]=(double)red[0]; g_acc[0]=g_acc[1]=g_acc[2]=g_acc[3]=0.0; }
}

__global__ void k_initW(const float* WihN,const float* WhhN,const float* bihN,const float* bhhN,
                        const float* WihC,const float* WhhC,const float* bihC,const float* bhhC,
                        const float* Wpm,const float* bpm,const float* Wps,const float* bps,
                        const float* Wbm,const float* bbm,const float* Wbs,const float* bbs){
    int i=blockIdx.x*256+threadIdx.x;
    if(i<131072){                                  // W1 (both paths), 512 x 256
        int j=i>>8, c=i&255; float vn,vc;
        if(j<256){
            vn = c<128 ? WihN[j*256+c]+WihN[j*256+128+c] : WhhN[j*128+c-128];
            vc = c<128 ? WihC[j*256+c]+WihC[j*256+128+c] : WhhC[j*128+c-128];
        } else if(j<384){
            vn = c<128 ? WihN[j*256+c]+WihN[j*256+128+c] : 0.f;
            vc = c<128 ? WihC[j*256+c]+WihC[j*256+128+c] : 0.f;
        } else { int jr=j-128;
            vn = c<128 ? 0.f : WhhN[jr*128+c-128];
            vc = c<128 ? 0.f : WhhC[jr*128+c-128];
        }
        g_W1n[i]=vn; g_W1c[i]=vc;
    } else if(i<163840){                           // W2, 256 x 128
        int o=i-131072, r=o>>7, c=o&127;
        g_W2n[o] = r<128 ? Wpm[r*128+c] : Wps[(r-128)*128+c];
        g_W2c[o] = r<128 ? Wbm[r*128+c] : Wbs[(r-128)*128+c];
    } else if(i<164352){                           // b1
        int j=i-163840; float bn,bc;
        if(j<256){ bn=bihN[j]+bhhN[j]; bc=bihC[j]+bhhC[j]; }
        else if(j<384){ bn=bihN[j]; bc=bihC[j]; }
        else { bn=bhhN[j-128]; bc=bhhC[j-128]; }
        g_b1n[j]=bn; g_b1c[j]=bc;
    } else if(i<164608){                           // b2
        int j=i-164352;
        g_b2n[j] = j<128 ? bpm[j] : bps[j-128];
        g_b2c[j] = j<128 ? bbm[j] : bbs[j-128];
    }
}

__global__ void k_initS(const float* Wp,const float* bp,const float* Wb,const float* bb){
    __shared__ float am[DD];
    int tid=threadIdx.x;
    if(tid<DD) am[tid]=g_am[tid];
    __syncthreads();
    int i=blockIdx.x*256+tid; if(i>=ROWS*DD) return;
    const float* wr; float bias;
    if(i<NN*DD){ wr=Wp+(size_t)i*DD; bias=bp[i]; }
    else { int o=i-NN*DD; wr=Wb+(size_t)o*DD; bias=bb[o]; }
    const float4* w4=(const float4*)wr; const float4* a4=(const float4*)am;
    float acc=bias;
    #pragma unroll 8
    for(int q=0;q<32;q++){ float4 w=w4[q],a=a4[q];
        acc+=w.x*a.x+w.y*a.y+w.z*a.z+w.w*a.w; }
    g_s[0][i]=acc; g_h[0][i]=0.f;
}

// C = A @ W^T + b, tiled 32x64, k-vectorized float4 smem reads.
template<int KD>
__global__ void k_gemm(int pp){
    extern __shared__ float sm[];
    const int LDA = KD+4;                 // pad keeps 16B alignment (KD%4==0)
    float* As=sm;                         // [32][LDA]
    float* Ws=sm+32*LDA;                  // [64][LDA]
    int mT=blockIdx.x, pT=blockIdx.y, tid=threadIdx.x;
    int beta=(mT==64);
    int row0=beta?2048:mT*32, rowsEff=beta?16:32, p0=pT*64;
    const float *A0,*A1,*W,*bias; float* C; int ldC;
    if(KD==256){ A0=g_s[pp]; A1=g_h[pp]; W=beta?g_W1c:g_W1n; bias=beta?g_b1c:g_b1n; C=g_G; ldC=512; }
    else       { A0=g_h[1-pp]; A1=0;     W=beta?g_W2c:g_W2n; bias=beta?g_b2c:g_b2n; C=g_Hm; ldC=256; }
    for(int i=tid;i<32*KD;i+=256){ int r=i/KD,c=i-r*KD; float v=0.f;
        if(r<rowsEff){ int g=(row0+r)*DD+(c&127); v=(KD==256&&c>=128)?A1[g]:A0[g]; }
        As[r*LDA+c]=v; }
    for(int i=tid;i<64*KD;i+=256){ int r=i/KD,c=i-r*KD;
        Ws[r*LDA+c]=W[(size_t)(p0+r)*KD+c]; }
    __syncthreads();
    int rm=(tid&7)*4, cp=(tid>>3)*2;
    float a00=0,a01=0,a10=0,a11=0,a20=0,a21=0,a30=0,a31=0;
    const float4* X0=(const float4*)(As+(rm+0)*LDA);
    const float4* X1=(const float4*)(As+(rm+1)*LDA);
    const float4* X2=(const float4*)(As+(rm+2)*LDA);
    const float4* X3=(const float4*)(As+(rm+3)*LDA);
    const float4* W0=(const float4*)(Ws+(cp+0)*LDA);
    const float4* W1=(const float4*)(Ws+(cp+1)*LDA);
    #pragma unroll 8
    for(int d4=0;d4<KD/4;d4++){
        float4 w0=W0[d4], w1=W1[d4];
        float4 x0=X0[d4], x1=X1[d4], x2=X2[d4], x3=X3[d4];
        a00+=x0.x*w0.x+x0.y*w0.y+x0.z*w0.z+x0.w*w0.w;
        a01+=x0.x*w1.x+x0.y*w1.y+x0.z*w1.z+x0.w*w1.w;
        a10+=x1.x*w0.x+x1.y*w0.y+x1.z*w0.z+x1.w*w0.w;
        a11+=x1.x*w1.x+x1.y*w1.y+x1.z*w1.z+x1.w*w1.w;
        a20+=x2.x*w0.x+x2.y*w0.y+x2.z*w0.z+x2.w*w0.w;
        a21+=x2.x*w1.x+x2.y*w1.y+x2.z*w1.z+x2.w*w1.w;
        a30+=x3.x*w0.x+x3.y*w0.y+x3.z*w0.z+x3.w*w0.w;
        a31+=x3.x*w1.x+x3.y*w1.y+x3.z*w1.z+x3.w*w1.w;
    }
    float b0=bias[p0+cp], b1=bias[p0+cp+1];
    float r0[4]={a00,a10,a20,a30}, r1[4]={a01,a11,a21,a31};
    for(int i=0;i<4;i++){ int r=rm+i; if(r<rowsEff){
        C[(size_t)(row0+r)*ldC+p0+cp]=r0[i]+b0;
        C[(size_t)(row0+r)*ldC+p0+cp+1]=r1[i]+b1; } }
}

__global__ void k_act(int pp){
    int i=blockIdx.x*256+threadIdx.x; if(i>=ROWS*DD) return;
    int row=i>>7, d=i&127;
    const float* G=g_G+(size_t)row*512;
    float r=fsig(G[d]), z=fsig(G[128+d]);
    float nn=ftanh(G[256+d]+r*G[384+d]);
    g_h[1-pp][i]=(1.f-z)*nn+z*g_h[pp][i];
}

__global__ void k_sample(int pp,const float* ept,const float* ebt){
    int i=blockIdx.x*256+threadIdx.x;
    if(i==0) g_Mmax=-1e30f;               // reset for k_matM (next launch)
    double kp=0,kb=0;
    if(i<ROWS*DD){
        int row=i>>7, d=i&127;
        float mean=g_Hm[row*256+d];
        float sd=fsoftplus(g_Hm[row*256+128+d]);
        float prior=g_s[pp][i];
        float e = row<NN ? ept[i] : ebt[(row-NN)*DD+d];
        g_s[1-pp][i]=mean+sd*e;
        float dm=mean-prior;
        if(row<NN) kp=0.5*(-2.0*(double)logf(sd)+(double)sd*sd+(double)dm*dm-1.0);
        else       kb=0.5*(2.0*(-2.302585092994046-(double)logf(sd))
                          +((double)sd*sd+(double)dm*dm)*100.0-1.0);
    }
    __shared__ double r1[256],r2[256];
    int t=threadIdx.x; r1[t]=kp; r2[t]=kb; __syncthreads();
    for(int o=128;o;o>>=1){ if(t<o){ r1[t]+=r1[t+o]; r2[t]+=r2[t+o]; } __syncthreads(); }
    if(t==0){ if(r1[0]!=0.0) atomicAdd(&g_acc[3],r1[0]);
              if(r2[0]!=0.0) atomicAdd(&g_acc[2],r2[0]); }
}

__global__ void k_matM(int pp,const float* Wdec){
    __shared__ float bs[KK*DD];
    __shared__ float wm[8];
    int t=threadIdx.x, po=1-pp;
    for(int i=t;i<KK*DD;i+=256) bs[i]=g_s[po][NN*DD+i];
    __syncthreads();
    int n=blockIdx.x*256+t;
    float acc[KK];
    #pragma unroll
    for(int k=0;k<KK;k++) acc[k]=0.f;
    const float4* w4=(const float4*)(Wdec+(size_t)n*DD);
    for(int q=0;q<32;q++){ float4 w=w4[q];
        #pragma unroll
        for(int k=0;k<KK;k++){ float4 b=((const float4*)(bs+k*DD))[q];
            acc[k]+=w.x*b.x+w.y*b.y+w.z*b.z+w.w*b.w; } }
    float mx=acc[0];
    #pragma unroll
    for(int k=0;k<KK;k++){ g_M[n*KK+k]=acc[k]; mx=fmaxf(mx,acc[k]); }
    for(int o=16;o;o>>=1) mx=fmaxf(mx,__shfl_xor_sync(0xffffffffu,mx,o));
    if((t&31)==0) wm[t>>5]=mx;
    __syncthreads();
    if(t==0){ float b=wm[0];
        #pragma unroll
        for(int j=1;j<8;j++) b=fmaxf(b,wm[j]);
        atomicMaxF(&g_Mmax,b); }
}

// 128 edges/block, 256 threads: thread pair (li, li+128) splits the N-scan.
__global__ void k_edgelse(int pp,const int* edt,const float* ut,const float* Wpi){
    extern __shared__ float sm[];
    float* Ms=sm; float* Pt=sm+NN*KK; float* Bt=Pt+DD*KK;
    __shared__ float s_s[256], s_vc[256];
    __shared__ double rd[256];
    int t=threadIdx.x, po=1-pp;
    int half=t>>7, li=t&127;
    for(int i=t;i<NN*KK;i+=256) Ms[i]=g_M[i];
    for(int i=t;i<DD*KK;i+=256){ int d=i>>4,k=i&15;
        Pt[i]=Wpi[k*DD+d]; Bt[i]=g_s[po][NN*DD+k*DD+d]; }
    __syncthreads();
    int e=blockIdx.x*128+li, w,c;
    if(e<EE){ w=edt[2*e]; c=edt[2*e+1]; } else { int e2=e-EE; w=edt[2*e2+1]; c=edt[2*e2]; }
    const float4* pw4=(const float4*)(g_s[po]+(size_t)w*DD);
    const float4* pc4=(const float4*)(g_s[po]+(size_t)c*DD);
    float lq[KK],lp[KK];
    #pragma unroll
    for(int k=0;k<KK;k++){ lq[k]=0.f; lp[k]=0.f; }
    for(int q=0;q<32;q++){
        float4 a=pw4[q], b=pc4[q];
        float aw[4]={a.x,a.y,a.z,a.w};
        float pr[4]={a.x*b.x,a.y*b.y,a.z*b.z,a.w*b.w};
        #pragma unroll
        for(int j=0;j<4;j++){ int d=q*4+j;
            const float4* P4=(const float4*)(Pt+d*KK);
            const float4* B4=(const float4*)(Bt+d*KK);
            #pragma unroll
            for(int h=0;h<4;h++){
                float4 P=P4[h], B=B4[h];
                lq[4*h+0]+=pr[j]*P.x; lq[4*h+1]+=pr[j]*P.y;
                lq[4*h+2]+=pr[j]*P.z; lq[4*h+3]+=pr[j]*P.w;
                lp[4*h+0]+=aw[j]*B.x; lp[4*h+1]+=aw[j]*B.y;
                lp[4*h+2]+=aw[j]*B.z; lp[4*h+3]+=aw[j]*B.w;
            }
        }
    }
    float mq=-3e38f,mp=-3e38f;
    #pragma unroll
    for(int k=0;k<KK;k++){ mq=fmaxf(mq,lq[k]); mp=fmaxf(mp,lp[k]); }
    float sq=0,sp=0;
    #pragma unroll
    for(int k=0;k<KK;k++){ sq+=__expf(lq[k]-mq); sp+=__expf(lp[k]-mp); }
    float lsq=__logf(sq), lsp=__logf(sp), kz=0.f;
    #pragma unroll
    for(int k=0;k<KK;k++){ float lpo=lq[k]-mq-lsq;
        kz+=__expf(lpo)*(lpo-(lp[k]-mp-lsp)); }
    const float4* u4=(const float4*)(ut+(size_t)e*KK);
    float ze[KK];
    #pragma unroll
    for(int q=0;q<4;q++){ float4 u=u4[q]; float uu[4]={u.x,u.y,u.z,u.w};
        #pragma unroll
        for(int j=0;j<4;j++)
            ze[q*4+j]=lq[q*4+j]-__logf(-__logf(uu[j]+1e-10f)+1e-10f); }
    float mz=-3e38f;
    #pragma unroll
    for(int k=0;k<KK;k++) mz=fmaxf(mz,ze[k]);
    float sz=0;
    #pragma unroll
    for(int k=0;k<KK;k++){ ze[k]=__expf(ze[k]-mz); sz+=ze[k]; }
    float inv=1.f/sz;
    #pragma unroll
    for(int k=0;k<KK;k++) ze[k]*=inv;
    // fixed-shift logsumexp over this half's n-range
    float Mmax=g_Mmax;
    float s0=0.f,s1=0.f,vc=0.f;
    int n0=half<<10;
    for(int n=n0;n<n0+1024;n+=2){
        const float4* m0=(const float4*)(Ms+n*KK);
        const float4* m1=(const float4*)(Ms+(n+1)*KK);
        float4 A0=m0[0],A1=m0[1],A2=m0[2],A3=m0[3];
        float4 C0=m1[0],C1=m1[1],C2=m1[2],C3=m1[3];
        float v0 = ze[0]*A0.x+ze[1]*A0.y+ze[2]*A0.z+ze[3]*A0.w
                 + ze[4]*A1.x+ze[5]*A1.y+ze[6]*A1.z+ze[7]*A1.w
                 + ze[8]*A2.x+ze[9]*A2.y+ze[10]*A2.z+ze[11]*A2.w
                 + ze[12]*A3.x+ze[13]*A3.y+ze[14]*A3.z+ze[15]*A3.w;
        float v1 = ze[0]*C0.x+ze[1]*C0.y+ze[2]*C0.z+ze[3]*C0.w
                 + ze[4]*C1.x+ze[5]*C1.y+ze[6]*C1.z+ze[7]*C1.w
                 + ze[8]*C2.x+ze[9]*C2.y+ze[10]*C2.z+ze[11]*C2.w
                 + ze[12]*C3.x+ze[13]*C3.y+ze[14]*C3.z+ze[15]*C3.w;
        s0+=__expf(v0-Mmax); s1+=__expf(v1-Mmax);
        if(n==c)   vc=v0;
        if(n+1==c) vc=v1;
    }
    s_s[t]=s0+s1; s_vc[t]=vc;
    __syncthreads();
    double nll=0.0,kzd=0.0;
    if(half==0){
        float st=s_s[t]+s_s[t+128];
        float vct=s_vc[t]+s_vc[t+128];     // exactly one half sets it; other is 0
        nll=(double)(-(vct-Mmax-__logf(st)));
        kzd=(double)kz;
    }
    rd[t]=nll; __syncthreads();
    for(int o=128;o;o>>=1){ if(t<o) rd[t]+=rd[t+o]; __syncthreads(); }
    if(t==0) atomicAdd(&g_acc[0],rd[0]);
    __syncthreads();
    rd[t]=kzd; __syncthreads();
    for(int o=128;o;o>>=1){ if(t<o) rd[t]+=rd[t+o]; __syncthreads(); }
    if(t==0) atomicAdd(&g_acc[1],rd[0]);
}

__global__ void k_out(float* out){
    out[0]=(float)(g_acc[0]/CNT);
    out[1]=(float)(g_acc[1]/CNT);
    out[2]=(float)(16.0*g_acc[4]/CNT);
    out[3]=(float)(g_acc[2]/CNT);
    out[4]=(float)(g_acc[3]/CNT);
}

extern "C" void kernel_launch(void* const* d_in,const int* in_sizes,int n_in,
                              void* d_out,int out_size){
    const int*   edges=(const int*)d_in[0];
    const int*   sidx =(const int*)d_in[1];
    const float* epp  =(const float*)d_in[2];
    const float* epb  =(const float*)d_in[3];
    const float* ug   =(const float*)d_in[4];
    const float* amean=(const float*)d_in[5];
    const float* astd =(const float*)d_in[6];
    const float* Ws2p =(const float*)d_in[7];  const float* bs2p=(const float*)d_in[8];
    const float* Ws2b =(const float*)d_in[9];  const float* bs2b=(const float*)d_in[10];
    const float* Wbm  =(const float*)d_in[11]; const float* bbm =(const float*)d_in[12];
    const float* Wbs  =(const float*)d_in[13]; const float* bbs =(const float*)d_in[14];
    const float* Wpm  =(const float*)d_in[15]; const float* bpm =(const float*)d_in[16];
    const float* Wps  =(const float*)d_in[17]; const float* bps =(const float*)d_in[18];
    const float* Wpi  =(const float*)d_in[19];
    const float* WihN =(const float*)d_in[20]; const float* WhhN=(const float*)d_in[21];
    const float* bihN =(const float*)d_in[22]; const float* bhhN=(const float*)d_in[23];
    const float* WihC =(const float*)d_in[24]; const float* WhhC=(const float*)d_in[25];
    const float* bihC =(const float*)d_in[26]; const float* bhhC=(const float*)d_in[27];
    const float* Wdec =(const float*)d_in[28];
    float* out=(float*)d_out;

    int smem1 = (32*(256+4)+64*(256+4))*4;   // 99840
    int smem2 = (32*(128+4)+64*(128+4))*4;   // 50688
    int smemE = (NN*KK+2*DD*KK)*4;           // 147456
    cudaFuncSetAttribute(k_gemm<256>,cudaFuncAttributeMaxDynamicSharedMemorySize,smem1);
    cudaFuncSetAttribute(k_gemm<128>,cudaFuncAttributeMaxDynamicSharedMemorySize,smem2);
    cudaFuncSetAttribute(k_edgelse,  cudaFuncAttributeMaxDynamicSharedMemorySize,smemE);

    k_init0<<<1,128>>>(sidx,amean,astd);
    k_initW<<<644,256>>>(WihN,WhhN,bihN,bhhN,WihC,WhhC,bihC,bhhC,
                         Wpm,bpm,Wps,bps,Wbm,bbm,Wbs,bbs);
    k_initS<<<1033,256>>>(Ws2p,bs2p,Ws2b,bs2b);
    for(int t=0;t<16;t++){
        int pp=t&1;
        k_gemm<256><<<dim3(65,8),256,smem1>>>(pp);
        k_act<<<1033,256>>>(pp);
        k_gemm<128><<<dim3(65,4),256,smem2>>>(pp);
        k_sample<<<1033,256>>>(pp, epp+(size_t)t*NN*DD, epb+(size_t)t*KK*DD);
        k_matM<<<8,256>>>(pp, Wdec);
        k_edgelse<<<128,256,smemE>>>(pp, edges+(size_t)t*EE*2,
                                     ug+(size_t)t*2*EE*KK, Wpi);
    }
    k_out<<<1,1>>>(out);
}

// round 8
// speedup vs baseline: 2.1192x; 2.1192x over previous
#include <cuda_runtime.h>
#include <math.h>

#define NN 2048
#define DD 128
#define KK 16
#define EE 8192
#define TWOE 16384
#define ROWS 2064               // 2048 phi rows + 16 beta rows
#define CNT 262144.0

__device__ float g_s[2][ROWS*DD];     // phi_s rows 0..2047, beta_s rows 2048..2063
__device__ float g_h[2][ROWS*DD];
__device__ float g_G[ROWS*512];
__device__ float g_Hm[ROWS*256];
__device__ float g_M[NN*KK];          // n-major, k contiguous
__device__ float g_Z[TWOE*KK];
__device__ float g_sE[TWOE];
__device__ float g_vcE[TWOE];
__device__ int   g_cE[TWOE];
__device__ float g_W1n[512*256], g_W1c[512*256];
__device__ float g_b1n[512],     g_b1c[512];
__device__ float g_W2n[256*DD],  g_W2c[256*DD];
__device__ float g_b2n[256],     g_b2c[256];
__device__ float g_am[DD];
__device__ double g_acc[5];           // nll, kldz, kldb, kldp, kld_alpha
__device__ float g_Mmax;

__device__ __forceinline__ float fsig(float x){ return 1.f/(1.f+__expf(-x)); }
__device__ __forceinline__ float ftanh(float x){
    float e=__expf(fminf(fmaxf(2.f*x,-30.f),30.f)); return (e-1.f)/(e+1.f); }
__device__ __forceinline__ float fsoftplus(float x){
    return fmaxf(x,0.f)+log1pf(__expf(-fabsf(x))); }
__device__ __forceinline__ void atomicMaxF(float* a, float v){
    int cur=__float_as_int(*a);
    while(__int_as_float(cur)<v){ int as=cur;
        cur=atomicCAS((int*)a,as,__float_as_int(v));
        if(cur==as) break; }
}

__global__ void k_init0(const int* sidx,const float* am,const float* as){
    int t=threadIdx.x; int s=sidx[0];
    __shared__ float red[128];
    float m=am[(size_t)s*DD+t];
    float sd=fsoftplus(as[(size_t)s*DD+t]);
    g_am[t]=m;
    red[t]=0.5f*(-2.f*logf(sd)+sd*sd+m*m-1.f);
    __syncthreads();
    for(int o=64;o;o>>=1){ if(t<o) red[t]+=red[t+o]; __syncthreads(); }
    if(t==0){ g_acc[4]=(double)red[0]; g_acc[0]=g_acc[1]=g_acc[2]=g_acc[3]=0.0; }
}

__global__ void k_initW(const float* WihN,const float* WhhN,const float* bihN,const float* bhhN,
                        const float* WihC,const float* WhhC,const float* bihC,const float* bhhC,
                        const float* Wpm,const float* bpm,const float* Wps,const float* bps,
                        const float* Wbm,const float* bbm,const float* Wbs,const float* bbs){
    int i=blockIdx.x*256+threadIdx.x;
    if(i<131072){                                  // W1 (both paths), 512 x 256
        int j=i>>8, c=i&255; float vn,vc;
        if(j<256){
            vn = c<128 ? WihN[j*256+c]+WihN[j*256+128+c] : WhhN[j*128+c-128];
            vc = c<128 ? WihC[j*256+c]+WihC[j*256+128+c] : WhhC[j*128+c-128];
        } else if(j<384){
            vn = c<128 ? WihN[j*256+c]+WihN[j*256+128+c] : 0.f;
            vc = c<128 ? WihC[j*256+c]+WihC[j*256+128+c] : 0.f;
        } else { int jr=j-128;
            vn = c<128 ? 0.f : WhhN[jr*128+c-128];
            vc = c<128 ? 0.f : WhhC[jr*128+c-128];
        }
        g_W1n[i]=vn; g_W1c[i]=vc;
    } else if(i<163840){                           // W2, 256 x 128
        int o=i-131072, r=o>>7, c=o&127;
        g_W2n[o] = r<128 ? Wpm[r*128+c] : Wps[(r-128)*128+c];
        g_W2c[o] = r<128 ? Wbm[r*128+c] : Wbs[(r-128)*128+c];
    } else if(i<164352){                           // b1
        int j=i-163840; float bn,bc;
        if(j<256){ bn=bihN[j]+bhhN[j]; bc=bihC[j]+bhhC[j]; }
        else if(j<384){ bn=bihN[j]; bc=bihC[j]; }
        else { bn=bhhN[j-128]; bc=bhhC[j-128]; }
        g_b1n[j]=bn; g_b1c[j]=bc;
    } else if(i<164608){                           // b2
        int j=i-164352;
        g_b2n[j] = j<128 ? bpm[j] : bps[j-128];
        g_b2c[j] = j<128 ? bbm[j] : bbs[j-128];
    }
}

__global__ void k_initS(const float* Wp,const float* bp,const float* Wb,const float* bb){
    __shared__ float am[DD];
    int tid=threadIdx.x;
    if(tid<DD) am[tid]=g_am[tid];
    __syncthreads();
    int i=blockIdx.x*256+tid; if(i>=ROWS*DD) return;
    const float* wr; float bias;
    if(i<NN*DD){ wr=Wp+(size_t)i*DD; bias=bp[i]; }
    else { int o=i-NN*DD; wr=Wb+(size_t)o*DD; bias=bb[o]; }
    const float4* w4=(const float4*)wr; const float4* a4=(const float4*)am;
    float acc=bias;
    #pragma unroll 8
    for(int q=0;q<32;q++){ float4 w=w4[q],a=a4[q];
        acc+=w.x*a.x+w.y*a.y+w.z*a.z+w.w*a.w; }
    g_s[0][i]=acc; g_h[0][i]=0.f;
}

// C = A @ W^T + b, tiled 32x64, scalar smem (stride KD+1, conflict-free).
template<int KD>
__global__ void k_gemm(int pp){
    extern __shared__ float sm[];
    float* As=sm; float* Ws=sm+32*(KD+1);
    int mT=blockIdx.x, pT=blockIdx.y, tid=threadIdx.x;
    int beta=(mT==64);
    int row0=beta?2048:mT*32, rowsEff=beta?16:32, p0=pT*64;
    const float *A0,*A1,*W,*bias; float* C; int ldC;
    if(KD==256){ A0=g_s[pp]; A1=g_h[pp]; W=beta?g_W1c:g_W1n; bias=beta?g_b1c:g_b1n; C=g_G; ldC=512; }
    else       { A0=g_h[1-pp]; A1=0;     W=beta?g_W2c:g_W2n; bias=beta?g_b2c:g_b2n; C=g_Hm; ldC=256; }
    for(int i=tid;i<32*KD;i+=256){ int r=i/KD,c=i-r*KD; float v=0.f;
        if(r<rowsEff){ int g=(row0+r)*DD+(c&127); v=(KD==256&&c>=128)?A1[g]:A0[g]; }
        As[r*(KD+1)+c]=v; }
    for(int i=tid;i<64*KD;i+=256){ int r=i/KD,c=i-r*KD;
        Ws[r*(KD+1)+c]=W[(size_t)(p0+r)*KD+c]; }
    __syncthreads();
    int rm=(tid&7)*4, cp=(tid>>3)*2;
    float a00=0,a01=0,a10=0,a11=0,a20=0,a21=0,a30=0,a31=0;
    #pragma unroll 8
    for(int d=0;d<KD;d++){
        float w0=Ws[cp*(KD+1)+d], w1=Ws[(cp+1)*(KD+1)+d];
        float x0=As[(rm+0)*(KD+1)+d], x1=As[(rm+1)*(KD+1)+d];
        float x2=As[(rm+2)*(KD+1)+d], x3=As[(rm+3)*(KD+1)+d];
        a00+=x0*w0; a01+=x0*w1; a10+=x1*w0; a11+=x1*w1;
        a20+=x2*w0; a21+=x2*w1; a30+=x3*w0; a31+=x3*w1;
    }
    float b0=bias[p0+cp], b1=bias[p0+cp+1];
    float r0[4]={a00,a10,a20,a30}, r1[4]={a01,a11,a21,a31};
    for(int i=0;i<4;i++){ int r=rm+i; if(r<rowsEff){
        C[(size_t)(row0+r)*ldC+p0+cp]=r0[i]+b0;
        C[(size_t)(row0+r)*ldC+p0+cp+1]=r1[i]+b1; } }
}

__global__ void k_act(int pp){
    int i=blockIdx.x*256+threadIdx.x; if(i>=ROWS*DD) return;
    int row=i>>7, d=i&127;
    const float* G=g_G+(size_t)row*512;
    float r=fsig(G[d]), z=fsig(G[128+d]);
    float nn=ftanh(G[256+d]+r*G[384+d]);
    g_h[1-pp][i]=(1.f-z)*nn+z*g_h[pp][i];
}

__global__ void k_sample(int pp,const float* ept,const float* ebt){
    int i=blockIdx.x*256+threadIdx.x;
    if(i==0) g_Mmax=-1e30f;               // reset for k_matM (next launch)
    double kp=0,kb=0;
    if(i<ROWS*DD){
        int row=i>>7, d=i&127;
        float mean=g_Hm[row*256+d];
        float sd=fsoftplus(g_Hm[row*256+128+d]);
        float prior=g_s[pp][i];
        float e = row<NN ? ept[i] : ebt[(row-NN)*DD+d];
        g_s[1-pp][i]=mean+sd*e;
        float dm=mean-prior;
        if(row<NN) kp=0.5*(-2.0*(double)logf(sd)+(double)sd*sd+(double)dm*dm-1.0);
        else       kb=0.5*(2.0*(-2.302585092994046-(double)logf(sd))
                          +((double)sd*sd+(double)dm*dm)*100.0-1.0);
    }
    __shared__ double r1[256],r2[256];
    int t=threadIdx.x; r1[t]=kp; r2[t]=kb; __syncthreads();
    for(int o=128;o;o>>=1){ if(t<o){ r1[t]+=r1[t+o]; r2[t]+=r2[t+o]; } __syncthreads(); }
    if(t==0){ if(r1[0]!=0.0) atomicAdd(&g_acc[3],r1[0]);
              if(r2[0]!=0.0) atomicAdd(&g_acc[2],r2[0]); }
}

__global__ void k_matM(int pp,const float* Wdec){
    __shared__ float bs[KK*DD];
    __shared__ float wm[8];
    int t=threadIdx.x, po=1-pp;
    for(int i=t;i<KK*DD;i+=256) bs[i]=g_s[po][NN*DD+i];
    __syncthreads();
    int n=blockIdx.x*256+t;
    float acc[KK];
    #pragma unroll
    for(int k=0;k<KK;k++) acc[k]=0.f;
    const float4* w4=(const float4*)(Wdec+(size_t)n*DD);
    for(int q=0;q<32;q++){ float4 w=w4[q];
        #pragma unroll
        for(int k=0;k<KK;k++){ float4 b=((const float4*)(bs+k*DD))[q];
            acc[k]+=w.x*b.x+w.y*b.y+w.z*b.z+w.w*b.w; } }
    float mx=acc[0];
    #pragma unroll
    for(int k=0;k<KK;k++){ g_M[n*KK+k]=acc[k]; mx=fmaxf(mx,acc[k]); }
    for(int o=16;o;o>>=1) mx=fmaxf(mx,__shfl_xor_sync(0xffffffffu,mx,o));
    if((t&31)==0) wm[t>>5]=mx;
    __syncthreads();
    if(t==0){ float b=wm[0];
        #pragma unroll
        for(int j=1;j<8;j++) b=fmaxf(b,wm[j]);
        atomicMaxF(&g_Mmax,b); }
}

// per-edge logits, softmaxes, KL(z), gumbel z -> g_Z; zero per-edge accums.
__global__ void k_logits(int pp,const int* edt,const float* ut,const float* Wpi){
    __shared__ float Pt[DD*KK];   // [d][k]
    __shared__ float Bt[DD*KK];
    __shared__ double rd[128];
    int t=threadIdx.x, po=1-pp;
    for(int i=t;i<DD*KK;i+=128){ int d=i>>4,k=i&15;
        Pt[i]=Wpi[k*DD+d]; Bt[i]=g_s[po][NN*DD+k*DD+d]; }
    __syncthreads();
    int e=blockIdx.x*128+t, w,c;
    if(e<EE){ w=edt[2*e]; c=edt[2*e+1]; } else { int e2=e-EE; w=edt[2*e2+1]; c=edt[2*e2]; }
    const float4* pw4=(const float4*)(g_s[po]+(size_t)w*DD);
    const float4* pc4=(const float4*)(g_s[po]+(size_t)c*DD);
    float lq[KK],lp[KK];
    #pragma unroll
    for(int k=0;k<KK;k++){ lq[k]=0.f; lp[k]=0.f; }
    for(int q=0;q<32;q++){
        float4 a=pw4[q], b=pc4[q];
        float aw[4]={a.x,a.y,a.z,a.w};
        float pr[4]={a.x*b.x,a.y*b.y,a.z*b.z,a.w*b.w};
        #pragma unroll
        for(int j=0;j<4;j++){ int d=q*4+j;
            const float4* P4=(const float4*)(Pt+d*KK);
            const float4* B4=(const float4*)(Bt+d*KK);
            #pragma unroll
            for(int h=0;h<4;h++){
                float4 P=P4[h], B=B4[h];
                lq[4*h+0]+=pr[j]*P.x; lq[4*h+1]+=pr[j]*P.y;
                lq[4*h+2]+=pr[j]*P.z; lq[4*h+3]+=pr[j]*P.w;
                lp[4*h+0]+=aw[j]*B.x; lp[4*h+1]+=aw[j]*B.y;
                lp[4*h+2]+=aw[j]*B.z; lp[4*h+3]+=aw[j]*B.w;
            }
        }
    }
    float mq=-3e38f,mp=-3e38f;
    #pragma unroll
    for(int k=0;k<KK;k++){ mq=fmaxf(mq,lq[k]); mp=fmaxf(mp,lp[k]); }
    float sq=0,sp=0;
    #pragma unroll
    for(int k=0;k<KK;k++){ sq+=__expf(lq[k]-mq); sp+=__expf(lp[k]-mp); }
    float lsq=__logf(sq), lsp=__logf(sp), kz=0.f;
    #pragma unroll
    for(int k=0;k<KK;k++){ float lpo=lq[k]-mq-lsq;
        kz+=__expf(lpo)*(lpo-(lp[k]-mp-lsp)); }
    const float4* u4=(const float4*)(ut+(size_t)e*KK);
    float ze[KK];
    #pragma unroll
    for(int q=0;q<4;q++){ float4 u=u4[q]; float uu[4]={u.x,u.y,u.z,u.w};
        #pragma unroll
        for(int j=0;j<4;j++)
            ze[q*4+j]=lq[q*4+j]-__logf(-__logf(uu[j]+1e-10f)+1e-10f); }
    float mz=-3e38f;
    #pragma unroll
    for(int k=0;k<KK;k++) mz=fmaxf(mz,ze[k]);
    float sz=0;
    #pragma unroll
    for(int k=0;k<KK;k++){ ze[k]=__expf(ze[k]-mz); sz+=ze[k]; }
    float inv=1.f/sz;
    float4* zo=(float4*)(g_Z+(size_t)e*KK);
    #pragma unroll
    for(int q=0;q<4;q++){
        float4 v; v.x=ze[q*4]*inv; v.y=ze[q*4+1]*inv;
        v.z=ze[q*4+2]*inv; v.w=ze[q*4+3]*inv; zo[q]=v; }
    g_cE[e]=c; g_sE[e]=0.f; g_vcE[e]=0.f;
    rd[t]=(double)kz; __syncthreads();
    for(int o=64;o;o>>=1){ if(t<o) rd[t]+=rd[t+o]; __syncthreads(); }
    if(t==0) atomicAdd(&g_acc[1],rd[0]);
}

// N-scan: grid (128 edge-tiles, 4 n-tiles), 256 thr; 2 threads per edge.
__global__ __launch_bounds__(256) void k_scan(){
    __shared__ float Ms[512*KK];
    __shared__ float Zs[128*KK];
    __shared__ float s_red[256], v_red[256];
    int tid=threadIdx.x;
    int n0=blockIdx.y*512, e0=blockIdx.x*128;
    for(int i=tid;i<512*KK;i+=256) Ms[i]=g_M[n0*KK+i];
    for(int i=tid;i<128*KK;i+=256) Zs[i]=g_Z[(size_t)e0*KK+i];
    __syncthreads();
    int li=tid&127, sub=tid>>7;
    int e=e0+li;
    int c=g_cE[e];
    const float4* z4=(const float4*)(Zs+li*KK);
    float4 Z0=z4[0],Z1=z4[1],Z2=z4[2],Z3=z4[3];
    float Mx=g_Mmax;
    float s0=0.f,s1=0.f,vc=0.f;
    int base=n0+sub*256;
    #pragma unroll 2
    for(int j=0;j<256;j+=2){
        const float4* m0=(const float4*)(Ms+(sub*256+j)*KK);
        const float4* m1=(const float4*)(Ms+(sub*256+j+1)*KK);
        float4 A0=m0[0],A1=m0[1],A2=m0[2],A3=m0[3];
        float4 B0=m1[0],B1=m1[1],B2=m1[2],B3=m1[3];
        float p0=Z0.x*A0.x+Z0.y*A0.y+Z0.z*A0.z+Z0.w*A0.w;
        float p1=Z1.x*A1.x+Z1.y*A1.y+Z1.z*A1.z+Z1.w*A1.w;
        float p2=Z2.x*A2.x+Z2.y*A2.y+Z2.z*A2.z+Z2.w*A2.w;
        float p3=Z3.x*A3.x+Z3.y*A3.y+Z3.z*A3.z+Z3.w*A3.w;
        float q0=Z0.x*B0.x+Z0.y*B0.y+Z0.z*B0.z+Z0.w*B0.w;
        float q1=Z1.x*B1.x+Z1.y*B1.y+Z1.z*B1.z+Z1.w*B1.w;
        float q2=Z2.x*B2.x+Z2.y*B2.y+Z2.z*B2.z+Z2.w*B2.w;
        float q3=Z3.x*B3.x+Z3.y*B3.y+Z3.z*B3.z+Z3.w*B3.w;
        float v0=(p0+p1)+(p2+p3);
        float v1=(q0+q1)+(q2+q3);
        s0+=__expf(v0-Mx); s1+=__expf(v1-Mx);
        if(base+j==c)   vc=v0;
        if(base+j+1==c) vc=v1;
    }
    s_red[tid]=s0+s1; v_red[tid]=vc;
    __syncthreads();
    if(sub==0){
        float st=s_red[li]+s_red[li+128];
        float vt=v_red[li]+v_red[li+128];
        atomicAdd(&g_sE[e],st);
        if(c>=n0 && c<n0+512) atomicAdd(&g_vcE[e],vt);
    }
}

__global__ void k_fin(){
    __shared__ double rd[256];
    int t=threadIdx.x;
    int e=blockIdx.x*256+t;
    double nll=0.0;
    if(e<TWOE)
        nll=(double)(-(g_vcE[e]-g_Mmax-__logf(g_sE[e])));
    rd[t]=nll; __syncthreads();
    for(int o=128;o;o>>=1){ if(t<o) rd[t]+=rd[t+o]; __syncthreads(); }
    if(t==0) atomicAdd(&g_acc[0],rd[0]);
}

__global__ void k_out(float* out){
    out[0]=(float)(g_acc[0]/CNT);
    out[1]=(float)(g_acc[1]/CNT);
    out[2]=(float)(16.0*g_acc[4]/CNT);
    out[3]=(float)(g_acc[2]/CNT);
    out[4]=(float)(g_acc[3]/CNT);
}

extern "C" void kernel_launch(void* const* d_in,const int* in_sizes,int n_in,
                              void* d_out,int out_size){
    const int*   edges=(const int*)d_in[0];
    const int*   sidx =(const int*)d_in[1];
    const float* epp  =(const float*)d_in[2];
    const float* epb  =(const float*)d_in[3];
    const float* ug   =(const float*)d_in[4];
    const float* amean=(const float*)d_in[5];
    const float* astd =(const float*)d_in[6];
    const float* Ws2p =(const float*)d_in[7];  const float* bs2p=(const float*)d_in[8];
    const float* Ws2b =(const float*)d_in[9];  const float* bs2b=(const float*)d_in[10];
    const float* Wbm  =(const float*)d_in[11]; const float* bbm =(const float*)d_in[12];
    const float* Wbs  =(const float*)d_in[13]; const float* bbs =(const float*)d_in[14];
    const float* Wpm  =(const float*)d_in[15]; const float* bpm =(const float*)d_in[16];
    const float* Wps  =(const float*)d_in[17]; const float* bps =(const float*)d_in[18];
    const float* Wpi  =(const float*)d_in[19];
    const float* WihN =(const float*)d_in[20]; const float* WhhN=(const float*)d_in[21];
    const float* bihN =(const float*)d_in[22]; const float* bhhN=(const float*)d_in[23];
    const float* WihC =(const float*)d_in[24]; const float* WhhC=(const float*)d_in[25];
    const float* bihC =(const float*)d_in[26]; const float* bhhC=(const float*)d_in[27];
    const float* Wdec =(const float*)d_in[28];
    float* out=(float*)d_out;

    int smem1 = (32*257+64*257)*4;   // 98688
    int smem2 = (32*129+64*129)*4;   // 49536
    cudaFuncSetAttribute(k_gemm<256>,cudaFuncAttributeMaxDynamicSharedMemorySize,smem1);
    cudaFuncSetAttribute(k_gemm<128>,cudaFuncAttributeMaxDynamicSharedMemorySize,smem2);

    k_init0<<<1,128>>>(sidx,amean,astd);
    k_initW<<<644,256>>>(WihN,WhhN,bihN,bhhN,WihC,WhhC,bihC,bhhC,
                         Wpm,bpm,Wps,bps,Wbm,bbm,Wbs,bbs);
    k_initS<<<1033,256>>>(Ws2p,bs2p,Ws2b,bs2b);
    for(int t=0;t<16;t++){
        int pp=t&1;
        k_gemm<256><<<dim3(65,8),256,smem1>>>(pp);
        k_act<<<1033,256>>>(pp);
        k_gemm<128><<<dim3(65,4),256,smem2>>>(pp);
        k_sample<<<1033,256>>>(pp, epp+(size_t)t*NN*DD, epb+(size_t)t*KK*DD);
        k_matM<<<8,256>>>(pp, Wdec);
        k_logits<<<128,128>>>(pp, edges+(size_t)t*EE*2,
                              ug+(size_t)t*2*EE*KK, Wpi);
        k_scan<<<dim3(128,4),256>>>();
        k_fin<<<64,256>>>();
    }
    k_out<<<1,1>>>(out);
}

// round 9
// speedup vs baseline: 2.4574x; 1.1596x over previous
#include <cuda_runtime.h>
#include <math.h>

#define NN 2048
#define DD 128
#define KK 16
#define EE 8192
#define TWOE 16384
#define ROWS 2064               // 2048 phi rows + 16 beta rows
#define CNT 262144.0

typedef unsigned long long ull;

__device__ float g_s[2][ROWS*DD];     // phi_s rows 0..2047, beta_s rows 2048..2063
__device__ float g_h[2][ROWS*DD];
__device__ float g_G[ROWS*512];
__device__ float g_Hm[ROWS*256];
__device__ float g_M[NN*KK];          // n-major, k contiguous
__device__ float g_Z[TWOE*KK];
__device__ float g_sE[TWOE];
__device__ float g_vcE[TWOE];
__device__ int   g_cE[TWOE];
__device__ float g_W1n[512*256], g_W1c[512*256];
__device__ float g_b1n[512],     g_b1c[512];
__device__ float g_W2n[256*DD],  g_W2c[256*DD];
__device__ float g_b2n[256],     g_b2c[256];
__device__ float g_am[DD];
__device__ double g_acc[5];           // nll, kldz, kldb, kldp, kld_alpha
__device__ float g_Mmax;

__device__ __forceinline__ float fsig(float x){ return 1.f/(1.f+__expf(-x)); }
__device__ __forceinline__ float ftanh(float x){
    float e=__expf(fminf(fmaxf(2.f*x,-30.f),30.f)); return (e-1.f)/(e+1.f); }
__device__ __forceinline__ float fsoftplus(float x){
    return fmaxf(x,0.f)+log1pf(__expf(-fabsf(x))); }
__device__ __forceinline__ void atomicMaxF(float* a, float v){
    int cur=__float_as_int(*a);
    while(__int_as_float(cur)<v){ int as=cur;
        cur=atomicCAS((int*)a,as,__float_as_int(v));
        if(cur==as) break; }
}
__device__ __forceinline__ ull ffma2(ull a, ull b, ull c){
    asm("fma.rn.f32x2 %0,%1,%2,%3;":"=l"(c):"l"(a),"l"(b),"l"(c));
    return c;
}
__device__ __forceinline__ ull fadd2(ull a, ull b){
    ull r; asm("add.rn.f32x2 %0,%1,%2;":"=l"(r):"l"(a),"l"(b));
    return r;
}
__device__ __forceinline__ float upsum(ull v){
    float lo,hi; asm("mov.b64 {%0,%1},%2;":"=f"(lo),"=f"(hi):"l"(v));
    return lo+hi;
}

__global__ void k_init0(const int* sidx,const float* am,const float* as){
    int t=threadIdx.x; int s=sidx[0];
    __shared__ float red[128];
    float m=am[(size_t)s*DD+t];
    float sd=fsoftplus(as[(size_t)s*DD+t]);
    g_am[t]=m;
    red[t]=0.5f*(-2.f*logf(sd)+sd*sd+m*m-1.f);
    __syncthreads();
    for(int o=64;o;o>>=1){ if(t<o) red[t]+=red[t+o]; __syncthreads(); }
    if(t==0){ g_acc[4]=(double)red[0]; g_acc[0]=g_acc[1]=g_acc[2]=g_acc[3]=0.0; }
}

__global__ void k_initW(const float* WihN,const float* WhhN,const float* bihN,const float* bhhN,
                        const float* WihC,const float* WhhC,const float* bihC,const float* bhhC,
                        const float* Wpm,const float* bpm,const float* Wps,const float* bps,
                        const float* Wbm,const float* bbm,const float* Wbs,const float* bbs){
    int i=blockIdx.x*256+threadIdx.x;
    if(i<131072){                                  // W1 (both paths), 512 x 256
        int j=i>>8, c=i&255; float vn,vc;
        if(j<256){
            vn = c<128 ? WihN[j*256+c]+WihN[j*256+128+c] : WhhN[j*128+c-128];
            vc = c<128 ? WihC[j*256+c]+WihC[j*256+128+c] : WhhC[j*128+c-128];
        } else if(j<384){
            vn = c<128 ? WihN[j*256+c]+WihN[j*256+128+c] : 0.f;
            vc = c<128 ? WihC[j*256+c]+WihC[j*256+128+c] : 0.f;
        } else { int jr=j-128;
            vn = c<128 ? 0.f : WhhN[jr*128+c-128];
            vc = c<128 ? 0.f : WhhC[jr*128+c-128];
        }
        g_W1n[i]=vn; g_W1c[i]=vc;
    } else if(i<163840){                           // W2, 256 x 128
        int o=i-131072, r=o>>7, c=o&127;
        g_W2n[o] = r<128 ? Wpm[r*128+c] : Wps[(r-128)*128+c];
        g_W2c[o] = r<128 ? Wbm[r*128+c] : Wbs[(r-128)*128+c];
    } else if(i<164352){                           // b1
        int j=i-163840; float bn,bc;
        if(j<256){ bn=bihN[j]+bhhN[j]; bc=bihC[j]+bhhC[j]; }
        else if(j<384){ bn=bihN[j]; bc=bihC[j]; }
        else { bn=bhhN[j-128]; bc=bhhC[j-128]; }
        g_b1n[j]=bn; g_b1c[j]=bc;
    } else if(i<164608){                           // b2
        int j=i-164352;
        g_b2n[j] = j<128 ? bpm[j] : bps[j-128];
        g_b2c[j] = j<128 ? bbm[j] : bbs[j-128];
    }
}

__global__ void k_initS(const float* Wp,const float* bp,const float* Wb,const float* bb){
    __shared__ float am[DD];
    int tid=threadIdx.x;
    if(tid<DD) am[tid]=g_am[tid];
    __syncthreads();
    int i=blockIdx.x*256+tid; if(i>=ROWS*DD) return;
    const float* wr; float bias;
    if(i<NN*DD){ wr=Wp+(size_t)i*DD; bias=bp[i]; }
    else { int o=i-NN*DD; wr=Wb+(size_t)o*DD; bias=bb[o]; }
    const float4* w4=(const float4*)wr; const float4* a4=(const float4*)am;
    float acc=bias;
    #pragma unroll 8
    for(int q=0;q<32;q++){ float4 w=w4[q],a=a4[q];
        acc+=w.x*a.x+w.y*a.y+w.z*a.z+w.w*a.w; }
    g_s[0][i]=acc; g_h[0][i]=0.f;
}

// C = A @ W^T + b, block tile 64x128, thread tile 8x4, packed f32x2 along k.
// smem stride KD+2: x-load banks 2g+c (8 distinct), w-load banks {0,8,16,24}.
template<int KD>
__global__ __launch_bounds__(256) void k_gemm(int pp){
    extern __shared__ float sm[];
    const int LDA=KD+2;
    float* As=sm;                 // [64][LDA]
    float* Ws=sm+64*LDA;          // [128][LDA]
    int mT=blockIdx.x, pT=blockIdx.y, tid=threadIdx.x;
    int beta=(mT==32);
    int row0=beta?2048:mT*64, rowsEff=beta?16:64, p0=pT*128;
    const float *A0,*A1,*W,*bias; float* C; int ldC;
    if(KD==256){ A0=g_s[pp]; A1=g_h[pp]; W=beta?g_W1c:g_W1n; bias=beta?g_b1c:g_b1n; C=g_G; ldC=512; }
    else       { A0=g_h[1-pp]; A1=0;     W=beta?g_W2c:g_W2n; bias=beta?g_b2c:g_b2n; C=g_Hm; ldC=256; }
    const int C4=KD/4;
    for(int i=tid;i<64*C4;i+=256){
        int r=i/C4, c4=i-r*C4;
        float4 v=make_float4(0.f,0.f,0.f,0.f);
        if(r<rowsEff){
            int gg=(row0+r)*DD+((c4*4)&127);
            const float* src=(KD==256 && c4>=32)?A1:A0;
            v=*(const float4*)(src+gg);
        }
        float* dst=As+r*LDA+c4*4;
        *(float2*)dst    =make_float2(v.x,v.y);
        *(float2*)(dst+2)=make_float2(v.z,v.w);
    }
    for(int i=tid;i<128*C4;i+=256){
        int r=i/C4, c4=i-r*C4;
        float4 v=*(const float4*)(W+(size_t)(p0+r)*KD+c4*4);
        float* dst=Ws+r*LDA+c4*4;
        *(float2*)dst    =make_float2(v.x,v.y);
        *(float2*)(dst+2)=make_float2(v.z,v.w);
    }
    __syncthreads();
    int g=tid&7, cp=(tid>>3)*4;
    const float* Ab=As+g*LDA;
    const float* Wb=Ws+cp*LDA;
    ull acc[8][4];
    #pragma unroll
    for(int i=0;i<8;i++)
        #pragma unroll
        for(int j=0;j<4;j++) acc[i][j]=0ull;
    #pragma unroll 2
    for(int d2=0;d2<KD/2;d2++){
        int off=2*d2;
        ull w0=*(const ull*)(Wb+0*LDA+off);
        ull w1=*(const ull*)(Wb+1*LDA+off);
        ull w2=*(const ull*)(Wb+2*LDA+off);
        ull w3=*(const ull*)(Wb+3*LDA+off);
        #pragma unroll
        for(int i=0;i<8;i++){
            ull x=*(const ull*)(Ab+i*8*LDA+off);
            acc[i][0]=ffma2(x,w0,acc[i][0]);
            acc[i][1]=ffma2(x,w1,acc[i][1]);
            acc[i][2]=ffma2(x,w2,acc[i][2]);
            acc[i][3]=ffma2(x,w3,acc[i][3]);
        }
    }
    #pragma unroll
    for(int i=0;i<8;i++){
        int r=g+8*i;
        if(r<rowsEff){
            float4 o;
            o.x=upsum(acc[i][0])+bias[p0+cp+0];
            o.y=upsum(acc[i][1])+bias[p0+cp+1];
            o.z=upsum(acc[i][2])+bias[p0+cp+2];
            o.w=upsum(acc[i][3])+bias[p0+cp+3];
            *(float4*)(C+(size_t)(row0+r)*ldC+p0+cp)=o;
        }
    }
}

__global__ void k_act(int pp){
    int i=blockIdx.x*256+threadIdx.x; if(i>=ROWS*DD) return;
    int row=i>>7, d=i&127;
    const float* G=g_G+(size_t)row*512;
    float r=fsig(G[d]), z=fsig(G[128+d]);
    float nn=ftanh(G[256+d]+r*G[384+d]);
    g_h[1-pp][i]=(1.f-z)*nn+z*g_h[pp][i];
}

__global__ void k_sample(int pp,const float* ept,const float* ebt){
    int i=blockIdx.x*256+threadIdx.x;
    if(i==0) g_Mmax=-1e30f;               // reset for k_matM (next launch)
    double kp=0,kb=0;
    if(i<ROWS*DD){
        int row=i>>7, d=i&127;
        float mean=g_Hm[row*256+d];
        float sd=fsoftplus(g_Hm[row*256+128+d]);
        float prior=g_s[pp][i];
        float e = row<NN ? ept[i] : ebt[(row-NN)*DD+d];
        g_s[1-pp][i]=mean+sd*e;
        float dm=mean-prior;
        if(row<NN) kp=0.5*(-2.0*(double)logf(sd)+(double)sd*sd+(double)dm*dm-1.0);
        else       kb=0.5*(2.0*(-2.302585092994046-(double)logf(sd))
                          +((double)sd*sd+(double)dm*dm)*100.0-1.0);
    }
    __shared__ double r1[256],r2[256];
    int t=threadIdx.x; r1[t]=kp; r2[t]=kb; __syncthreads();
    for(int o=128;o;o>>=1){ if(t<o){ r1[t]+=r1[t+o]; r2[t]+=r2[t+o]; } __syncthreads(); }
    if(t==0){ if(r1[0]!=0.0) atomicAdd(&g_acc[3],r1[0]);
              if(r2[0]!=0.0) atomicAdd(&g_acc[2],r2[0]); }
}

__global__ void k_matM(int pp,const float* Wdec){
    __shared__ float bs[KK*DD];
    __shared__ float wm[8];
    int t=threadIdx.x, po=1-pp;
    for(int i=t;i<KK*DD;i+=256) bs[i]=g_s[po][NN*DD+i];
    __syncthreads();
    int n=blockIdx.x*256+t;
    float acc[KK];
    #pragma unroll
    for(int k=0;k<KK;k++) acc[k]=0.f;
    const float4* w4=(const float4*)(Wdec+(size_t)n*DD);
    for(int q=0;q<32;q++){ float4 w=w4[q];
        #pragma unroll
        for(int k=0;k<KK;k++){ float4 b=((const float4*)(bs+k*DD))[q];
            acc[k]+=w.x*b.x+w.y*b.y+w.z*b.z+w.w*b.w; } }
    float mx=acc[0];
    #pragma unroll
    for(int k=0;k<KK;k++){ g_M[n*KK+k]=acc[k]; mx=fmaxf(mx,acc[k]); }
    for(int o=16;o;o>>=1) mx=fmaxf(mx,__shfl_xor_sync(0xffffffffu,mx,o));
    if((t&31)==0) wm[t>>5]=mx;
    __syncthreads();
    if(t==0){ float b=wm[0];
        #pragma unroll
        for(int j=1;j<8;j++) b=fmaxf(b,wm[j]);
        atomicMaxF(&g_Mmax,b); }
}

// per-edge logits, softmaxes, KL(z), gumbel z -> g_Z; zero per-edge accums.
__global__ void k_logits(int pp,const int* edt,const float* ut,const float* Wpi){
    __shared__ float Pt[DD*KK];   // [d][k]
    __shared__ float Bt[DD*KK];
    __shared__ double rd[128];
    int t=threadIdx.x, po=1-pp;
    for(int i=t;i<DD*KK;i+=128){ int d=i>>4,k=i&15;
        Pt[i]=Wpi[k*DD+d]; Bt[i]=g_s[po][NN*DD+k*DD+d]; }
    __syncthreads();
    int e=blockIdx.x*128+t, w,c;
    if(e<EE){ w=edt[2*e]; c=edt[2*e+1]; } else { int e2=e-EE; w=edt[2*e2+1]; c=edt[2*e2]; }
    const float4* pw4=(const float4*)(g_s[po]+(size_t)w*DD);
    const float4* pc4=(const float4*)(g_s[po]+(size_t)c*DD);
    float lq[KK],lp[KK];
    #pragma unroll
    for(int k=0;k<KK;k++){ lq[k]=0.f; lp[k]=0.f; }
    for(int q=0;q<32;q++){
        float4 a=pw4[q], b=pc4[q];
        float aw[4]={a.x,a.y,a.z,a.w};
        float pr[4]={a.x*b.x,a.y*b.y,a.z*b.z,a.w*b.w};
        #pragma unroll
        for(int j=0;j<4;j++){ int d=q*4+j;
            const float4* P4=(const float4*)(Pt+d*KK);
            const float4* B4=(const float4*)(Bt+d*KK);
            #pragma unroll
            for(int h=0;h<4;h++){
                float4 P=P4[h], B=B4[h];
                lq[4*h+0]+=pr[j]*P.x; lq[4*h+1]+=pr[j]*P.y;
                lq[4*h+2]+=pr[j]*P.z; lq[4*h+3]+=pr[j]*P.w;
                lp[4*h+0]+=aw[j]*B.x; lp[4*h+1]+=aw[j]*B.y;
                lp[4*h+2]+=aw[j]*B.z; lp[4*h+3]+=aw[j]*B.w;
            }
        }
    }
    float mq=-3e38f,mp=-3e38f;
    #pragma unroll
    for(int k=0;k<KK;k++){ mq=fmaxf(mq,lq[k]); mp=fmaxf(mp,lp[k]); }
    float sq=0,sp=0;
    #pragma unroll
    for(int k=0;k<KK;k++){ sq+=__expf(lq[k]-mq); sp+=__expf(lp[k]-mp); }
    float lsq=__logf(sq), lsp=__logf(sp), kz=0.f;
    #pragma unroll
    for(int k=0;k<KK;k++){ float lpo=lq[k]-mq-lsq;
        kz+=__expf(lpo)*(lpo-(lp[k]-mp-lsp)); }
    const float4* u4=(const float4*)(ut+(size_t)e*KK);
    float ze[KK];
    #pragma unroll
    for(int q=0;q<4;q++){ float4 u=u4[q]; float uu[4]={u.x,u.y,u.z,u.w};
        #pragma unroll
        for(int j=0;j<4;j++)
            ze[q*4+j]=lq[q*4+j]-__logf(-__logf(uu[j]+1e-10f)+1e-10f); }
    float mz=-3e38f;
    #pragma unroll
    for(int k=0;k<KK;k++) mz=fmaxf(mz,ze[k]);
    float sz=0;
    #pragma unroll
    for(int k=0;k<KK;k++){ ze[k]=__expf(ze[k]-mz); sz+=ze[k]; }
    float inv=1.f/sz;
    float4* zo=(float4*)(g_Z+(size_t)e*KK);
    #pragma unroll
    for(int q=0;q<4;q++){
        float4 v; v.x=ze[q*4]*inv; v.y=ze[q*4+1]*inv;
        v.z=ze[q*4+2]*inv; v.w=ze[q*4+3]*inv; zo[q]=v; }
    g_cE[e]=c; g_sE[e]=0.f; g_vcE[e]=0.f;
    rd[t]=(double)kz; __syncthreads();
    for(int o=64;o;o>>=1){ if(t<o) rd[t]+=rd[t+o]; __syncthreads(); }
    if(t==0) atomicAdd(&g_acc[1],rd[0]);
}

// N-scan: grid (128 edge-tiles, 4 n-tiles), 256 thr; 2 threads per edge.
__global__ __launch_bounds__(256) void k_scan(){
    __shared__ float Ms[512*KK];
    __shared__ float Zs[128*KK];
    __shared__ float s_red[256], v_red[256];
    int tid=threadIdx.x;
    int n0=blockIdx.y*512, e0=blockIdx.x*128;
    for(int i=tid;i<512*KK;i+=256) Ms[i]=g_M[n0*KK+i];
    for(int i=tid;i<128*KK;i+=256) Zs[i]=g_Z[(size_t)e0*KK+i];
    __syncthreads();
    int li=tid&127, sub=tid>>7;
    int e=e0+li;
    int c=g_cE[e];
    ull zp[8];
    {   const ull* z8=(const ull*)(Zs+li*KK);
        #pragma unroll
        for(int q=0;q<8;q++) zp[q]=z8[q]; }
    float Mx=g_Mmax;
    float s0=0.f,s1=0.f,vc=0.f;
    int base=n0+sub*256;
    #pragma unroll 2
    for(int j=0;j<256;j+=2){
        const ulonglong2* m0=(const ulonglong2*)(Ms+(sub*256+j)*KK);
        const ulonglong2* m1=(const ulonglong2*)(Ms+(sub*256+j+1)*KK);
        ulonglong2 A0=m0[0],A1=m0[1],A2=m0[2],A3=m0[3];
        ulonglong2 B0=m1[0],B1=m1[1],B2=m1[2],B3=m1[3];
        ull ta=ffma2(zp[0],A0.x,0ull); ull tb=ffma2(zp[1],A0.y,0ull);
        ta=ffma2(zp[2],A1.x,ta);       tb=ffma2(zp[3],A1.y,tb);
        ta=ffma2(zp[4],A2.x,ta);       tb=ffma2(zp[5],A2.y,tb);
        ta=ffma2(zp[6],A3.x,ta);       tb=ffma2(zp[7],A3.y,tb);
        ull tc=ffma2(zp[0],B0.x,0ull); ull td=ffma2(zp[1],B0.y,0ull);
        tc=ffma2(zp[2],B1.x,tc);       td=ffma2(zp[3],B1.y,td);
        tc=ffma2(zp[4],B2.x,tc);       td=ffma2(zp[5],B2.y,td);
        tc=ffma2(zp[6],B3.x,tc);       td=ffma2(zp[7],B3.y,td);
        float v0=upsum(fadd2(ta,tb));
        float v1=upsum(fadd2(tc,td));
        s0+=__expf(v0-Mx); s1+=__expf(v1-Mx);
        if(base+j==c)   vc=v0;
        if(base+j+1==c) vc=v1;
    }
    s_red[tid]=s0+s1; v_red[tid]=vc;
    __syncthreads();
    if(sub==0){
        float st=s_red[li]+s_red[li+128];
        float vt=v_red[li]+v_red[li+128];
        atomicAdd(&g_sE[e],st);
        if(c>=n0 && c<n0+512) atomicAdd(&g_vcE[e],vt);
    }
}

__global__ void k_fin(){
    __shared__ double rd[256];
    int t=threadIdx.x;
    int e=blockIdx.x*256+t;
    double nll=0.0;
    if(e<TWOE)
        nll=(double)(-(g_vcE[e]-g_Mmax-__logf(g_sE[e])));
    rd[t]=nll; __syncthreads();
    for(int o=128;o;o>>=1){ if(t<o) rd[t]+=rd[t+o]; __syncthreads(); }
    if(t==0) atomicAdd(&g_acc[0],rd[0]);
}

__global__ void k_out(float* out){
    out[0]=(float)(g_acc[0]/CNT);
    out[1]=(float)(g_acc[1]/CNT);
    out[2]=(float)(16.0*g_acc[4]/CNT);
    out[3]=(float)(g_acc[2]/CNT);
    out[4]=(float)(g_acc[3]/CNT);
}

extern "C" void kernel_launch(void* const* d_in,const int* in_sizes,int n_in,
                              void* d_out,int out_size){
    const int*   edges=(const int*)d_in[0];
    const int*   sidx =(const int*)d_in[1];
    const float* epp  =(const float*)d_in[2];
    const float* epb  =(const float*)d_in[3];
    const float* ug   =(const float*)d_in[4];
    const float* amean=(const float*)d_in[5];
    const float* astd =(const float*)d_in[6];
    const float* Ws2p =(const float*)d_in[7];  const float* bs2p=(const float*)d_in[8];
    const float* Ws2b =(const float*)d_in[9];  const float* bs2b=(const float*)d_in[10];
    const float* Wbm  =(const float*)d_in[11]; const float* bbm =(const float*)d_in[12];
    const float* Wbs  =(const float*)d_in[13]; const float* bbs =(const float*)d_in[14];
    const float* Wpm  =(const float*)d_in[15]; const float* bpm =(const float*)d_in[16];
    const float* Wps  =(const float*)d_in[17]; const float* bps =(const float*)d_in[18];
    const float* Wpi  =(const float*)d_in[19];
    const float* WihN =(const float*)d_in[20]; const float* WhhN=(const float*)d_in[21];
    const float* bihN =(const float*)d_in[22]; const float* bhhN=(const float*)d_in[23];
    const float* WihC =(const float*)d_in[24]; const float* WhhC=(const float*)d_in[25];
    const float* bihC =(const float*)d_in[26]; const float* bhhC=(const float*)d_in[27];
    const float* Wdec =(const float*)d_in[28];
    float* out=(float*)d_out;

    int smem1 = 192*258*4;   // 198144: A 64x258 + W 128x258
    int smem2 = 192*130*4;   //  99840
    cudaFuncSetAttribute(k_gemm<256>,cudaFuncAttributeMaxDynamicSharedMemorySize,smem1);
    cudaFuncSetAttribute(k_gemm<128>,cudaFuncAttributeMaxDynamicSharedMemorySize,smem2);

    k_init0<<<1,128>>>(sidx,amean,astd);
    k_initW<<<644,256>>>(WihN,WhhN,bihN,bhhN,WihC,WhhC,bihC,bhhC,
                         Wpm,bpm,Wps,bps,Wbm,bbm,Wbs,bbs);
    k_initS<<<1033,256>>>(Ws2p,bs2p,Ws2b,bs2b);
    for(int t=0;t<16;t++){
        int pp=t&1;
        k_gemm<256><<<dim3(33,4),256,smem1>>>(pp);
        k_act<<<1033,256>>>(pp);
        k_gemm<128><<<dim3(33,2),256,smem2>>>(pp);
        k_sample<<<1033,256>>>(pp, epp+(size_t)t*NN*DD, epb+(size_t)t*KK*DD);
        k_matM<<<8,256>>>(pp, Wdec);
        k_logits<<<128,128>>>(pp, edges+(size_t)t*EE*2,
                              ug+(size_t)t*2*EE*KK, Wpi);
        k_scan<<<dim3(128,4),256>>>();
        k_fin<<<64,256>>>();
    }
    k_out<<<1,1>>>(out);
}

// round 11
// speedup vs baseline: 2.6493x; 1.0781x over previous
#include <cuda_runtime.h>
#include <math.h>

#define NN 2048
#define DD 128
#define KK 16
#define EE 8192
#define TWOE 16384
#define ROWS 2064               // 2048 phi rows + 16 beta rows
#define CNT 262144.0

typedef unsigned long long ull;

__device__ float g_s[2][ROWS*DD];     // phi_s rows 0..2047, beta_s rows 2048..2063
__device__ float g_h[2][ROWS*DD];
__device__ float g_M[NN*KK];          // n-major, k contiguous
__device__ float g_Z[TWOE*KK];
__device__ float g_sE[TWOE];
__device__ float g_vcE[TWOE];
__device__ int   g_cE[TWOE];
__device__ float g_W1n[512*256], g_W1c[512*256];   // rows interleaved 4d+{r,z,in,hn}
__device__ float g_b1n[512],     g_b1c[512];
__device__ float g_W2n[256*DD],  g_W2c[256*DD];    // rows interleaved 2d+{mean,std}
__device__ float g_b2n[256],     g_b2c[256];
__device__ float g_am[DD];
__device__ double g_acc[5];           // nll, kldz, kldb, kldp, kld_alpha
__device__ float g_Mmax;

__device__ __forceinline__ float fsig(float x){ return 1.f/(1.f+__expf(-x)); }
__device__ __forceinline__ float ftanh(float x){
    float e=__expf(fminf(fmaxf(2.f*x,-30.f),30.f)); return (e-1.f)/(e+1.f); }
__device__ __forceinline__ float fsoftplus(float x){
    return fmaxf(x,0.f)+log1pf(__expf(-fabsf(x))); }
__device__ __forceinline__ void atomicMaxF(float* a, float v){
    int cur=__float_as_int(*a);
    while(__int_as_float(cur)<v){ int as=cur;
        cur=atomicCAS((int*)a,as,__float_as_int(v));
        if(cur==as) break; }
}
__device__ __forceinline__ ull ffma2(ull a, ull b, ull c){
    asm("fma.rn.f32x2 %0,%1,%2,%3;":"=l"(c):"l"(a),"l"(b),"l"(c));
    return c;
}
__device__ __forceinline__ ull fadd2(ull a, ull b){
    ull r; asm("add.rn.f32x2 %0,%1,%2;":"=l"(r):"l"(a),"l"(b));
    return r;
}
__device__ __forceinline__ float upsum(ull v){
    float lo,hi; asm("mov.b64 {%0,%1},%2;":"=f"(lo),"=f"(hi):"l"(v));
    return lo+hi;
}

__global__ void k_init0(const int* sidx,const float* am,const float* as){
    int t=threadIdx.x; int s=sidx[0];
    __shared__ float red[128];
    float m=am[(size_t)s*DD+t];
    float sd=fsoftplus(as[(size_t)s*DD+t]);
    g_am[t]=m;
    red[t]=0.5f*(-2.f*logf(sd)+sd*sd+m*m-1.f);
    __syncthreads();
    for(int o=64;o;o>>=1){ if(t<o) red[t]+=red[t+o]; __syncthreads(); }
    if(t==0){ g_acc[4]=(double)red[0]; g_acc[0]=g_acc[1]=g_acc[2]=g_acc[3]=0.0; }
}

__global__ void k_initW(const float* WihN,const float* WhhN,const float* bihN,const float* bhhN,
                        const float* WihC,const float* WhhC,const float* bihC,const float* bhhC,
                        const float* Wpm,const float* bpm,const float* Wps,const float* bps,
                        const float* Wbm,const float* bbm,const float* Wbs,const float* bbs){
    int i=blockIdx.x*256+threadIdx.x;
    if(i<131072){                                  // W1: row j'=4d+gate, 512 x 256
        int j=i>>8, c=i&255;
        int d=j>>2, gate=j&3;
        float vn,vc;
        if(gate==0||gate==1){
            int jr=gate*128+d;
            if(c<128){ vn=WihN[jr*256+c]+WihN[jr*256+128+c];
                       vc=WihC[jr*256+c]+WihC[jr*256+128+c]; }
            else     { vn=WhhN[jr*128+c-128]; vc=WhhC[jr*128+c-128]; }
        } else if(gate==2){
            int jr=256+d;
            if(c<128){ vn=WihN[jr*256+c]+WihN[jr*256+128+c];
                       vc=WihC[jr*256+c]+WihC[jr*256+128+c]; }
            else     { vn=0.f; vc=0.f; }
        } else {
            int jr=256+d;
            if(c<128){ vn=0.f; vc=0.f; }
            else     { vn=WhhN[jr*128+c-128]; vc=WhhC[jr*128+c-128]; }
        }
        g_W1n[i]=vn; g_W1c[i]=vc;
    } else if(i<163840){                           // W2: row j'=2d+m, 256 x 128
        int o=i-131072, j=o>>7, c=o&127;
        int d=j>>1, m=j&1;
        g_W2n[o] = m==0 ? Wpm[d*128+c] : Wps[d*128+c];
        g_W2c[o] = m==0 ? Wbm[d*128+c] : Wbs[d*128+c];
    } else if(i<164352){                           // b1
        int j=i-163840; int d=j>>2, gate=j&3; float bn,bc;
        if(gate==0||gate==1){ int jr=gate*128+d;
            bn=bihN[jr]+bhhN[jr]; bc=bihC[jr]+bhhC[jr]; }
        else if(gate==2){ bn=bihN[256+d]; bc=bihC[256+d]; }
        else            { bn=bhhN[256+d]; bc=bhhC[256+d]; }
        g_b1n[j]=bn; g_b1c[j]=bc;
    } else if(i<164608){                           // b2
        int j=i-164352; int d=j>>1, m=j&1;
        g_b2n[j] = m==0 ? bpm[d] : bps[d];
        g_b2c[j] = m==0 ? bbm[d] : bbs[d];
    }
}

__global__ void k_initS(const float* Wp,const float* bp,const float* Wb,const float* bb){
    __shared__ float am[DD];
    int tid=threadIdx.x;
    if(tid<DD) am[tid]=g_am[tid];
    __syncthreads();
    int i=blockIdx.x*256+tid; if(i>=ROWS*DD) return;
    const float* wr; float bias;
    if(i<NN*DD){ wr=Wp+(size_t)i*DD; bias=bp[i]; }
    else { int o=i-NN*DD; wr=Wb+(size_t)o*DD; bias=bb[o]; }
    const float4* w4=(const float4*)wr; const float4* a4=(const float4*)am;
    float acc=bias;
    #pragma unroll 8
    for(int q=0;q<32;q++){ float4 w=w4[q],a=a4[q];
        acc+=w.x*a.x+w.y*a.y+w.z*a.z+w.w*a.w; }
    g_s[0][i]=acc; g_h[0][i]=0.f;
}

// GRU GEMM + fused activation. Block tile 64x128, thread tile 8x4 (=1 d quad).
// K staged in 4 chunks of 64 (smem 50.7KB -> 2 blocks/SM by regs).
__global__ __launch_bounds__(256) void k_gru(int pp){
    extern __shared__ float sm[];
    float* As=sm;            // [64][66]
    float* Ws=sm+64*66;      // [128][66]
    int mT=blockIdx.x, pT=blockIdx.y, tid=threadIdx.x;
    if(mT==0&&pT==0&&tid==0) g_Mmax=-1e30f;
    int beta=(mT==32);
    int row0=beta?2048:mT*64, rowsEff=beta?16:64, p0=pT*128;
    const float* W   = beta? g_W1c : g_W1n;
    const float* bias= beta? g_b1c : g_b1n;
    const float* S0=g_s[pp]; const float* H0=g_h[pp];
    float* H1=g_h[1-pp];
    int g=tid&7, cp=(tid>>3)*4;
    ull acc[8][4];
    #pragma unroll
    for(int i=0;i<8;i++)
        #pragma unroll
        for(int j=0;j<4;j++) acc[i][j]=0ull;
    for(int kc=0;kc<4;kc++){
        const float* src = kc<2 ? S0 : H0;
        int kb=(kc&1)*64;
        for(int i=tid;i<64*16;i+=256){
            int r=i>>4, c4=i&15;
            float4 v=make_float4(0.f,0.f,0.f,0.f);
            if(r<rowsEff) v=*(const float4*)(src+(size_t)(row0+r)*DD+kb+c4*4);
            float* dst=As+r*66+c4*4;
            *(float2*)dst=make_float2(v.x,v.y);
            *(float2*)(dst+2)=make_float2(v.z,v.w);
        }
        for(int i=tid;i<128*16;i+=256){
            int r=i>>4, c4=i&15;
            float4 v=*(const float4*)(W+(size_t)(p0+r)*256+kc*64+c4*4);
            float* dst=Ws+r*66+c4*4;
            *(float2*)dst=make_float2(v.x,v.y);
            *(float2*)(dst+2)=make_float2(v.z,v.w);
        }
        __syncthreads();
        const float* Ab=As+g*66;
        const float* Wb=Ws+cp*66;
        #pragma unroll 4
        for(int d2=0;d2<32;d2++){
            int off=2*d2;
            ull w0=*(const ull*)(Wb+0*66+off);
            ull w1=*(const ull*)(Wb+1*66+off);
            ull w2=*(const ull*)(Wb+2*66+off);
            ull w3=*(const ull*)(Wb+3*66+off);
            #pragma unroll
            for(int i=0;i<8;i++){
                ull x=*(const ull*)(Ab+i*8*66+off);
                acc[i][0]=ffma2(x,w0,acc[i][0]);
                acc[i][1]=ffma2(x,w1,acc[i][1]);
                acc[i][2]=ffma2(x,w2,acc[i][2]);
                acc[i][3]=ffma2(x,w3,acc[i][3]);
            }
        }
        __syncthreads();
    }
    int d=(p0+cp)>>2;
    float b0=bias[p0+cp],b1=bias[p0+cp+1],b2=bias[p0+cp+2],b3=bias[p0+cp+3];
    #pragma unroll
    for(int i=0;i<8;i++){
        int r=g+8*i;
        if(r<rowsEff){
            int row=row0+r;
            float q0=upsum(acc[i][0])+b0;
            float q1=upsum(acc[i][1])+b1;
            float q2=upsum(acc[i][2])+b2;
            float q3=upsum(acc[i][3])+b3;
            float rg=fsig(q0), zg=fsig(q1);
            float nn=ftanh(q2+rg*q3);
            float hold=H0[(size_t)row*DD+d];
            H1[(size_t)row*DD+d]=(1.f-zg)*nn+zg*hold;
        }
    }
}

// Head GEMM + fused sampling + KLD. Block 64x128, thread 8x4 (= 2 (mean,std) pairs).
__global__ __launch_bounds__(256) void k_head(int pp,const float* ept,const float* ebt){
    extern __shared__ float sm[];
    float* As=sm;            // [64][66]
    float* Ws=sm+64*66;      // [128][66]
    __shared__ double r1[256],r2[256];
    int mT=blockIdx.x, pT=blockIdx.y, tid=threadIdx.x;
    int beta=(mT==32);
    int row0=beta?2048:mT*64, rowsEff=beta?16:64, p0=pT*128;
    const float* W   = beta? g_W2c : g_W2n;
    const float* bias= beta? g_b2c : g_b2n;
    const float* H1=g_h[1-pp];
    const float* Sp=g_s[pp];
    float* Sn=g_s[1-pp];
    int g=tid&7, cp=(tid>>3)*4;
    ull acc[8][4];
    #pragma unroll
    for(int i=0;i<8;i++)
        #pragma unroll
        for(int j=0;j<4;j++) acc[i][j]=0ull;
    for(int kc=0;kc<2;kc++){
        int kb=kc*64;
        for(int i=tid;i<64*16;i+=256){
            int r=i>>4, c4=i&15;
            float4 v=make_float4(0.f,0.f,0.f,0.f);
            if(r<rowsEff) v=*(const float4*)(H1+(size_t)(row0+r)*DD+kb+c4*4);
            float* dst=As+r*66+c4*4;
            *(float2*)dst=make_float2(v.x,v.y);
            *(float2*)(dst+2)=make_float2(v.z,v.w);
        }
        for(int i=tid;i<128*16;i+=256){
            int r=i>>4, c4=i&15;
            float4 v=*(const float4*)(W+(size_t)(p0+r)*DD+kb+c4*4);
            float* dst=Ws+r*66+c4*4;
            *(float2*)dst=make_float2(v.x,v.y);
            *(float2*)(dst+2)=make_float2(v.z,v.w);
        }
        __syncthreads();
        const float* Ab=As+g*66;
        const float* Wb=Ws+cp*66;
        #pragma unroll 4
        for(int d2=0;d2<32;d2++){
            int off=2*d2;
            ull w0=*(const ull*)(Wb+0*66+off);
            ull w1=*(const ull*)(Wb+1*66+off);
            ull w2=*(const ull*)(Wb+2*66+off);
            ull w3=*(const ull*)(Wb+3*66+off);
            #pragma unroll
            for(int i=0;i<8;i++){
                ull x=*(const ull*)(Ab+i*8*66+off);
                acc[i][0]=ffma2(x,w0,acc[i][0]);
                acc[i][1]=ffma2(x,w1,acc[i][1]);
                acc[i][2]=ffma2(x,w2,acc[i][2]);
                acc[i][3]=ffma2(x,w3,acc[i][3]);
            }
        }
        __syncthreads();
    }
    int d0=(p0+cp)>>1;        // cols = mean_d0,std_d0,mean_{d0+1},std_{d0+1}
    float b0=bias[p0+cp],b1=bias[p0+cp+1],b2=bias[p0+cp+2],b3=bias[p0+cp+3];
    double kp=0.0,kb2=0.0;
    #pragma unroll
    for(int i=0;i<8;i++){
        int r=g+8*i;
        if(r<rowsEff){
            int row=row0+r;
            float m0=upsum(acc[i][0])+b0;
            float s0=fsoftplus(upsum(acc[i][1])+b1);
            float m1=upsum(acc[i][2])+b2;
            float s1=fsoftplus(upsum(acc[i][3])+b3);
            float p0v=Sp[(size_t)row*DD+d0], p1v=Sp[(size_t)row*DD+d0+1];
            float e0,e1;
            if(row<NN){ e0=ept[(size_t)row*DD+d0]; e1=ept[(size_t)row*DD+d0+1]; }
            else      { e0=ebt[(size_t)(row-NN)*DD+d0]; e1=ebt[(size_t)(row-NN)*DD+d0+1]; }
            Sn[(size_t)row*DD+d0]  =m0+s0*e0;
            Sn[(size_t)row*DD+d0+1]=m1+s1*e1;
            float dm0=m0-p0v, dm1=m1-p1v;
            if(row<NN){
                kp+=0.5*(-2.0*(double)logf(s0)+(double)s0*s0+(double)dm0*dm0-1.0);
                kp+=0.5*(-2.0*(double)logf(s1)+(double)s1*s1+(double)dm1*dm1-1.0);
            } else {
                kb2+=0.5*(2.0*(-2.302585092994046-(double)logf(s0))
                         +((double)s0*s0+(double)dm0*dm0)*100.0-1.0);
                kb2+=0.5*(2.0*(-2.302585092994046-(double)logf(s1))
                         +((double)s1*s1+(double)dm1*dm1)*100.0-1.0);
            }
        }
    }
    r1[tid]=kp; r2[tid]=kb2;
    __syncthreads();
    for(int o=128;o;o>>=1){ if(tid<o){ r1[tid]+=r1[tid+o]; r2[tid]+=r2[tid+o]; } __syncthreads(); }
    if(tid==0){ if(r1[0]!=0.0) atomicAdd(&g_acc[3],r1[0]);
                if(r2[0]!=0.0) atomicAdd(&g_acc[2],r2[0]); }
}

__global__ void k_matM(int pp,const float* Wdec){
    __shared__ float bs[KK*DD];
    __shared__ float wm[8];
    int t=threadIdx.x, po=1-pp;
    for(int i=t;i<KK*DD;i+=256) bs[i]=g_s[po][NN*DD+i];
    __syncthreads();
    int n=blockIdx.x*256+t;
    float acc[KK];
    #pragma unroll
    for(int k=0;k<KK;k++) acc[k]=0.f;
    const float4* w4=(const float4*)(Wdec+(size_t)n*DD);
    for(int q=0;q<32;q++){ float4 w=w4[q];
        #pragma unroll
        for(int k=0;k<KK;k++){ float4 b=((const float4*)(bs+k*DD))[q];
            acc[k]+=w.x*b.x+w.y*b.y+w.z*b.z+w.w*b.w; } }
    float mx=acc[0];
    #pragma unroll
    for(int k=0;k<KK;k++){ g_M[n*KK+k]=acc[k]; mx=fmaxf(mx,acc[k]); }
    for(int o=16;o;o>>=1) mx=fmaxf(mx,__shfl_xor_sync(0xffffffffu,mx,o));
    if((t&31)==0) wm[t>>5]=mx;
    __syncthreads();
    if(t==0){ float b=wm[0];
        #pragma unroll
        for(int j=1;j<8;j++) b=fmaxf(b,wm[j]);
        atomicMaxF(&g_Mmax,b); }
}

// per-edge logits, softmaxes, KL(z), gumbel z -> g_Z; zero per-edge accums.
__global__ void k_logits(int pp,const int* edt,const float* ut,const float* Wpi){
    __shared__ float Pt[DD*KK];   // [d][k]
    __shared__ float Bt[DD*KK];
    __shared__ double rd[128];
    int t=threadIdx.x, po=1-pp;
    for(int i=t;i<DD*KK;i+=128){ int d=i>>4,k=i&15;
        Pt[i]=Wpi[k*DD+d]; Bt[i]=g_s[po][NN*DD+k*DD+d]; }
    __syncthreads();
    int e=blockIdx.x*128+t, w,c;
    if(e<EE){ w=edt[2*e]; c=edt[2*e+1]; } else { int e2=e-EE; w=edt[2*e2+1]; c=edt[2*e2]; }
    const float4* pw4=(const float4*)(g_s[po]+(size_t)w*DD);
    const float4* pc4=(const float4*)(g_s[po]+(size_t)c*DD);
    float lq[KK],lp[KK];
    #pragma unroll
    for(int k=0;k<KK;k++){ lq[k]=0.f; lp[k]=0.f; }
    for(int q=0;q<32;q++){
        float4 a=pw4[q], b=pc4[q];
        float aw[4]={a.x,a.y,a.z,a.w};
        float pr[4]={a.x*b.x,a.y*b.y,a.z*b.z,a.w*b.w};
        #pragma unroll
        for(int j=0;j<4;j++){ int d=q*4+j;
            const float4* P4=(const float4*)(Pt+d*KK);
            const float4* B4=(const float4*)(Bt+d*KK);
            #pragma unroll
            for(int h=0;h<4;h++){
                float4 P=P4[h], B=B4[h];
                lq[4*h+0]+=pr[j]*P.x; lq[4*h+1]+=pr[j]*P.y;
                lq[4*h+2]+=pr[j]*P.z; lq[4*h+3]+=pr[j]*P.w;
                lp[4*h+0]+=aw[j]*B.x; lp[4*h+1]+=aw[j]*B.y;
                lp[4*h+2]+=aw[j]*B.z; lp[4*h+3]+=aw[j]*B.w;
            }
        }
    }
    float mq=-3e38f,mp=-3e38f;
    #pragma unroll
    for(int k=0;k<KK;k++){ mq=fmaxf(mq,lq[k]); mp=fmaxf(mp,lp[k]); }
    float sq=0,sp=0;
    #pragma unroll
    for(int k=0;k<KK;k++){ sq+=__expf(lq[k]-mq); sp+=__expf(lp[k]-mp); }
    float lsq=__logf(sq), lsp=__logf(sp), kz=0.f;
    #pragma unroll
    for(int k=0;k<KK;k++){ float lpo=lq[k]-mq-lsq;
        kz+=__expf(lpo)*(lpo-(lp[k]-mp-lsp)); }
    const float4* u4=(const float4*)(ut+(size_t)e*KK);
    float ze[KK];
    #pragma unroll
    for(int q=0;q<4;q++){ float4 u=u4[q]; float uu[4]={u.x,u.y,u.z,u.w};
        #pragma unroll
        for(int j=0;j<4;j++)
            ze[q*4+j]=lq[q*4+j]-__logf(-__logf(uu[j]+1e-10f)+1e-10f); }
    float mz=-3e38f;
    #pragma unroll
    for(int k=0;k<KK;k++) mz=fmaxf(mz,ze[k]);
    float sz=0;
    #pragma unroll
    for(int k=0;k<KK;k++){ ze[k]=__expf(ze[k]-mz); sz+=ze[k]; }
    float inv=1.f/sz;
    float4* zo=(float4*)(g_Z+(size_t)e*KK);
    #pragma unroll
    for(int q=0;q<4;q++){
        float4 v; v.x=ze[q*4]*inv; v.y=ze[q*4+1]*inv;
        v.z=ze[q*4+2]*inv; v.w=ze[q*4+3]*inv; zo[q]=v; }
    g_cE[e]=c; g_sE[e]=0.f; g_vcE[e]=0.f;
    rd[t]=(double)kz; __syncthreads();
    for(int o=64;o;o>>=1){ if(t<o) rd[t]+=rd[t+o]; __syncthreads(); }
    if(t==0) atomicAdd(&g_acc[1],rd[0]);
}

// N-scan: grid (128 edge-tiles, 4 n-tiles), 256 thr; 2 threads per edge.
__global__ __launch_bounds__(256) void k_scan(){
    __shared__ float Ms[512*KK];
    __shared__ float Zs[128*KK];
    __shared__ float s_red[256], v_red[256];
    int tid=threadIdx.x;
    int n0=blockIdx.y*512, e0=blockIdx.x*128;
    for(int i=tid;i<512*KK;i+=256) Ms[i]=g_M[n0*KK+i];
    for(int i=tid;i<128*KK;i+=256) Zs[i]=g_Z[(size_t)e0*KK+i];
    __syncthreads();
    int li=tid&127, sub=tid>>7;
    int e=e0+li;
    int c=g_cE[e];
    ull zp[8];
    {   const ull* z8=(const ull*)(Zs+li*KK);
        #pragma unroll
        for(int q=0;q<8;q++) zp[q]=z8[q]; }
    float Mx=g_Mmax;
    float s0=0.f,s1=0.f,vc=0.f;
    int base=n0+sub*256;
    #pragma unroll 2
    for(int j=0;j<256;j+=2){
        const ulonglong2* m0=(const ulonglong2*)(Ms+(sub*256+j)*KK);
        const ulonglong2* m1=(const ulonglong2*)(Ms+(sub*256+j+1)*KK);
        ulonglong2 A0=m0[0],A1=m0[1],A2=m0[2],A3=m0[3];
        ulonglong2 B0=m1[0],B1=m1[1],B2=m1[2],B3=m1[3];
        ull ta=ffma2(zp[0],A0.x,0ull); ull tb=ffma2(zp[1],A0.y,0ull);
        ta=ffma2(zp[2],A1.x,ta);       tb=ffma2(zp[3],A1.y,tb);
        ta=ffma2(zp[4],A2.x,ta);       tb=ffma2(zp[5],A2.y,tb);
        ta=ffma2(zp[6],A3.x,ta);       tb=ffma2(zp[7],A3.y,tb);
        ull tc=ffma2(zp[0],B0.x,0ull); ull td=ffma2(zp[1],B0.y,0ull);
        tc=ffma2(zp[2],B1.x,tc);       td=ffma2(zp[3],B1.y,td);
        tc=ffma2(zp[4],B2.x,tc);       td=ffma2(zp[5],B2.y,td);
        tc=ffma2(zp[6],B3.x,tc);       td=ffma2(zp[7],B3.y,td);
        float v0=upsum(fadd2(ta,tb));
        float v1=upsum(fadd2(tc,td));
        s0+=__expf(v0-Mx); s1+=__expf(v1-Mx);
        if(base+j==c)   vc=v0;
        if(base+j+1==c) vc=v1;
    }
    s_red[tid]=s0+s1; v_red[tid]=vc;
    __syncthreads();
    if(sub==0){
        float st=s_red[li]+s_red[li+128];
        float vt=v_red[li]+v_red[li+128];
        atomicAdd(&g_sE[e],st);
        if(c>=n0 && c<n0+512) atomicAdd(&g_vcE[e],vt);
    }
}

__global__ void k_fin(){
    __shared__ double rd[256];
    int t=threadIdx.x;
    int e=blockIdx.x*256+t;
    double nll=0.0;
    if(e<TWOE)
        nll=(double)(-(g_vcE[e]-g_Mmax-__logf(g_sE[e])));
    rd[t]=nll; __syncthreads();
    for(int o=128;o;o>>=1){ if(t<o) rd[t]+=rd[t+o]; __syncthreads(); }
    if(t==0) atomicAdd(&g_acc[0],rd[0]);
}

__global__ void k_out(float* out){
    out[0]=(float)(g_acc[0]/CNT);
    out[1]=(float)(g_acc[1]/CNT);
    out[2]=(float)(16.0*g_acc[4]/CNT);
    out[3]=(float)(g_acc[2]/CNT);
    out[4]=(float)(g_acc[3]/CNT);
}

extern "C" void kernel_launch(void* const* d_in,const int* in_sizes,int n_in,
                              void* d_out,int out_size){
    const int*   edges=(const int*)d_in[0];
    const int*   sidx =(const int*)d_in[1];
    const float* epp  =(const float*)d_in[2];
    const float* epb  =(const float*)d_in[3];
    const float* ug   =(const float*)d_in[4];
    const float* amean=(const float*)d_in[5];
    const float* astd =(const float*)d_in[6];
    const float* Ws2p =(const float*)d_in[7];  const float* bs2p=(const float*)d_in[8];
    const float* Ws2b =(const float*)d_in[9];  const float* bs2b=(const float*)d_in[10];
    const float* Wbm  =(const float*)d_in[11]; const float* bbm =(const float*)d_in[12];
    const float* Wbs  =(const float*)d_in[13]; const float* bbs =(const float*)d_in[14];
    const float* Wpm  =(const float*)d_in[15]; const float* bpm =(const float*)d_in[16];
    const float* Wps  =(const float*)d_in[17]; const float* bps =(const float*)d_in[18];
    const float* Wpi  =(const float*)d_in[19];
    const float* WihN =(const float*)d_in[20]; const float* WhhN=(const float*)d_in[21];
    const float* bihN =(const float*)d_in[22]; const float* bhhN=(const float*)d_in[23];
    const float* WihC =(const float*)d_in[24]; const float* WhhC=(const float*)d_in[25];
    const float* bihC =(const float*)d_in[26]; const float* bhhC=(const float*)d_in[27];
    const float* Wdec =(const float*)d_in[28];
    float* out=(float*)d_out;

    int smemG = (64*66+128*66)*4;     // 50688
    cudaFuncSetAttribute(k_gru, cudaFuncAttributeMaxDynamicSharedMemorySize,smemG);
    cudaFuncSetAttribute(k_head,cudaFuncAttributeMaxDynamicSharedMemorySize,smemG);

    k_init0<<<1,128>>>(sidx,amean,astd);
    k_initW<<<644,256>>>(WihN,WhhN,bihN,bhhN,WihC,WhhC,bihC,bhhC,
                         Wpm,bpm,Wps,bps,Wbm,bbm,Wbs,bbs);
    k_initS<<<1033,256>>>(Ws2p,bs2p,Ws2b,bs2b);
    for(int t=0;t<16;t++){
        int pp=t&1;
        k_gru<<<dim3(33,4),256,smemG>>>(pp);
        k_head<<<dim3(33,2),256,smemG>>>(pp, epp+(size_t)t*NN*DD, epb+(size_t)t*KK*DD);
        k_matM<<<8,256>>>(pp, Wdec);
        k_logits<<<128,128>>>(pp, edges+(size_t)t*EE*2,
                              ug+(size_t)t*2*EE*KK, Wpi);
        k_scan<<<dim3(128,4),256>>>();
        k_fin<<<64,256>>>();
    }
    k_out<<<1,1>>>(out);
}

// round 12
// speedup vs baseline: 3.1315x; 1.1820x over previous
#include <cuda_runtime.h>
#include <math.h>

#define NN 2048
#define DD 128
#define KK 16
#define EE 8192
#define TWOE 16384
#define ROWS 2064               // 2048 phi rows + 16 beta rows
#define CNT 262144.0

typedef unsigned long long ull;

__device__ float g_s[2][ROWS*DD];     // phi_s rows 0..2047, beta_s rows 2048..2063
__device__ float g_h[2][ROWS*DD];
__device__ float g_M[NN*KK];          // n-major, k contiguous
__device__ float g_Z[TWOE*KK];
__device__ float g_sE[TWOE];
__device__ float g_vcE[TWOE];
__device__ int   g_cE[TWOE];
__device__ int   g_scnt[128];
__device__ float g_W1n[512*256], g_W1c[512*256];   // rows interleaved 4d+{r,z,in,hn}
__device__ float g_b1n[512],     g_b1c[512];
__device__ float g_W2n[256*DD],  g_W2c[256*DD];    // rows interleaved 2d+{mean,std}
__device__ float g_b2n[256],     g_b2c[256];
__device__ float g_am[DD];
__device__ double g_acc[5];           // nll, kldz, kldb, kldp, kld_alpha
__device__ float g_Mmax;

__device__ __forceinline__ float fsig(float x){ return 1.f/(1.f+__expf(-x)); }
__device__ __forceinline__ float ftanh(float x){
    float e=__expf(fminf(fmaxf(2.f*x,-30.f),30.f)); return (e-1.f)/(e+1.f); }
__device__ __forceinline__ float fsoftplus(float x){
    return fmaxf(x,0.f)+log1pf(__expf(-fabsf(x))); }
__device__ __forceinline__ void atomicMaxF(float* a, float v){
    int cur=__float_as_int(*a);
    while(__int_as_float(cur)<v){ int as=cur;
        cur=atomicCAS((int*)a,as,__float_as_int(v));
        if(cur==as) break; }
}
__device__ __forceinline__ ull ffma2(ull a, ull b, ull c){
    asm("fma.rn.f32x2 %0,%1,%2,%3;":"=l"(c):"l"(a),"l"(b),"l"(c));
    return c;
}
__device__ __forceinline__ ull fadd2(ull a, ull b){
    ull r; asm("add.rn.f32x2 %0,%1,%2;":"=l"(r):"l"(a),"l"(b));
    return r;
}
__device__ __forceinline__ float upsum(ull v){
    float lo,hi; asm("mov.b64 {%0,%1},%2;":"=f"(lo),"=f"(hi):"l"(v));
    return lo+hi;
}

__global__ void k_init0(const int* sidx,const float* am,const float* as){
    int t=threadIdx.x; int s=sidx[0];
    __shared__ float red[128];
    float m=am[(size_t)s*DD+t];
    float sd=fsoftplus(as[(size_t)s*DD+t]);
    g_am[t]=m;
    red[t]=0.5f*(-2.f*logf(sd)+sd*sd+m*m-1.f);
    __syncthreads();
    for(int o=64;o;o>>=1){ if(t<o) red[t]+=red[t+o]; __syncthreads(); }
    if(t==0){ g_acc[4]=(double)red[0]; g_acc[0]=g_acc[1]=g_acc[2]=g_acc[3]=0.0; }
}

__global__ void k_initW(const float* WihN,const float* WhhN,const float* bihN,const float* bhhN,
                        const float* WihC,const float* WhhC,const float* bihC,const float* bhhC,
                        const float* Wpm,const float* bpm,const float* Wps,const float* bps,
                        const float* Wbm,const float* bbm,const float* Wbs,const float* bbs){
    int i=blockIdx.x*256+threadIdx.x;
    if(i<131072){                                  // W1: row j'=4d+gate, 512 x 256
        int j=i>>8, c=i&255;
        int d=j>>2, gate=j&3;
        float vn,vc;
        if(gate==0||gate==1){
            int jr=gate*128+d;
            if(c<128){ vn=WihN[jr*256+c]+WihN[jr*256+128+c];
                       vc=WihC[jr*256+c]+WihC[jr*256+128+c]; }
            else     { vn=WhhN[jr*128+c-128]; vc=WhhC[jr*128+c-128]; }
        } else if(gate==2){
            int jr=256+d;
            if(c<128){ vn=WihN[jr*256+c]+WihN[jr*256+128+c];
                       vc=WihC[jr*256+c]+WihC[jr*256+128+c]; }
            else     { vn=0.f; vc=0.f; }
        } else {
            int jr=256+d;
            if(c<128){ vn=0.f; vc=0.f; }
            else     { vn=WhhN[jr*128+c-128]; vc=WhhC[jr*128+c-128]; }
        }
        g_W1n[i]=vn; g_W1c[i]=vc;
    } else if(i<163840){                           // W2: row j'=2d+m, 256 x 128
        int o=i-131072, j=o>>7, c=o&127;
        int d=j>>1, m=j&1;
        g_W2n[o] = m==0 ? Wpm[d*128+c] : Wps[d*128+c];
        g_W2c[o] = m==0 ? Wbm[d*128+c] : Wbs[d*128+c];
    } else if(i<164352){                           // b1
        int j=i-163840; int d=j>>2, gate=j&3; float bn,bc;
        if(gate==0||gate==1){ int jr=gate*128+d;
            bn=bihN[jr]+bhhN[jr]; bc=bihC[jr]+bhhC[jr]; }
        else if(gate==2){ bn=bihN[256+d]; bc=bihC[256+d]; }
        else            { bn=bhhN[256+d]; bc=bhhC[256+d]; }
        g_b1n[j]=bn; g_b1c[j]=bc;
    } else if(i<164608){                           // b2
        int j=i-164352; int d=j>>1, m=j&1;
        g_b2n[j] = m==0 ? bpm[d] : bps[d];
        g_b2c[j] = m==0 ? bbm[d] : bbs[d];
    }
}

__global__ void k_initS(const float* Wp,const float* bp,const float* Wb,const float* bb){
    __shared__ float am[DD];
    int tid=threadIdx.x;
    if(tid<DD) am[tid]=g_am[tid];
    __syncthreads();
    int i=blockIdx.x*256+tid; if(i>=ROWS*DD) return;
    const float* wr; float bias;
    if(i<NN*DD){ wr=Wp+(size_t)i*DD; bias=bp[i]; }
    else { int o=i-NN*DD; wr=Wb+(size_t)o*DD; bias=bb[o]; }
    const float4* w4=(const float4*)wr; const float4* a4=(const float4*)am;
    float acc=bias;
    #pragma unroll 8
    for(int q=0;q<32;q++){ float4 w=w4[q],a=a4[q];
        acc+=w.x*a.x+w.y*a.y+w.z*a.z+w.w*a.w; }
    g_s[0][i]=acc; g_h[0][i]=0.f;
}

// GRU GEMM + fused activation. Block tile 32x128, 256 thr, thread tile 4x4.
// grid (65,4) = 260 blocks -> 2 blocks/SM on most SMs (16 warps).
__global__ __launch_bounds__(256) void k_gru(int pp){
    extern __shared__ float sm[];
    float* As=sm;            // [32][66]
    float* Ws=sm+32*66;      // [128][66]
    int mT=blockIdx.x, pT=blockIdx.y, tid=threadIdx.x;
    if(mT==0&&pT==0&&tid==0) g_Mmax=-1e30f;
    int beta=(mT==64);
    int row0=beta?2048:mT*32, rowsEff=beta?16:32, p0=pT*128;
    const float* W   = beta? g_W1c : g_W1n;
    const float* bias= beta? g_b1c : g_b1n;
    const float* S0=g_s[pp]; const float* H0=g_h[pp];
    float* H1=g_h[1-pp];
    int g=tid&7, cp=(tid>>3)*4;
    ull acc[4][4];
    #pragma unroll
    for(int i=0;i<4;i++)
        #pragma unroll
        for(int j=0;j<4;j++) acc[i][j]=0ull;
    for(int kc=0;kc<4;kc++){
        const float* src = kc<2 ? S0 : H0;
        int kb=(kc&1)*64;
        for(int i=tid;i<32*16;i+=256){
            int r=i>>4, c4=i&15;
            float4 v=make_float4(0.f,0.f,0.f,0.f);
            if(r<rowsEff) v=*(const float4*)(src+(size_t)(row0+r)*DD+kb+c4*4);
            float* dst=As+r*66+c4*4;
            *(float2*)dst=make_float2(v.x,v.y);
            *(float2*)(dst+2)=make_float2(v.z,v.w);
        }
        for(int i=tid;i<128*16;i+=256){
            int r=i>>4, c4=i&15;
            float4 v=*(const float4*)(W+(size_t)(p0+r)*256+kc*64+c4*4);
            float* dst=Ws+r*66+c4*4;
            *(float2*)dst=make_float2(v.x,v.y);
            *(float2*)(dst+2)=make_float2(v.z,v.w);
        }
        __syncthreads();
        const float* Ab=As+g*66;
        const float* Wb=Ws+cp*66;
        #pragma unroll 4
        for(int d2=0;d2<32;d2++){
            int off=2*d2;
            ull w0=*(const ull*)(Wb+0*66+off);
            ull w1=*(const ull*)(Wb+1*66+off);
            ull w2=*(const ull*)(Wb+2*66+off);
            ull w3=*(const ull*)(Wb+3*66+off);
            #pragma unroll
            for(int i=0;i<4;i++){
                ull x=*(const ull*)(Ab+i*8*66+off);
                acc[i][0]=ffma2(x,w0,acc[i][0]);
                acc[i][1]=ffma2(x,w1,acc[i][1]);
                acc[i][2]=ffma2(x,w2,acc[i][2]);
                acc[i][3]=ffma2(x,w3,acc[i][3]);
            }
        }
        __syncthreads();
    }
    int d=(p0+cp)>>2;
    float b0=bias[p0+cp],b1=bias[p0+cp+1],b2=bias[p0+cp+2],b3=bias[p0+cp+3];
    #pragma unroll
    for(int i=0;i<4;i++){
        int r=g+8*i;
        if(r<rowsEff){
            int row=row0+r;
            float q0=upsum(acc[i][0])+b0;
            float q1=upsum(acc[i][1])+b1;
            float q2=upsum(acc[i][2])+b2;
            float q3=upsum(acc[i][3])+b3;
            float rg=fsig(q0), zg=fsig(q1);
            float nn=ftanh(q2+rg*q3);
            float hold=H0[(size_t)row*DD+d];
            H1[(size_t)row*DD+d]=(1.f-zg)*nn+zg*hold;
        }
    }
}

// Head GEMM + fused sampling + KLD. Block tile 32x64, 128 thr, thread 4x4.
// grid (65,4) = 260 blocks.
__global__ __launch_bounds__(128) void k_head(int pp,const float* ept,const float* ebt){
    extern __shared__ float sm[];
    float* As=sm;            // [32][66]
    float* Ws=sm+32*66;      // [64][66]
    __shared__ double r1[128],r2[128];
    int mT=blockIdx.x, pT=blockIdx.y, tid=threadIdx.x;
    int beta=(mT==64);
    int row0=beta?2048:mT*32, rowsEff=beta?16:32, p0=pT*64;
    const float* W   = beta? g_W2c : g_W2n;
    const float* bias= beta? g_b2c : g_b2n;
    const float* H1=g_h[1-pp];
    const float* Sp=g_s[pp];
    float* Sn=g_s[1-pp];
    int g=tid&7, cp=(tid>>3)*4;
    ull acc[4][4];
    #pragma unroll
    for(int i=0;i<4;i++)
        #pragma unroll
        for(int j=0;j<4;j++) acc[i][j]=0ull;
    for(int kc=0;kc<2;kc++){
        int kb=kc*64;
        for(int i=tid;i<32*16;i+=128){
            int r=i>>4, c4=i&15;
            float4 v=make_float4(0.f,0.f,0.f,0.f);
            if(r<rowsEff) v=*(const float4*)(H1+(size_t)(row0+r)*DD+kb+c4*4);
            float* dst=As+r*66+c4*4;
            *(float2*)dst=make_float2(v.x,v.y);
            *(float2*)(dst+2)=make_float2(v.z,v.w);
        }
        for(int i=tid;i<64*16;i+=128){
            int r=i>>4, c4=i&15;
            float4 v=*(const float4*)(W+(size_t)(p0+r)*DD+kb+c4*4);
            float* dst=Ws+r*66+c4*4;
            *(float2*)dst=make_float2(v.x,v.y);
            *(float2*)(dst+2)=make_float2(v.z,v.w);
        }
        __syncthreads();
        const float* Ab=As+g*66;
        const float* Wb=Ws+cp*66;
        #pragma unroll 4
        for(int d2=0;d2<32;d2++){
            int off=2*d2;
            ull w0=*(const ull*)(Wb+0*66+off);
            ull w1=*(const ull*)(Wb+1*66+off);
            ull w2=*(const ull*)(Wb+2*66+off);
            ull w3=*(const ull*)(Wb+3*66+off);
            #pragma unroll
            for(int i=0;i<4;i++){
                ull x=*(const ull*)(Ab+i*8*66+off);
                acc[i][0]=ffma2(x,w0,acc[i][0]);
                acc[i][1]=ffma2(x,w1,acc[i][1]);
                acc[i][2]=ffma2(x,w2,acc[i][2]);
                acc[i][3]=ffma2(x,w3,acc[i][3]);
            }
        }
        __syncthreads();
    }
    int d0=(p0+cp)>>1;        // cols = mean_d0,std_d0,mean_{d0+1},std_{d0+1}
    float b0=bias[p0+cp],b1=bias[p0+cp+1],b2=bias[p0+cp+2],b3=bias[p0+cp+3];
    double kp=0.0,kb2=0.0;
    #pragma unroll
    for(int i=0;i<4;i++){
        int r=g+8*i;
        if(r<rowsEff){
            int row=row0+r;
            float m0=upsum(acc[i][0])+b0;
            float s0=fsoftplus(upsum(acc[i][1])+b1);
            float m1=upsum(acc[i][2])+b2;
            float s1=fsoftplus(upsum(acc[i][3])+b3);
            float p0v=Sp[(size_t)row*DD+d0], p1v=Sp[(size_t)row*DD+d0+1];
            float e0,e1;
            if(row<NN){ e0=ept[(size_t)row*DD+d0]; e1=ept[(size_t)row*DD+d0+1]; }
            else      { e0=ebt[(size_t)(row-NN)*DD+d0]; e1=ebt[(size_t)(row-NN)*DD+d0+1]; }
            Sn[(size_t)row*DD+d0]  =m0+s0*e0;
            Sn[(size_t)row*DD+d0+1]=m1+s1*e1;
            float dm0=m0-p0v, dm1=m1-p1v;
            if(row<NN){
                kp+=0.5*(-2.0*(double)logf(s0)+(double)s0*s0+(double)dm0*dm0-1.0);
                kp+=0.5*(-2.0*(double)logf(s1)+(double)s1*s1+(double)dm1*dm1-1.0);
            } else {
                kb2+=0.5*(2.0*(-2.302585092994046-(double)logf(s0))
                         +((double)s0*s0+(double)dm0*dm0)*100.0-1.0);
                kb2+=0.5*(2.0*(-2.302585092994046-(double)logf(s1))
                         +((double)s1*s1+(double)dm1*dm1)*100.0-1.0);
            }
        }
    }
    r1[tid]=kp; r2[tid]=kb2;
    __syncthreads();
    for(int o=64;o;o>>=1){ if(tid<o){ r1[tid]+=r1[tid+o]; r2[tid]+=r2[tid+o]; } __syncthreads(); }
    if(tid==0){ if(r1[0]!=0.0) atomicAdd(&g_acc[3],r1[0]);
                if(r2[0]!=0.0) atomicAdd(&g_acc[2],r2[0]); }
}

// Merged: blocks 0..7 = matM (M + Mmax), blocks 8..71 = per-edge logits/z/KL.
__global__ void k_mlog(int pp,const float* Wdec,const int* edt,const float* ut,const float* Wpi){
    int b=blockIdx.x, t=threadIdx.x, po=1-pp;
    if(b<8){
        __shared__ float bs[KK*DD];
        __shared__ float wm[8];
        if(b==0 && t<128) g_scnt[t]=0;
        for(int i=t;i<KK*DD;i+=256) bs[i]=g_s[po][NN*DD+i];
        __syncthreads();
        int n=b*256+t;
        float acc[KK];
        #pragma unroll
        for(int k=0;k<KK;k++) acc[k]=0.f;
        const float4* w4=(const float4*)(Wdec+(size_t)n*DD);
        for(int q=0;q<32;q++){ float4 w=w4[q];
            #pragma unroll
            for(int k=0;k<KK;k++){ float4 bb=((const float4*)(bs+k*DD))[q];
                acc[k]+=w.x*bb.x+w.y*bb.y+w.z*bb.z+w.w*bb.w; } }
        float mx=acc[0];
        #pragma unroll
        for(int k=0;k<KK;k++){ g_M[n*KK+k]=acc[k]; mx=fmaxf(mx,acc[k]); }
        for(int o=16;o;o>>=1) mx=fmaxf(mx,__shfl_xor_sync(0xffffffffu,mx,o));
        if((t&31)==0) wm[t>>5]=mx;
        __syncthreads();
        if(t==0){ float bb=wm[0];
            #pragma unroll
            for(int j=1;j<8;j++) bb=fmaxf(bb,wm[j]);
            atomicMaxF(&g_Mmax,bb); }
        return;
    }
    __shared__ float Pt[DD*KK];   // [d][k]
    __shared__ float Bt[DD*KK];
    __shared__ double rd[256];
    for(int i=t;i<DD*KK;i+=256){ int d=i>>4,k=i&15;
        Pt[i]=Wpi[k*DD+d]; Bt[i]=g_s[po][NN*DD+k*DD+d]; }
    __syncthreads();
    int e=(b-8)*256+t, w,c;
    if(e<EE){ w=edt[2*e]; c=edt[2*e+1]; } else { int e2=e-EE; w=edt[2*e2+1]; c=edt[2*e2]; }
    const float4* pw4=(const float4*)(g_s[po]+(size_t)w*DD);
    const float4* pc4=(const float4*)(g_s[po]+(size_t)c*DD);
    float lq[KK],lp[KK];
    #pragma unroll
    for(int k=0;k<KK;k++){ lq[k]=0.f; lp[k]=0.f; }
    for(int q=0;q<32;q++){
        float4 a=pw4[q], bb=pc4[q];
        float aw[4]={a.x,a.y,a.z,a.w};
        float pr[4]={a.x*bb.x,a.y*bb.y,a.z*bb.z,a.w*bb.w};
        #pragma unroll
        for(int j=0;j<4;j++){ int d=q*4+j;
            const float4* P4=(const float4*)(Pt+d*KK);
            const float4* B4=(const float4*)(Bt+d*KK);
            #pragma unroll
            for(int h=0;h<4;h++){
                float4 P=P4[h], B=B4[h];
                lq[4*h+0]+=pr[j]*P.x; lq[4*h+1]+=pr[j]*P.y;
                lq[4*h+2]+=pr[j]*P.z; lq[4*h+3]+=pr[j]*P.w;
                lp[4*h+0]+=aw[j]*B.x; lp[4*h+1]+=aw[j]*B.y;
                lp[4*h+2]+=aw[j]*B.z; lp[4*h+3]+=aw[j]*B.w;
            }
        }
    }
    float mq=-3e38f,mp=-3e38f;
    #pragma unroll
    for(int k=0;k<KK;k++){ mq=fmaxf(mq,lq[k]); mp=fmaxf(mp,lp[k]); }
    float sq=0,sp=0;
    #pragma unroll
    for(int k=0;k<KK;k++){ sq+=__expf(lq[k]-mq); sp+=__expf(lp[k]-mp); }
    float lsq=__logf(sq), lsp=__logf(sp), kz=0.f;
    #pragma unroll
    for(int k=0;k<KK;k++){ float lpo=lq[k]-mq-lsq;
        kz+=__expf(lpo)*(lpo-(lp[k]-mp-lsp)); }
    const float4* u4=(const float4*)(ut+(size_t)e*KK);
    float ze[KK];
    #pragma unroll
    for(int q=0;q<4;q++){ float4 u=u4[q]; float uu[4]={u.x,u.y,u.z,u.w};
        #pragma unroll
        for(int j=0;j<4;j++)
            ze[q*4+j]=lq[q*4+j]-__logf(-__logf(uu[j]+1e-10f)+1e-10f); }
    float mz=-3e38f;
    #pragma unroll
    for(int k=0;k<KK;k++) mz=fmaxf(mz,ze[k]);
    float sz=0;
    #pragma unroll
    for(int k=0;k<KK;k++){ ze[k]=__expf(ze[k]-mz); sz+=ze[k]; }
    float inv=1.f/sz;
    float4* zo=(float4*)(g_Z+(size_t)e*KK);
    #pragma unroll
    for(int q=0;q<4;q++){
        float4 v; v.x=ze[q*4]*inv; v.y=ze[q*4+1]*inv;
        v.z=ze[q*4+2]*inv; v.w=ze[q*4+3]*inv; zo[q]=v; }
    g_cE[e]=c; g_sE[e]=0.f; g_vcE[e]=0.f;
    rd[t]=(double)kz; __syncthreads();
    for(int o=128;o;o>>=1){ if(t<o) rd[t]+=rd[t+o]; __syncthreads(); }
    if(t==0) atomicAdd(&g_acc[1],rd[0]);
}

// N-scan + fused per-edge finish (last n-tile block per edge-tile does nll).
__global__ __launch_bounds__(256) void k_scan(){
    __shared__ float Ms[512*KK];
    __shared__ float Zs[128*KK];
    __shared__ float s_red[256], v_red[256];
    __shared__ double rd[256];
    __shared__ int s_old;
    int tid=threadIdx.x;
    int n0=blockIdx.y*512, e0=blockIdx.x*128;
    for(int i=tid;i<512*KK;i+=256) Ms[i]=g_M[n0*KK+i];
    for(int i=tid;i<128*KK;i+=256) Zs[i]=g_Z[(size_t)e0*KK+i];
    __syncthreads();
    int li=tid&127, sub=tid>>7;
    int e=e0+li;
    int c=g_cE[e];
    ull zp[8];
    {   const ull* z8=(const ull*)(Zs+li*KK);
        #pragma unroll
        for(int q=0;q<8;q++) zp[q]=z8[q]; }
    float Mx=g_Mmax;
    float s0=0.f,s1=0.f,vc=0.f;
    int base=n0+sub*256;
    #pragma unroll 2
    for(int j=0;j<256;j+=2){
        const ulonglong2* m0=(const ulonglong2*)(Ms+(sub*256+j)*KK);
        const ulonglong2* m1=(const ulonglong2*)(Ms+(sub*256+j+1)*KK);
        ulonglong2 A0=m0[0],A1=m0[1],A2=m0[2],A3=m0[3];
        ulonglong2 B0=m1[0],B1=m1[1],B2=m1[2],B3=m1[3];
        ull ta=ffma2(zp[0],A0.x,0ull); ull tb=ffma2(zp[1],A0.y,0ull);
        ta=ffma2(zp[2],A1.x,ta);       tb=ffma2(zp[3],A1.y,tb);
        ta=ffma2(zp[4],A2.x,ta);       tb=ffma2(zp[5],A2.y,tb);
        ta=ffma2(zp[6],A3.x,ta);       tb=ffma2(zp[7],A3.y,tb);
        ull tc=ffma2(zp[0],B0.x,0ull); ull td=ffma2(zp[1],B0.y,0ull);
        tc=ffma2(zp[2],B1.x,tc);       td=ffma2(zp[3],B1.y,td);
        tc=ffma2(zp[4],B2.x,tc);       td=ffma2(zp[5],B2.y,td);
        tc=ffma2(zp[6],B3.x,tc);       td=ffma2(zp[7],B3.y,td);
        float v0=upsum(fadd2(ta,tb));
        float v1=upsum(fadd2(tc,td));
        s0+=__expf(v0-Mx); s1+=__expf(v1-Mx);
        if(base+j==c)   vc=v0;
        if(base+j+1==c) vc=v1;
    }
    s_red[tid]=s0+s1; v_red[tid]=vc;
    __syncthreads();
    if(sub==0){
        float st=s_red[li]+s_red[li+128];
        float vt=v_red[li]+v_red[li+128];
        atomicAdd(&g_sE[e],st);
        if(c>=n0 && c<n0+512) atomicAdd(&g_vcE[e],vt);
    }
    __threadfence();
    __syncthreads();
    if(tid==0) s_old=atomicAdd(&g_scnt[blockIdx.x],1);
    __syncthreads();
    if(s_old==3){
        __threadfence();
        double nll=0.0;
        if(tid<128){
            int ee=e0+tid;
            nll=(double)(-(g_vcE[ee]-Mx-__logf(g_sE[ee])));
        }
        rd[tid]=nll; __syncthreads();
        for(int o=128;o;o>>=1){ if(tid<o) rd[tid]+=rd[tid+o]; __syncthreads(); }
        if(tid==0) atomicAdd(&g_acc[0],rd[0]);
    }
}

__global__ void k_out(float* out){
    out[0]=(float)(g_acc[0]/CNT);
    out[1]=(float)(g_acc[1]/CNT);
    out[2]=(float)(16.0*g_acc[4]/CNT);
    out[3]=(float)(g_acc[2]/CNT);
    out[4]=(float)(g_acc[3]/CNT);
}

extern "C" void kernel_launch(void* const* d_in,const int* in_sizes,int n_in,
                              void* d_out,int out_size){
    const int*   edges=(const int*)d_in[0];
    const int*   sidx =(const int*)d_in[1];
    const float* epp  =(const float*)d_in[2];
    const float* epb  =(const float*)d_in[3];
    const float* ug   =(const float*)d_in[4];
    const float* amean=(const float*)d_in[5];
    const float* astd =(const float*)d_in[6];
    const float* Ws2p =(const float*)d_in[7];  const float* bs2p=(const float*)d_in[8];
    const float* Ws2b =(const float*)d_in[9];  const float* bs2b=(const float*)d_in[10];
    const float* Wbm  =(const float*)d_in[11]; const float* bbm =(const float*)d_in[12];
    const float* Wbs  =(const float*)d_in[13]; const float* bbs =(const float*)d_in[14];
    const float* Wpm  =(const float*)d_in[15]; const float* bpm =(const float*)d_in[16];
    const float* Wps  =(const float*)d_in[17]; const float* bps =(const float*)d_in[18];
    const float* Wpi  =(const float*)d_in[19];
    const float* WihN =(const float*)d_in[20]; const float* WhhN=(const float*)d_in[21];
    const float* bihN =(const float*)d_in[22]; const float* bhhN=(const float*)d_in[23];
    const float* WihC =(const float*)d_in[24]; const float* WhhC=(const float*)d_in[25];
    const float* bihC =(const float*)d_in[26]; const float* bhhC=(const float*)d_in[27];
    const float* Wdec =(const float*)d_in[28];
    float* out=(float*)d_out;

    int smemG = (32*66+128*66)*4;     // 42240
    int smemH = (32*66+64*66)*4;      // 25344
    cudaFuncSetAttribute(k_gru, cudaFuncAttributeMaxDynamicSharedMemorySize,smemG);
    cudaFuncSetAttribute(k_head,cudaFuncAttributeMaxDynamicSharedMemorySize,smemH);

    k_init0<<<1,128>>>(sidx,amean,astd);
    k_initW<<<644,256>>>(WihN,WhhN,bihN,bhhN,WihC,WhhC,bihC,bhhC,
                         Wpm,bpm,Wps,bps,Wbm,bbm,Wbs,bbs);
    k_initS<<<1033,256>>>(Ws2p,bs2p,Ws2b,bs2b);
    for(int t=0;t<16;t++){
        int pp=t&1;
        k_gru<<<dim3(65,4),256,smemG>>>(pp);
        k_head<<<dim3(65,4),128,smemH>>>(pp, epp+(size_t)t*NN*DD, epb+(size_t)t*KK*DD);
        k_mlog<<<72,256>>>(pp, Wdec, edges+(size_t)t*EE*2,
                           ug+(size_t)t*2*EE*KK, Wpi);
        k_scan<<<dim3(128,4),256>>>();
    }
    k_out<<<1,1>>>(out);
}

// round 14
// speedup vs baseline: 3.2162x; 1.0270x over previous
#include <cuda_runtime.h>
#include <math.h>

#define NN 2048
#define DD 128
#define KK 16
#define EE 8192
#define TWOE 16384
#define ROWS 2064               // 2048 phi rows + 16 beta rows
#define CNT 262144.0
#define L2E 1.4426950408889634f
#define LN2 0.6931471805599453f

typedef unsigned long long ull;

__device__ float g_s[2][ROWS*DD];     // phi_s rows 0..2047, beta_s rows 2048..2063
__device__ float g_h[2][ROWS*DD];
__device__ float g_M[NN*KK];          // n-major, k contiguous
__device__ float g_Z[TWOE*KK];        // z * log2(e)
__device__ float g_sE[TWOE];
__device__ int   g_cE[TWOE];
__device__ int   g_scnt[128];
__device__ float g_W1n[512*256], g_W1c[512*256];   // rows interleaved 4d+{r,z,in,hn}
__device__ float g_b1n[512],     g_b1c[512];
__device__ float g_W2n[256*DD],  g_W2c[256*DD];    // rows interleaved 2d+{mean,std}
__device__ float g_b2n[256],     g_b2c[256];
__device__ float g_am[DD];
__device__ double g_acc[5];           // nll, kldz, kldb, kldp, kld_alpha
__device__ float g_Mmax;

__device__ __forceinline__ float fsig(float x){ return 1.f/(1.f+__expf(-x)); }
__device__ __forceinline__ float ftanh(float x){
    float e=__expf(fminf(fmaxf(2.f*x,-30.f),30.f)); return (e-1.f)/(e+1.f); }
__device__ __forceinline__ float fsoftplus(float x){
    return fmaxf(x,0.f)+log1pf(__expf(-fabsf(x))); }
__device__ __forceinline__ void atomicMaxF(float* a, float v){
    int cur=__float_as_int(*a);
    while(__int_as_float(cur)<v){ int as=cur;
        cur=atomicCAS((int*)a,as,__float_as_int(v));
        if(cur==as) break; }
}
__device__ __forceinline__ ull ffma2(ull a, ull b, ull c){
    asm("fma.rn.f32x2 %0,%1,%2,%3;":"=l"(c):"l"(a),"l"(b),"l"(c));
    return c;
}
__device__ __forceinline__ ull fadd2(ull a, ull b){
    ull r; asm("add.rn.f32x2 %0,%1,%2;":"=l"(r):"l"(a),"l"(b));
    return r;
}
__device__ __forceinline__ float upsum(ull v){
    float lo,hi; asm("mov.b64 {%0,%1},%2;":"=f"(lo),"=f"(hi):"l"(v));
    return lo+hi;
}
__device__ __forceinline__ ull pack2(float lo,float hi){
    ull r; asm("mov.b64 %0,{%1,%2};":"=l"(r):"f"(lo),"f"(hi));
    return r;
}
__device__ __forceinline__ float fex2(float x){
    float r; asm("ex2.approx.f32 %0,%1;":"=f"(r):"f"(x));
    return r;
}

__global__ void k_init0(const int* sidx,const float* am,const float* as){
    int t=threadIdx.x; int s=sidx[0];
    __shared__ float red[128];
    float m=am[(size_t)s*DD+t];
    float sd=fsoftplus(as[(size_t)s*DD+t]);
    g_am[t]=m;
    red[t]=0.5f*(-2.f*logf(sd)+sd*sd+m*m-1.f);
    __syncthreads();
    for(int o=64;o;o>>=1){ if(t<o) red[t]+=red[t+o]; __syncthreads(); }
    if(t==0){ g_acc[4]=(double)red[0]; g_acc[0]=g_acc[1]=g_acc[2]=g_acc[3]=0.0; }
}

__global__ void k_initW(const float* WihN,const float* WhhN,const float* bihN,const float* bhhN,
                        const float* WihC,const float* WhhC,const float* bihC,const float* bhhC,
                        const float* Wpm,const float* bpm,const float* Wps,const float* bps,
                        const float* Wbm,const float* bbm,const float* Wbs,const float* bbs){
    int i=blockIdx.x*256+threadIdx.x;
    if(i<131072){                                  // W1: row j'=4d+gate, 512 x 256
        int j=i>>8, c=i&255;
        int d=j>>2, gate=j&3;
        float vn,vc;
        if(gate==0||gate==1){
            int jr=gate*128+d;
            if(c<128){ vn=WihN[jr*256+c]+WihN[jr*256+128+c];
                       vc=WihC[jr*256+c]+WihC[jr*256+128+c]; }
            else     { vn=WhhN[jr*128+c-128]; vc=WhhC[jr*128+c-128]; }
        } else if(gate==2){
            int jr=256+d;
            if(c<128){ vn=WihN[jr*256+c]+WihN[jr*256+128+c];
                       vc=WihC[jr*256+c]+WihC[jr*256+128+c]; }
            else     { vn=0.f; vc=0.f; }
        } else {
            int jr=256+d;
            if(c<128){ vn=0.f; vc=0.f; }
            else     { vn=WhhN[jr*128+c-128]; vc=WhhC[jr*128+c-128]; }
        }
        g_W1n[i]=vn; g_W1c[i]=vc;
    } else if(i<163840){                           // W2: row j'=2d+m, 256 x 128
        int o=i-131072, j=o>>7, c=o&127;
        int d=j>>1, m=j&1;
        g_W2n[o] = m==0 ? Wpm[d*128+c] : Wps[d*128+c];
        g_W2c[o] = m==0 ? Wbm[d*128+c] : Wbs[d*128+c];
    } else if(i<164352){                           // b1
        int j=i-163840; int d=j>>2, gate=j&3; float bn,bc;
        if(gate==0||gate==1){ int jr=gate*128+d;
            bn=bihN[jr]+bhhN[jr]; bc=bihC[jr]+bhhC[jr]; }
        else if(gate==2){ bn=bihN[256+d]; bc=bihC[256+d]; }
        else            { bn=bhhN[256+d]; bc=bhhC[256+d]; }
        g_b1n[j]=bn; g_b1c[j]=bc;
    } else if(i<164608){                           // b2
        int j=i-164352; int d=j>>1, m=j&1;
        g_b2n[j] = m==0 ? bpm[d] : bps[d];
        g_b2c[j] = m==0 ? bbm[d] : bbs[d];
    }
}

__global__ void k_initS(const float* Wp,const float* bp,const float* Wb,const float* bb){
    __shared__ float am[DD];
    int tid=threadIdx.x;
    if(tid<DD) am[tid]=g_am[tid];
    __syncthreads();
    int i=blockIdx.x*256+tid; if(i>=ROWS*DD) return;
    const float* wr; float bias;
    if(i<NN*DD){ wr=Wp+(size_t)i*DD; bias=bp[i]; }
    else { int o=i-NN*DD; wr=Wb+(size_t)o*DD; bias=bb[o]; }
    const float4* w4=(const float4*)wr; const float4* a4=(const float4*)am;
    float acc=bias;
    #pragma unroll 8
    for(int q=0;q<32;q++){ float4 w=w4[q],a=a4[q];
        acc+=w.x*a.x+w.y*a.y+w.z*a.z+w.w*a.w; }
    g_s[0][i]=acc; g_h[0][i]=0.f;
}

// GRU GEMM + fused activation. Block tile 32x128, 256 thr, thread tile 4x4.
__global__ __launch_bounds__(256) void k_gru(int pp){
    extern __shared__ float sm[];
    float* As=sm;            // [32][66]
    float* Ws=sm+32*66;      // [128][66]
    int mT=blockIdx.x, pT=blockIdx.y, tid=threadIdx.x;
    if(mT==0&&pT==0&&tid==0) g_Mmax=-1e30f;
    int beta=(mT==64);
    int row0=beta?2048:mT*32, rowsEff=beta?16:32, p0=pT*128;
    const float* W   = beta? g_W1c : g_W1n;
    const float* bias= beta? g_b1c : g_b1n;
    const float* S0=g_s[pp]; const float* H0=g_h[pp];
    float* H1=g_h[1-pp];
    int g=tid&7, cp=(tid>>3)*4;
    ull acc[4][4];
    #pragma unroll
    for(int i=0;i<4;i++)
        #pragma unroll
        for(int j=0;j<4;j++) acc[i][j]=0ull;
    for(int kc=0;kc<4;kc++){
        const float* src = kc<2 ? S0 : H0;
        int kb=(kc&1)*64;
        for(int i=tid;i<32*16;i+=256){
            int r=i>>4, c4=i&15;
            float4 v=make_float4(0.f,0.f,0.f,0.f);
            if(r<rowsEff) v=*(const float4*)(src+(size_t)(row0+r)*DD+kb+c4*4);
            float* dst=As+r*66+c4*4;
            *(float2*)dst=make_float2(v.x,v.y);
            *(float2*)(dst+2)=make_float2(v.z,v.w);
        }
        for(int i=tid;i<128*16;i+=256){
            int r=i>>4, c4=i&15;
            float4 v=*(const float4*)(W+(size_t)(p0+r)*256+kc*64+c4*4);
            float* dst=Ws+r*66+c4*4;
            *(float2*)dst=make_float2(v.x,v.y);
            *(float2*)(dst+2)=make_float2(v.z,v.w);
        }
        __syncthreads();
        const float* Ab=As+g*66;
        const float* Wb=Ws+cp*66;
        #pragma unroll 4
        for(int d2=0;d2<32;d2++){
            int off=2*d2;
            ull w0=*(const ull*)(Wb+0*66+off);
            ull w1=*(const ull*)(Wb+1*66+off);
            ull w2=*(const ull*)(Wb+2*66+off);
            ull w3=*(const ull*)(Wb+3*66+off);
            #pragma unroll
            for(int i=0;i<4;i++){
                ull x=*(const ull*)(Ab+i*8*66+off);
                acc[i][0]=ffma2(x,w0,acc[i][0]);
                acc[i][1]=ffma2(x,w1,acc[i][1]);
                acc[i][2]=ffma2(x,w2,acc[i][2]);
                acc[i][3]=ffma2(x,w3,acc[i][3]);
            }
        }
        __syncthreads();
    }
    int d=(p0+cp)>>2;
    float b0=bias[p0+cp],b1=bias[p0+cp+1],b2=bias[p0+cp+2],b3=bias[p0+cp+3];
    #pragma unroll
    for(int i=0;i<4;i++){
        int r=g+8*i;
        if(r<rowsEff){
            int row=row0+r;
            float q0=upsum(acc[i][0])+b0;
            float q1=upsum(acc[i][1])+b1;
            float q2=upsum(acc[i][2])+b2;
            float q3=upsum(acc[i][3])+b3;
            float rg=fsig(q0), zg=fsig(q1);
            float nn=ftanh(q2+rg*q3);
            float hold=H0[(size_t)row*DD+d];
            H1[(size_t)row*DD+d]=(1.f-zg)*nn+zg*hold;
        }
    }
}

// Head GEMM + fused sampling + KLD. Block tile 32x64, 128 thr, thread 4x4.
__global__ __launch_bounds__(128) void k_head(int pp,const float* ept,const float* ebt){
    extern __shared__ float sm[];
    float* As=sm;            // [32][66]
    float* Ws=sm+32*66;      // [64][66]
    __shared__ double r1[128],r2[128];
    int mT=blockIdx.x, pT=blockIdx.y, tid=threadIdx.x;
    int beta=(mT==64);
    int row0=beta?2048:mT*32, rowsEff=beta?16:32, p0=pT*64;
    const float* W   = beta? g_W2c : g_W2n;
    const float* bias= beta? g_b2c : g_b2n;
    const float* H1=g_h[1-pp];
    const float* Sp=g_s[pp];
    float* Sn=g_s[1-pp];
    int g=tid&7, cp=(tid>>3)*4;
    ull acc[4][4];
    #pragma unroll
    for(int i=0;i<4;i++)
        #pragma unroll
        for(int j=0;j<4;j++) acc[i][j]=0ull;
    for(int kc=0;kc<2;kc++){
        int kb=kc*64;
        for(int i=tid;i<32*16;i+=128){
            int r=i>>4, c4=i&15;
            float4 v=make_float4(0.f,0.f,0.f,0.f);
            if(r<rowsEff) v=*(const float4*)(H1+(size_t)(row0+r)*DD+kb+c4*4);
            float* dst=As+r*66+c4*4;
            *(float2*)dst=make_float2(v.x,v.y);
            *(float2*)(dst+2)=make_float2(v.z,v.w);
        }
        for(int i=tid;i<64*16;i+=128){
            int r=i>>4, c4=i&15;
            float4 v=*(const float4*)(W+(size_t)(p0+r)*DD+kb+c4*4);
            float* dst=Ws+r*66+c4*4;
            *(float2*)dst=make_float2(v.x,v.y);
            *(float2*)(dst+2)=make_float2(v.z,v.w);
        }
        __syncthreads();
        const float* Ab=As+g*66;
        const float* Wb=Ws+cp*66;
        #pragma unroll 4
        for(int d2=0;d2<32;d2++){
            int off=2*d2;
            ull w0=*(const ull*)(Wb+0*66+off);
            ull w1=*(const ull*)(Wb+1*66+off);
            ull w2=*(const ull*)(Wb+2*66+off);
            ull w3=*(const ull*)(Wb+3*66+off);
            #pragma unroll
            for(int i=0;i<4;i++){
                ull x=*(const ull*)(Ab+i*8*66+off);
                acc[i][0]=ffma2(x,w0,acc[i][0]);
                acc[i][1]=ffma2(x,w1,acc[i][1]);
                acc[i][2]=ffma2(x,w2,acc[i][2]);
                acc[i][3]=ffma2(x,w3,acc[i][3]);
            }
        }
        __syncthreads();
    }
    int d0=(p0+cp)>>1;        // cols = mean_d0,std_d0,mean_{d0+1},std_{d0+1}
    float b0=bias[p0+cp],b1=bias[p0+cp+1],b2=bias[p0+cp+2],b3=bias[p0+cp+3];
    double kp=0.0,kb2=0.0;
    #pragma unroll
    for(int i=0;i<4;i++){
        int r=g+8*i;
        if(r<rowsEff){
            int row=row0+r;
            float m0=upsum(acc[i][0])+b0;
            float s0=fsoftplus(upsum(acc[i][1])+b1);
            float m1=upsum(acc[i][2])+b2;
            float s1=fsoftplus(upsum(acc[i][3])+b3);
            float p0v=Sp[(size_t)row*DD+d0], p1v=Sp[(size_t)row*DD+d0+1];
            float e0,e1;
            if(row<NN){ e0=ept[(size_t)row*DD+d0]; e1=ept[(size_t)row*DD+d0+1]; }
            else      { e0=ebt[(size_t)(row-NN)*DD+d0]; e1=ebt[(size_t)(row-NN)*DD+d0+1]; }
            Sn[(size_t)row*DD+d0]  =m0+s0*e0;
            Sn[(size_t)row*DD+d0+1]=m1+s1*e1;
            float dm0=m0-p0v, dm1=m1-p1v;
            if(row<NN){
                kp+=0.5*(-2.0*(double)logf(s0)+(double)s0*s0+(double)dm0*dm0-1.0);
                kp+=0.5*(-2.0*(double)logf(s1)+(double)s1*s1+(double)dm1*dm1-1.0);
            } else {
                kb2+=0.5*(2.0*(-2.302585092994046-(double)logf(s0))
                         +((double)s0*s0+(double)dm0*dm0)*100.0-1.0);
                kb2+=0.5*(2.0*(-2.302585092994046-(double)logf(s1))
                         +((double)s1*s1+(double)dm1*dm1)*100.0-1.0);
            }
        }
    }
    r1[tid]=kp; r2[tid]=kb2;
    __syncthreads();
    for(int o=64;o;o>>=1){ if(tid<o){ r1[tid]+=r1[tid+o]; r2[tid]+=r2[tid+o]; } __syncthreads(); }
    if(tid==0){ if(r1[0]!=0.0) atomicAdd(&g_acc[3],r1[0]);
                if(r2[0]!=0.0) atomicAdd(&g_acc[2],r2[0]); }
}

// Merged: blocks 0..7 = matM (M + Mmax), blocks 8..71 = per-edge logits/z/KL.
__global__ void k_mlog(int pp,const float* Wdec,const int* edt,const float* ut,const float* Wpi){
    int b=blockIdx.x, t=threadIdx.x, po=1-pp;
    if(b<8){
        __shared__ float bs[KK*DD];
        __shared__ float wm[8];
        if(b==0 && t<128) g_scnt[t]=0;
        for(int i=t;i<KK*DD;i+=256) bs[i]=g_s[po][NN*DD+i];
        __syncthreads();
        int n=b*256+t;
        float acc[KK];
        #pragma unroll
        for(int k=0;k<KK;k++) acc[k]=0.f;
        const float4* w4=(const float4*)(Wdec+(size_t)n*DD);
        for(int q=0;q<32;q++){ float4 w=w4[q];
            #pragma unroll
            for(int k=0;k<KK;k++){ float4 bb=((const float4*)(bs+k*DD))[q];
                acc[k]+=w.x*bb.x+w.y*bb.y+w.z*bb.z+w.w*bb.w; } }
        float mx=acc[0];
        #pragma unroll
        for(int k=0;k<KK;k++){ g_M[n*KK+k]=acc[k]; mx=fmaxf(mx,acc[k]); }
        for(int o=16;o;o>>=1) mx=fmaxf(mx,__shfl_xor_sync(0xffffffffu,mx,o));
        if((t&31)==0) wm[t>>5]=mx;
        __syncthreads();
        if(t==0){ float bb=wm[0];
            #pragma unroll
            for(int j=1;j<8;j++) bb=fmaxf(bb,wm[j]);
            atomicMaxF(&g_Mmax,bb); }
        return;
    }
    __shared__ float Pt[DD*KK];   // [d][k]
    __shared__ float Bt[DD*KK];
    __shared__ double rd[256];
    for(int i=t;i<DD*KK;i+=256){ int d=i>>4,k=i&15;
        Pt[i]=Wpi[k*DD+d]; Bt[i]=g_s[po][NN*DD+k*DD+d]; }
    __syncthreads();
    int e=(b-8)*256+t, w,c;
    if(e<EE){ w=edt[2*e]; c=edt[2*e+1]; } else { int e2=e-EE; w=edt[2*e2+1]; c=edt[2*e2]; }
    const float4* pw4=(const float4*)(g_s[po]+(size_t)w*DD);
    const float4* pc4=(const float4*)(g_s[po]+(size_t)c*DD);
    float lq[KK],lp[KK];
    #pragma unroll
    for(int k=0;k<KK;k++){ lq[k]=0.f; lp[k]=0.f; }
    for(int q=0;q<32;q++){
        float4 a=pw4[q], bb=pc4[q];
        float aw[4]={a.x,a.y,a.z,a.w};
        float pr[4]={a.x*bb.x,a.y*bb.y,a.z*bb.z,a.w*bb.w};
        #pragma unroll
        for(int j=0;j<4;j++){ int d=q*4+j;
            const float4* P4=(const float4*)(Pt+d*KK);
            const float4* B4=(const float4*)(Bt+d*KK);
            #pragma unroll
            for(int h=0;h<4;h++){
                float4 P=P4[h], B=B4[h];
                lq[4*h+0]+=pr[j]*P.x; lq[4*h+1]+=pr[j]*P.y;
                lq[4*h+2]+=pr[j]*P.z; lq[4*h+3]+=pr[j]*P.w;
                lp[4*h+0]+=aw[j]*B.x; lp[4*h+1]+=aw[j]*B.y;
                lp[4*h+2]+=aw[j]*B.z; lp[4*h+3]+=aw[j]*B.w;
            }
        }
    }
    float mq=-3e38f,mp=-3e38f;
    #pragma unroll
    for(int k=0;k<KK;k++){ mq=fmaxf(mq,lq[k]); mp=fmaxf(mp,lp[k]); }
    float sq=0,sp=0;
    #pragma unroll
    for(int k=0;k<KK;k++){ sq+=__expf(lq[k]-mq); sp+=__expf(lp[k]-mp); }
    float lsq=__logf(sq), lsp=__logf(sp), kz=0.f;
    #pragma unroll
    for(int k=0;k<KK;k++){ float lpo=lq[k]-mq-lsq;
        kz+=__expf(lpo)*(lpo-(lp[k]-mp-lsp)); }
    const float4* u4=(const float4*)(ut+(size_t)e*KK);
    float ze[KK];
    #pragma unroll
    for(int q=0;q<4;q++){ float4 u=u4[q]; float uu[4]={u.x,u.y,u.z,u.w};
        #pragma unroll
        for(int j=0;j<4;j++)
            ze[q*4+j]=lq[q*4+j]-__logf(-__logf(uu[j]+1e-10f)+1e-10f); }
    float mz=-3e38f;
    #pragma unroll
    for(int k=0;k<KK;k++) mz=fmaxf(mz,ze[k]);
    float sz=0;
    #pragma unroll
    for(int k=0;k<KK;k++){ ze[k]=__expf(ze[k]-mz); sz+=ze[k]; }
    float inv=L2E/sz;                 // z scaled by log2(e)
    float4* zo=(float4*)(g_Z+(size_t)e*KK);
    #pragma unroll
    for(int q=0;q<4;q++){
        float4 v; v.x=ze[q*4]*inv; v.y=ze[q*4+1]*inv;
        v.z=ze[q*4+2]*inv; v.w=ze[q*4+3]*inv; zo[q]=v; }
    g_cE[e]=c; g_sE[e]=0.f;
    rd[t]=(double)kz; __syncthreads();
    for(int o=128;o;o>>=1){ if(t<o) rd[t]+=rd[t+o]; __syncthreads(); }
    if(t==0) atomicAdd(&g_acc[1],rd[0]);
}

// N-scan (log2 domain, Mx folded into accumulator seed) + fused finish.
__global__ __launch_bounds__(256) void k_scan(){
    __shared__ float Ms[512*KK];
    __shared__ float Zs[128*KK];
    __shared__ float s_red[256];
    __shared__ double rd[256];
    __shared__ int s_old;
    int tid=threadIdx.x;
    int n0=blockIdx.y*512, e0=blockIdx.x*128;
    for(int i=tid;i<512*KK;i+=256) Ms[i]=g_M[n0*KK+i];
    for(int i=tid;i<128*KK;i+=256) Zs[i]=g_Z[(size_t)e0*KK+i];
    __syncthreads();
    int li=tid&127, sub=tid>>7;
    int e=e0+li;
    ull zp[8];
    {   const ull* z8=(const ull*)(Zs+li*KK);
        #pragma unroll
        for(int q=0;q<8;q++) zp[q]=z8[q]; }
    float Mx2=g_Mmax*L2E;
    ull seed=pack2(-Mx2,0.f);
    float s0=0.f,s1=0.f;
    #pragma unroll 4
    for(int j=0;j<256;j+=2){
        const ulonglong2* m0=(const ulonglong2*)(Ms+(sub*256+j)*KK);
        const ulonglong2* m1=(const ulonglong2*)(Ms+(sub*256+j+1)*KK);
        ulonglong2 A0=m0[0],A1=m0[1],A2=m0[2],A3=m0[3];
        ulonglong2 B0=m1[0],B1=m1[1],B2=m1[2],B3=m1[3];
        ull ta=ffma2(zp[0],A0.x,seed); ull tb=ffma2(zp[1],A0.y,0ull);
        ta=ffma2(zp[2],A1.x,ta);       tb=ffma2(zp[3],A1.y,tb);
        ta=ffma2(zp[4],A2.x,ta);       tb=ffma2(zp[5],A2.y,tb);
        ta=ffma2(zp[6],A3.x,ta);       tb=ffma2(zp[7],A3.y,tb);
        ull tc=ffma2(zp[0],B0.x,seed); ull td=ffma2(zp[1],B0.y,0ull);
        tc=ffma2(zp[2],B1.x,tc);       td=ffma2(zp[3],B1.y,td);
        tc=ffma2(zp[4],B2.x,tc);       td=ffma2(zp[5],B2.y,td);
        tc=ffma2(zp[6],B3.x,tc);       td=ffma2(zp[7],B3.y,td);
        s0+=fex2(upsum(fadd2(ta,tb)));
        s1+=fex2(upsum(fadd2(tc,td)));
    }
    s_red[tid]=s0+s1;
    __syncthreads();
    if(sub==0) atomicAdd(&g_sE[e], s_red[li]+s_red[li+128]);
    __threadfence();
    __syncthreads();
    if(tid==0) s_old=atomicAdd(&g_scnt[blockIdx.x],1);
    __syncthreads();
    if(s_old==3){
        __threadfence();
        double nll=0.0;
        if(tid<128){
            int ee=e0+tid;
            int c=g_cE[ee];
            const float4* mc=(const float4*)(g_M+(size_t)c*KK);
            const float4* zz=(const float4*)(Zs+tid*KK);
            float vc2=0.f;
            #pragma unroll
            for(int q=0;q<4;q++){ float4 z=zz[q], m=mc[q];
                vc2+=z.x*m.x+z.y*m.y+z.z*m.z+z.w*m.w; }
            float vc=vc2*LN2;                       // undo log2e scaling
            nll=(double)(-(vc-g_Mmax-__logf(g_sE[ee])));
        }
        rd[tid]=nll; __syncthreads();
        for(int o=128;o;o>>=1){ if(tid<o) rd[tid]+=rd[tid+o]; __syncthreads(); }
        if(tid==0) atomicAdd(&g_acc[0],rd[0]);
    }
}

__global__ void k_out(float* out){
    out[0]=(float)(g_acc[0]/CNT);
    out[1]=(float)(g_acc[1]/CNT);
    out[2]=(float)(16.0*g_acc[4]/CNT);
    out[3]=(float)(g_acc[2]/CNT);
    out[4]=(float)(g_acc[3]/CNT);
}

extern "C" void kernel_launch(void* const* d_in,const int* in_sizes,int n_in,
                              void* d_out,int out_size){
    const int*   edges=(const int*)d_in[0];
    const int*   sidx =(const int*)d_in[1];
    const float* epp  =(const float*)d_in[2];
    const float* epb  =(const float*)d_in[3];
    const float* ug   =(const float*)d_in[4];
    const float* amean=(const float*)d_in[5];
    const float* astd =(const float*)d_in[6];
    const float* Ws2p =(const float*)d_in[7];  const float* bs2p=(const float*)d_in[8];
    const float* Ws2b =(const float*)d_in[9];  const float* bs2b=(const float*)d_in[10];
    const float* Wbm  =(const float*)d_in[11]; const float* bbm =(const float*)d_in[12];
    const float* Wbs  =(const float*)d_in[13]; const float* bbs =(const float*)d_in[14];
    const float* Wpm  =(const float*)d_in[15]; const float* bpm =(const float*)d_in[16];
    const float* Wps  =(const float*)d_in[17]; const float* bps =(const float*)d_in[18];
    const float* Wpi  =(const float*)d_in[19];
    const float* WihN =(const float*)d_in[20]; const float* WhhN=(const float*)d_in[21];
    const float* bihN =(const float*)d_in[22]; const float* bhhN=(const float*)d_in[23];
    const float* WihC =(const float*)d_in[24]; const float* WhhC=(const float*)d_in[25];
    const float* bihC =(const float*)d_in[26]; const float* bhhC=(const float*)d_in[27];
    const float* Wdec =(const float*)d_in[28];
    float* out=(float*)d_out;

    int smemG = (32*66+128*66)*4;     // 42240
    int smemH = (32*66+64*66)*4;      // 25344
    cudaFuncSetAttribute(k_gru, cudaFuncAttributeMaxDynamicSharedMemorySize,smemG);
    cudaFuncSetAttribute(k_head,cudaFuncAttributeMaxDynamicSharedMemorySize,smemH);

    k_init0<<<1,128>>>(sidx,amean,astd);
    k_initW<<<644,256>>>(WihN,WhhN,bihN,bhhN,WihC,WhhC,bihC,bhhC,
                         Wpm,bpm,Wps,bps,Wbm,bbm,Wbs,bbs);
    k_initS<<<1033,256>>>(Ws2p,bs2p,Ws2b,bs2b);
    for(int t=0;t<16;t++){
        int pp=t&1;
        k_gru<<<dim3(65,4),256,smemG>>>(pp);
        k_head<<<dim3(65,4),128,smemH>>>(pp, epp+(size_t)t*NN*DD, epb+(size_t)t*KK*DD);
        k_mlog<<<72,256>>>(pp, Wdec, edges+(size_t)t*EE*2,
                           ug+(size_t)t*2*EE*KK, Wpi);
        k_scan<<<dim3(128,4),256>>>();
    }
    k_out<<<1,1>>>(out);
}

// round 15
// speedup vs baseline: 3.2889x; 1.0226x over previous
#include <cuda_runtime.h>
#include <math.h>

#define NN 2048
#define DD 128
#define KK 16
#define EE 8192
#define TWOE 16384
#define ROWS 2064               // 2048 phi rows + 16 beta rows
#define CNT 262144.0
#define L2E 1.4426950408889634f
#define LN2 0.6931471805599453f

typedef unsigned long long ull;

__device__ float g_s[2][ROWS*DD];     // phi_s rows 0..2047, beta_s rows 2048..2063
__device__ float g_h[2][ROWS*DD];
__device__ float g_M[NN*KK];          // n-major, k contiguous
__device__ float g_Z[TWOE*KK];        // z * log2(e)
__device__ float g_sE[TWOE];
__device__ int   g_cE[TWOE];
__device__ int   g_scnt[128];
__device__ float g_W1n[512*256], g_W1c[512*256];   // rows interleaved 4d+{r,z,in,hn}
__device__ float g_b1n[512],     g_b1c[512];
__device__ float g_W2n[256*DD],  g_W2c[256*DD];    // rows interleaved 2d+{mean,std}
__device__ float g_b2n[256],     g_b2c[256];
__device__ float g_am[DD];
__device__ double g_acc[5];           // nll, kldz, kldb, kldp, kld_alpha
__device__ float g_Mmax;

__device__ __forceinline__ float fsig(float x){ return 1.f/(1.f+__expf(-x)); }
__device__ __forceinline__ float ftanh(float x){
    float e=__expf(fminf(fmaxf(2.f*x,-30.f),30.f)); return (e-1.f)/(e+1.f); }
__device__ __forceinline__ float fsoftplus(float x){
    return fmaxf(x,0.f)+log1pf(__expf(-fabsf(x))); }
__device__ __forceinline__ void atomicMaxF(float* a, float v){
    int cur=__float_as_int(*a);
    while(__int_as_float(cur)<v){ int as=cur;
        cur=atomicCAS((int*)a,as,__float_as_int(v));
        if(cur==as) break; }
}
__device__ __forceinline__ ull ffma2(ull a, ull b, ull c){
    asm("fma.rn.f32x2 %0,%1,%2,%3;":"=l"(c):"l"(a),"l"(b),"l"(c));
    return c;
}
__device__ __forceinline__ ull fadd2(ull a, ull b){
    ull r; asm("add.rn.f32x2 %0,%1,%2;":"=l"(r):"l"(a),"l"(b));
    return r;
}
__device__ __forceinline__ float upsum(ull v){
    float lo,hi; asm("mov.b64 {%0,%1},%2;":"=f"(lo),"=f"(hi):"l"(v));
    return lo+hi;
}
__device__ __forceinline__ ull pack2(float lo,float hi){
    ull r; asm("mov.b64 %0,{%1,%2};":"=l"(r):"f"(lo),"f"(hi));
    return r;
}
__device__ __forceinline__ float fex2(float x){
    float r; asm("ex2.approx.f32 %0,%1;":"=f"(r):"f"(x));
    return r;
}

__global__ void k_init0(const int* sidx,const float* am,const float* as){
    int t=threadIdx.x; int s=sidx[0];
    __shared__ float red[128];
    float m=am[(size_t)s*DD+t];
    float sd=fsoftplus(as[(size_t)s*DD+t]);
    g_am[t]=m;
    red[t]=0.5f*(-2.f*logf(sd)+sd*sd+m*m-1.f);
    __syncthreads();
    for(int o=64;o;o>>=1){ if(t<o) red[t]+=red[t+o]; __syncthreads(); }
    if(t==0){ g_acc[4]=(double)red[0]; g_acc[0]=g_acc[1]=g_acc[2]=g_acc[3]=0.0; }
}

__global__ void k_initW(const float* WihN,const float* WhhN,const float* bihN,const float* bhhN,
                        const float* WihC,const float* WhhC,const float* bihC,const float* bhhC,
                        const float* Wpm,const float* bpm,const float* Wps,const float* bps,
                        const float* Wbm,const float* bbm,const float* Wbs,const float* bbs){
    int i=blockIdx.x*256+threadIdx.x;
    if(i<131072){                                  // W1: row j'=4d+gate, 512 x 256
        int j=i>>8, c=i&255;
        int d=j>>2, gate=j&3;
        float vn,vc;
        if(gate==0||gate==1){
            int jr=gate*128+d;
            if(c<128){ vn=WihN[jr*256+c]+WihN[jr*256+128+c];
                       vc=WihC[jr*256+c]+WihC[jr*256+128+c]; }
            else     { vn=WhhN[jr*128+c-128]; vc=WhhC[jr*128+c-128]; }
        } else if(gate==2){
            int jr=256+d;
            if(c<128){ vn=WihN[jr*256+c]+WihN[jr*256+128+c];
                       vc=WihC[jr*256+c]+WihC[jr*256+128+c]; }
            else     { vn=0.f; vc=0.f; }
        } else {
            int jr=256+d;
            if(c<128){ vn=0.f; vc=0.f; }
            else     { vn=WhhN[jr*128+c-128]; vc=WhhC[jr*128+c-128]; }
        }
        g_W1n[i]=vn; g_W1c[i]=vc;
    } else if(i<163840){                           // W2: row j'=2d+m, 256 x 128
        int o=i-131072, j=o>>7, c=o&127;
        int d=j>>1, m=j&1;
        g_W2n[o] = m==0 ? Wpm[d*128+c] : Wps[d*128+c];
        g_W2c[o] = m==0 ? Wbm[d*128+c] : Wbs[d*128+c];
    } else if(i<164352){                           // b1
        int j=i-163840; int d=j>>2, gate=j&3; float bn,bc;
        if(gate==0||gate==1){ int jr=gate*128+d;
            bn=bihN[jr]+bhhN[jr]; bc=bihC[jr]+bhhC[jr]; }
        else if(gate==2){ bn=bihN[256+d]; bc=bihC[256+d]; }
        else            { bn=bhhN[256+d]; bc=bhhC[256+d]; }
        g_b1n[j]=bn; g_b1c[j]=bc;
    } else if(i<164608){                           // b2
        int j=i-164352; int d=j>>1, m=j&1;
        g_b2n[j] = m==0 ? bpm[d] : bps[d];
        g_b2c[j] = m==0 ? bbm[d] : bbs[d];
    }
}

__global__ void k_initS(const float* Wp,const float* bp,const float* Wb,const float* bb){
    __shared__ float am[DD];
    int tid=threadIdx.x;
    if(tid<DD) am[tid]=g_am[tid];
    __syncthreads();
    int i=blockIdx.x*256+tid; if(i>=ROWS*DD) return;
    const float* wr; float bias;
    if(i<NN*DD){ wr=Wp+(size_t)i*DD; bias=bp[i]; }
    else { int o=i-NN*DD; wr=Wb+(size_t)o*DD; bias=bb[o]; }
    const float4* w4=(const float4*)wr; const float4* a4=(const float4*)am;
    float acc=bias;
    #pragma unroll 8
    for(int q=0;q<32;q++){ float4 w=w4[q],a=a4[q];
        acc+=w.x*a.x+w.y*a.y+w.z*a.z+w.w*a.w; }
    g_s[0][i]=acc; g_h[0][i]=0.f;
}

// GRU GEMM + fused activation. Block tile 32x128, 256 thr, thread tile 4x4.
__global__ __launch_bounds__(256) void k_gru(int pp){
    extern __shared__ float sm[];
    float* As=sm;            // [32][66]
    float* Ws=sm+32*66;      // [128][66]
    int mT=blockIdx.x, pT=blockIdx.y, tid=threadIdx.x;
    if(mT==0&&pT==0&&tid==0) g_Mmax=-1e30f;
    int beta=(mT==64);
    int row0=beta?2048:mT*32, rowsEff=beta?16:32, p0=pT*128;
    const float* W   = beta? g_W1c : g_W1n;
    const float* bias= beta? g_b1c : g_b1n;
    const float* S0=g_s[pp]; const float* H0=g_h[pp];
    float* H1=g_h[1-pp];
    int g=tid&7, cp=(tid>>3)*4;
    ull acc[4][4];
    #pragma unroll
    for(int i=0;i<4;i++)
        #pragma unroll
        for(int j=0;j<4;j++) acc[i][j]=0ull;
    for(int kc=0;kc<4;kc++){
        const float* src = kc<2 ? S0 : H0;
        int kb=(kc&1)*64;
        for(int i=tid;i<32*16;i+=256){
            int r=i>>4, c4=i&15;
            float4 v=make_float4(0.f,0.f,0.f,0.f);
            if(r<rowsEff) v=*(const float4*)(src+(size_t)(row0+r)*DD+kb+c4*4);
            float* dst=As+r*66+c4*4;
            *(float2*)dst=make_float2(v.x,v.y);
            *(float2*)(dst+2)=make_float2(v.z,v.w);
        }
        for(int i=tid;i<128*16;i+=256){
            int r=i>>4, c4=i&15;
            float4 v=*(const float4*)(W+(size_t)(p0+r)*256+kc*64+c4*4);
            float* dst=Ws+r*66+c4*4;
            *(float2*)dst=make_float2(v.x,v.y);
            *(float2*)(dst+2)=make_float2(v.z,v.w);
        }
        __syncthreads();
        const float* Ab=As+g*66;
        const float* Wb=Ws+cp*66;
        #pragma unroll 4
        for(int d2=0;d2<32;d2++){
            int off=2*d2;
            ull w0=*(const ull*)(Wb+0*66+off);
            ull w1=*(const ull*)(Wb+1*66+off);
            ull w2=*(const ull*)(Wb+2*66+off);
            ull w3=*(const ull*)(Wb+3*66+off);
            #pragma unroll
            for(int i=0;i<4;i++){
                ull x=*(const ull*)(Ab+i*8*66+off);
                acc[i][0]=ffma2(x,w0,acc[i][0]);
                acc[i][1]=ffma2(x,w1,acc[i][1]);
                acc[i][2]=ffma2(x,w2,acc[i][2]);
                acc[i][3]=ffma2(x,w3,acc[i][3]);
            }
        }
        __syncthreads();
    }
    int d=(p0+cp)>>2;
    float b0=bias[p0+cp],b1=bias[p0+cp+1],b2=bias[p0+cp+2],b3=bias[p0+cp+3];
    #pragma unroll
    for(int i=0;i<4;i++){
        int r=g+8*i;
        if(r<rowsEff){
            int row=row0+r;
            float q0=upsum(acc[i][0])+b0;
            float q1=upsum(acc[i][1])+b1;
            float q2=upsum(acc[i][2])+b2;
            float q3=upsum(acc[i][3])+b3;
            float rg=fsig(q0), zg=fsig(q1);
            float nn=ftanh(q2+rg*q3);
            float hold=H0[(size_t)row*DD+d];
            H1[(size_t)row*DD+d]=(1.f-zg)*nn+zg*hold;
        }
    }
}

// Head GEMM + fused sampling + KLD. Block tile 32x64, 128 thr, thread 4x4.
__global__ __launch_bounds__(128) void k_head(int pp,const float* ept,const float* ebt){
    extern __shared__ float sm[];
    float* As=sm;            // [32][66]
    float* Ws=sm+32*66;      // [64][66]
    __shared__ double r1[128],r2[128];
    int mT=blockIdx.x, pT=blockIdx.y, tid=threadIdx.x;
    int beta=(mT==64);
    int row0=beta?2048:mT*32, rowsEff=beta?16:32, p0=pT*64;
    const float* W   = beta? g_W2c : g_W2n;
    const float* bias= beta? g_b2c : g_b2n;
    const float* H1=g_h[1-pp];
    const float* Sp=g_s[pp];
    float* Sn=g_s[1-pp];
    int g=tid&7, cp=(tid>>3)*4;
    ull acc[4][4];
    #pragma unroll
    for(int i=0;i<4;i++)
        #pragma unroll
        for(int j=0;j<4;j++) acc[i][j]=0ull;
    for(int kc=0;kc<2;kc++){
        int kb=kc*64;
        for(int i=tid;i<32*16;i+=128){
            int r=i>>4, c4=i&15;
            float4 v=make_float4(0.f,0.f,0.f,0.f);
            if(r<rowsEff) v=*(const float4*)(H1+(size_t)(row0+r)*DD+kb+c4*4);
            float* dst=As+r*66+c4*4;
            *(float2*)dst=make_float2(v.x,v.y);
            *(float2*)(dst+2)=make_float2(v.z,v.w);
        }
        for(int i=tid;i<64*16;i+=128){
            int r=i>>4, c4=i&15;
            float4 v=*(const float4*)(W+(size_t)(p0+r)*DD+kb+c4*4);
            float* dst=Ws+r*66+c4*4;
            *(float2*)dst=make_float2(v.x,v.y);
            *(float2*)(dst+2)=make_float2(v.z,v.w);
        }
        __syncthreads();
        const float* Ab=As+g*66;
        const float* Wb=Ws+cp*66;
        #pragma unroll 4
        for(int d2=0;d2<32;d2++){
            int off=2*d2;
            ull w0=*(const ull*)(Wb+0*66+off);
            ull w1=*(const ull*)(Wb+1*66+off);
            ull w2=*(const ull*)(Wb+2*66+off);
            ull w3=*(const ull*)(Wb+3*66+off);
            #pragma unroll
            for(int i=0;i<4;i++){
                ull x=*(const ull*)(Ab+i*8*66+off);
                acc[i][0]=ffma2(x,w0,acc[i][0]);
                acc[i][1]=ffma2(x,w1,acc[i][1]);
                acc[i][2]=ffma2(x,w2,acc[i][2]);
                acc[i][3]=ffma2(x,w3,acc[i][3]);
            }
        }
        __syncthreads();
    }
    int d0=(p0+cp)>>1;        // cols = mean_d0,std_d0,mean_{d0+1},std_{d0+1}
    float b0=bias[p0+cp],b1=bias[p0+cp+1],b2=bias[p0+cp+2],b3=bias[p0+cp+3];
    double kp=0.0,kb2=0.0;
    #pragma unroll
    for(int i=0;i<4;i++){
        int r=g+8*i;
        if(r<rowsEff){
            int row=row0+r;
            float m0=upsum(acc[i][0])+b0;
            float s0=fsoftplus(upsum(acc[i][1])+b1);
            float m1=upsum(acc[i][2])+b2;
            float s1=fsoftplus(upsum(acc[i][3])+b3);
            float p0v=Sp[(size_t)row*DD+d0], p1v=Sp[(size_t)row*DD+d0+1];
            float e0,e1;
            if(row<NN){ e0=ept[(size_t)row*DD+d0]; e1=ept[(size_t)row*DD+d0+1]; }
            else      { e0=ebt[(size_t)(row-NN)*DD+d0]; e1=ebt[(size_t)(row-NN)*DD+d0+1]; }
            Sn[(size_t)row*DD+d0]  =m0+s0*e0;
            Sn[(size_t)row*DD+d0+1]=m1+s1*e1;
            float dm0=m0-p0v, dm1=m1-p1v;
            if(row<NN){
                kp+=0.5*(-2.0*(double)logf(s0)+(double)s0*s0+(double)dm0*dm0-1.0);
                kp+=0.5*(-2.0*(double)logf(s1)+(double)s1*s1+(double)dm1*dm1-1.0);
            } else {
                kb2+=0.5*(2.0*(-2.302585092994046-(double)logf(s0))
                         +((double)s0*s0+(double)dm0*dm0)*100.0-1.0);
                kb2+=0.5*(2.0*(-2.302585092994046-(double)logf(s1))
                         +((double)s1*s1+(double)dm1*dm1)*100.0-1.0);
            }
        }
    }
    r1[tid]=kp; r2[tid]=kb2;
    __syncthreads();
    for(int o=64;o;o>>=1){ if(tid<o){ r1[tid]+=r1[tid+o]; r2[tid]+=r2[tid+o]; } __syncthreads(); }
    if(tid==0){ if(r1[0]!=0.0) atomicAdd(&g_acc[3],r1[0]);
                if(r2[0]!=0.0) atomicAdd(&g_acc[2],r2[0]); }
}

// Merged: blocks 0..7 = matM (M + Mmax), blocks 8..71 = per-edge logits/z/KL.
__global__ void k_mlog(int pp,const float* Wdec,const int* edt,const float* ut,const float* Wpi){
    int b=blockIdx.x, t=threadIdx.x, po=1-pp;
    if(b<8){
        __shared__ float bs[KK*DD];
        __shared__ float wm[8];
        if(b==0 && t<128) g_scnt[t]=0;
        for(int i=t;i<KK*DD;i+=256) bs[i]=g_s[po][NN*DD+i];
        __syncthreads();
        int n=b*256+t;
        float acc[KK];
        #pragma unroll
        for(int k=0;k<KK;k++) acc[k]=0.f;
        const float4* w4=(const float4*)(Wdec+(size_t)n*DD);
        for(int q=0;q<32;q++){ float4 w=w4[q];
            #pragma unroll
            for(int k=0;k<KK;k++){ float4 bb=((const float4*)(bs+k*DD))[q];
                acc[k]+=w.x*bb.x+w.y*bb.y+w.z*bb.z+w.w*bb.w; } }
        float mx=acc[0];
        #pragma unroll
        for(int k=0;k<KK;k++){ g_M[n*KK+k]=acc[k]; mx=fmaxf(mx,acc[k]); }
        for(int o=16;o;o>>=1) mx=fmaxf(mx,__shfl_xor_sync(0xffffffffu,mx,o));
        if((t&31)==0) wm[t>>5]=mx;
        __syncthreads();
        if(t==0){ float bb=wm[0];
            #pragma unroll
            for(int j=1;j<8;j++) bb=fmaxf(bb,wm[j]);
            atomicMaxF(&g_Mmax,bb); }
        return;
    }
    __shared__ float Pt[DD*KK];   // [d][k]
    __shared__ float Bt[DD*KK];
    __shared__ double rd[256];
    for(int i=t;i<DD*KK;i+=256){ int d=i>>4,k=i&15;
        Pt[i]=Wpi[k*DD+d]; Bt[i]=g_s[po][NN*DD+k*DD+d]; }
    __syncthreads();
    int e=(b-8)*256+t, w,c;
    if(e<EE){ w=edt[2*e]; c=edt[2*e+1]; } else { int e2=e-EE; w=edt[2*e2+1]; c=edt[2*e2]; }
    const float4* pw4=(const float4*)(g_s[po]+(size_t)w*DD);
    const float4* pc4=(const float4*)(g_s[po]+(size_t)c*DD);
    float lq[KK],lp[KK];
    #pragma unroll
    for(int k=0;k<KK;k++){ lq[k]=0.f; lp[k]=0.f; }
    for(int q=0;q<32;q++){
        float4 a=pw4[q], bb=pc4[q];
        float aw[4]={a.x,a.y,a.z,a.w};
        float pr[4]={a.x*bb.x,a.y*bb.y,a.z*bb.z,a.w*bb.w};
        #pragma unroll
        for(int j=0;j<4;j++){ int d=q*4+j;
            const float4* P4=(const float4*)(Pt+d*KK);
            const float4* B4=(const float4*)(Bt+d*KK);
            #pragma unroll
            for(int h=0;h<4;h++){
                float4 P=P4[h], B=B4[h];
                lq[4*h+0]+=pr[j]*P.x; lq[4*h+1]+=pr[j]*P.y;
                lq[4*h+2]+=pr[j]*P.z; lq[4*h+3]+=pr[j]*P.w;
                lp[4*h+0]+=aw[j]*B.x; lp[4*h+1]+=aw[j]*B.y;
                lp[4*h+2]+=aw[j]*B.z; lp[4*h+3]+=aw[j]*B.w;
            }
        }
    }
    float mq=-3e38f,mp=-3e38f;
    #pragma unroll
    for(int k=0;k<KK;k++){ mq=fmaxf(mq,lq[k]); mp=fmaxf(mp,lp[k]); }
    float sq=0,sp=0;
    #pragma unroll
    for(int k=0;k<KK;k++){ sq+=__expf(lq[k]-mq); sp+=__expf(lp[k]-mp); }
    float lsq=__logf(sq), lsp=__logf(sp), kz=0.f;
    #pragma unroll
    for(int k=0;k<KK;k++){ float lpo=lq[k]-mq-lsq;
        kz+=__expf(lpo)*(lpo-(lp[k]-mp-lsp)); }
    const float4* u4=(const float4*)(ut+(size_t)e*KK);
    float ze[KK];
    #pragma unroll
    for(int q=0;q<4;q++){ float4 u=u4[q]; float uu[4]={u.x,u.y,u.z,u.w};
        #pragma unroll
        for(int j=0;j<4;j++)
            ze[q*4+j]=lq[q*4+j]-__logf(-__logf(uu[j]+1e-10f)+1e-10f); }
    float mz=-3e38f;
    #pragma unroll
    for(int k=0;k<KK;k++) mz=fmaxf(mz,ze[k]);
    float sz=0;
    #pragma unroll
    for(int k=0;k<KK;k++){ ze[k]=__expf(ze[k]-mz); sz+=ze[k]; }
    float inv=L2E/sz;                 // z scaled by log2(e)
    float4* zo=(float4*)(g_Z+(size_t)e*KK);
    #pragma unroll
    for(int q=0;q<4;q++){
        float4 v; v.x=ze[q*4]*inv; v.y=ze[q*4+1]*inv;
        v.z=ze[q*4+2]*inv; v.w=ze[q*4+3]*inv; zo[q]=v; }
    g_cE[e]=c; g_sE[e]=0.f;
    rd[t]=(double)kz; __syncthreads();
    for(int o=128;o;o>>=1){ if(t<o) rd[t]+=rd[t+o]; __syncthreads(); }
    if(t==0) atomicAdd(&g_acc[1],rd[0]);
}

// N-scan: 2 edges/thread (M row loaded once, used twice), log2 domain.
__global__ __launch_bounds__(256) void k_scan(){
    __shared__ float Ms[512*KK];
    __shared__ float Zs[128*KK];
    __shared__ float sA[256], sB[256];
    __shared__ double rd[256];
    __shared__ int s_old;
    int tid=threadIdx.x;
    int n0=blockIdx.y*512, e0=blockIdx.x*128;
    for(int i=tid;i<512*KK;i+=256) Ms[i]=g_M[n0*KK+i];
    for(int i=tid;i<128*KK;i+=256) Zs[i]=g_Z[(size_t)e0*KK+i];
    __syncthreads();
    int li=tid&63, sub=tid>>6;       // 64 edge-pairs x 4 n-quarters
    ull za[8], zb[8];
    {   const ull* z8=(const ull*)(Zs+(2*li)*KK);
        #pragma unroll
        for(int q=0;q<8;q++) za[q]=z8[q];
        const ull* z9=(const ull*)(Zs+(2*li+1)*KK);
        #pragma unroll
        for(int q=0;q<8;q++) zb[q]=z9[q]; }
    float Mx2=g_Mmax*L2E;
    ull seed=pack2(-Mx2,0.f);
    float s0=0.f,s1=0.f;
    const float* Mb=Ms+(sub*128)*KK;
    #pragma unroll 2
    for(int j=0;j<128;j++){
        const ulonglong2* m0=(const ulonglong2*)(Mb+j*KK);
        ulonglong2 A0=m0[0],A1=m0[1],A2=m0[2],A3=m0[3];
        ull ta=ffma2(za[0],A0.x,seed); ull tb=ffma2(za[1],A0.y,0ull);
        ta=ffma2(za[2],A1.x,ta);       tb=ffma2(za[3],A1.y,tb);
        ta=ffma2(za[4],A2.x,ta);       tb=ffma2(za[5],A2.y,tb);
        ta=ffma2(za[6],A3.x,ta);       tb=ffma2(za[7],A3.y,tb);
        ull tc=ffma2(zb[0],A0.x,seed); ull td=ffma2(zb[1],A0.y,0ull);
        tc=ffma2(zb[2],A1.x,tc);       td=ffma2(zb[3],A1.y,td);
        tc=ffma2(zb[4],A2.x,tc);       td=ffma2(zb[5],A2.y,td);
        tc=ffma2(zb[6],A3.x,tc);       td=ffma2(zb[7],A3.y,td);
        s0+=fex2(upsum(fadd2(ta,tb)));
        s1+=fex2(upsum(fadd2(tc,td)));
    }
    sA[tid]=s0; sB[tid]=s1;
    __syncthreads();
    if(tid<128){
        int lie=tid>>1;
        const float* arr=(tid&1)? sB : sA;
        float st=(arr[lie]+arr[64+lie])+(arr[128+lie]+arr[192+lie]);
        atomicAdd(&g_sE[e0+tid],st);
    }
    __threadfence();
    __syncthreads();
    if(tid==0) s_old=atomicAdd(&g_scnt[blockIdx.x],1);
    __syncthreads();
    if(s_old==3){
        __threadfence();
        double nll=0.0;
        if(tid<128){
            int ee=e0+tid;
            int c=g_cE[ee];
            const float4* mc=(const float4*)(g_M+(size_t)c*KK);
            const float4* zz=(const float4*)(Zs+tid*KK);
            float vc2=0.f;
            #pragma unroll
            for(int q=0;q<4;q++){ float4 z=zz[q], m=mc[q];
                vc2+=z.x*m.x+z.y*m.y+z.z*m.z+z.w*m.w; }
            float vc=vc2*LN2;                       // undo log2e scaling
            nll=(double)(-(vc-g_Mmax-__logf(g_sE[ee])));
        }
        rd[tid]=nll; __syncthreads();
        for(int o=128;o;o>>=1){ if(tid<o) rd[tid]+=rd[tid+o]; __syncthreads(); }
        if(tid==0) atomicAdd(&g_acc[0],rd[0]);
    }
}

__global__ void k_out(float* out){
    out[0]=(float)(g_acc[0]/CNT);
    out[1]=(float)(g_acc[1]/CNT);
    out[2]=(float)(16.0*g_acc[4]/CNT);
    out[3]=(float)(g_acc[2]/CNT);
    out[4]=(float)(g_acc[3]/CNT);
}

extern "C" void kernel_launch(void* const* d_in,const int* in_sizes,int n_in,
                              void* d_out,int out_size){
    const int*   edges=(const int*)d_in[0];
    const int*   sidx =(const int*)d_in[1];
    const float* epp  =(const float*)d_in[2];
    const float* epb  =(const float*)d_in[3];
    const float* ug   =(const float*)d_in[4];
    const float* amean=(const float*)d_in[5];
    const float* astd =(const float*)d_in[6];
    const float* Ws2p =(const float*)d_in[7];  const float* bs2p=(const float*)d_in[8];
    const float* Ws2b =(const float*)d_in[9];  const float* bs2b=(const float*)d_in[10];
    const float* Wbm  =(const float*)d_in[11]; const float* bbm =(const float*)d_in[12];
    const float* Wbs  =(const float*)d_in[13]; const float* bbs =(const float*)d_in[14];
    const float* Wpm  =(const float*)d_in[15]; const float* bpm =(const float*)d_in[16];
    const float* Wps  =(const float*)d_in[17]; const float* bps =(const float*)d_in[18];
    const float* Wpi  =(const float*)d_in[19];
    const float* WihN =(const float*)d_in[20]; const float* WhhN=(const float*)d_in[21];
    const float* bihN =(const float*)d_in[22]; const float* bhhN=(const float*)d_in[23];
    const float* WihC =(const float*)d_in[24]; const float* WhhC=(const float*)d_in[25];
    const float* bihC =(const float*)d_in[26]; const float* bhhC=(const float*)d_in[27];
    const float* Wdec =(const float*)d_in[28];
    float* out=(float*)d_out;

    int smemG = (32*66+128*66)*4;     // 42240
    int smemH = (32*66+64*66)*4;      // 25344
    cudaFuncSetAttribute(k_gru, cudaFuncAttributeMaxDynamicSharedMemorySize,smemG);
    cudaFuncSetAttribute(k_head,cudaFuncAttributeMaxDynamicSharedMemorySize,smemH);

    k_init0<<<1,128>>>(sidx,amean,astd);
    k_initW<<<644,256>>>(WihN,WhhN,bihN,bhhN,WihC,WhhC,bihC,bhhC,
                         Wpm,bpm,Wps,bps,Wbm,bbm,Wbs,bbs);
    k_initS<<<1033,256>>>(Ws2p,bs2p,Ws2b,bs2b);
    for(int t=0;t<16;t++){
        int pp=t&1;
        k_gru<<<dim3(65,4),256,smemG>>>(pp);
        k_head<<<dim3(65,4),128,smemH>>>(pp, epp+(size_t)t*NN*DD, epb+(size_t)t*KK*DD);
        k_mlog<<<72,256>>>(pp, Wdec, edges+(size_t)t*EE*2,
                           ug+(size_t)t*2*EE*KK, Wpi);
        k_scan<<<dim3(128,4),256>>>();
    }
    k_out<<<1,1>>>(out);
}

// round 17
// speedup vs baseline: 3.9715x; 1.2075x over previous
#include <cuda_runtime.h>
#include <math.h>

#define NN 2048
#define DD 128
#define KK 16
#define EE 8192
#define TWOE 16384
#define ROWS 2064               // 2048 phi rows + 16 beta rows
#define CNT 262144.0
#define L2E 1.4426950408889634f
#define LN2 0.6931471805599453f

typedef unsigned long long ull;
typedef unsigned int uint;

__device__ float g_s[2][ROWS*DD];     // phi_s rows 0..2047, beta_s rows 2048..2063
__device__ float g_h[2][ROWS*DD];
__device__ float g_M[NN*KK];          // n-major, k contiguous
__device__ float g_Z[TWOE*KK];        // z * log2(e)
__device__ float g_sE[TWOE];
__device__ int   g_cE[TWOE];
__device__ int   g_scnt[128];
__device__ float g_W1n[512*256], g_W1c[512*256];   // rows interleaved 4d+{r,z,in,hn}
__device__ float g_b1n[512],     g_b1c[512];
__device__ float g_W2n[256*DD],  g_W2c[256*DD];    // rows interleaved 2d+{mean,std}
__device__ float g_b2n[256],     g_b2c[256];
__device__ float g_am[DD];
__device__ double g_acc[5];           // nll, kldz, kldb, kldp, kld_alpha
__device__ float g_Mmax;

__device__ __forceinline__ float fsig(float x){ return 1.f/(1.f+__expf(-x)); }
__device__ __forceinline__ float ftanh(float x){
    float e=__expf(fminf(fmaxf(2.f*x,-30.f),30.f)); return (e-1.f)/(e+1.f); }
__device__ __forceinline__ float fsoftplus(float x){
    return fmaxf(x,0.f)+log1pf(__expf(-fabsf(x))); }
__device__ __forceinline__ void atomicMaxF(float* a, float v){
    int cur=__float_as_int(*a);
    while(__int_as_float(cur)<v){ int as=cur;
        cur=atomicCAS((int*)a,as,__float_as_int(v));
        if(cur==as) break; }
}
__device__ __forceinline__ ull ffma2(ull a, ull b, ull c){
    asm("fma.rn.f32x2 %0,%1,%2,%3;":"=l"(c):"l"(a),"l"(b),"l"(c));
    return c;
}
__device__ __forceinline__ float fex2(float x){
    float r; asm("ex2.approx.f32 %0,%1;":"=f"(r):"f"(x));
    return r;
}
__device__ __forceinline__ float upsum(ull v){
    float lo,hi; asm("mov.b64 {%0,%1},%2;":"=f"(lo),"=f"(hi):"l"(v));
    return lo+hi;
}
__device__ __forceinline__ uint ftf32(float f){
    uint u; asm("cvt.rna.tf32.f32 %0,%1;":"=r"(u):"f"(f));
    return u;
}
__device__ __forceinline__ void mma_tf32(float&c0,float&c1,float&c2,float&c3,
    uint a0,uint a1,uint a2,uint a3,uint b0,uint b1){
    asm("mma.sync.aligned.m16n8k8.row.col.f32.tf32.tf32.f32 "
        "{%0,%1,%2,%3},{%4,%5,%6,%7},{%8,%9},{%0,%1,%2,%3};"
        : "+f"(c0),"+f"(c1),"+f"(c2),"+f"(c3)
        : "r"(a0),"r"(a1),"r"(a2),"r"(a3),"r"(b0),"r"(b1));
}

__global__ void k_init0(const int* sidx,const float* am,const float* as){
    int t=threadIdx.x; int s=sidx[0];
    __shared__ float red[128];
    float m=am[(size_t)s*DD+t];
    float sd=fsoftplus(as[(size_t)s*DD+t]);
    g_am[t]=m;
    red[t]=0.5f*(-2.f*logf(sd)+sd*sd+m*m-1.f);
    __syncthreads();
    for(int o=64;o;o>>=1){ if(t<o) red[t]+=red[t+o]; __syncthreads(); }
    if(t==0){ g_acc[4]=(double)red[0]; g_acc[0]=g_acc[1]=g_acc[2]=g_acc[3]=0.0; }
}

__global__ void k_initW(const float* WihN,const float* WhhN,const float* bihN,const float* bhhN,
                        const float* WihC,const float* WhhC,const float* bihC,const float* bhhC,
                        const float* Wpm,const float* bpm,const float* Wps,const float* bps,
                        const float* Wbm,const float* bbm,const float* Wbs,const float* bbs){
    int i=blockIdx.x*256+threadIdx.x;
    if(i<131072){                                  // W1: row j'=4d+gate, 512 x 256
        int j=i>>8, c=i&255;
        int d=j>>2, gate=j&3;
        float vn,vc;
        if(gate==0||gate==1){
            int jr=gate*128+d;
            if(c<128){ vn=WihN[jr*256+c]+WihN[jr*256+128+c];
                       vc=WihC[jr*256+c]+WihC[jr*256+128+c]; }
            else     { vn=WhhN[jr*128+c-128]; vc=WhhC[jr*128+c-128]; }
        } else if(gate==2){
            int jr=256+d;
            if(c<128){ vn=WihN[jr*256+c]+WihN[jr*256+128+c];
                       vc=WihC[jr*256+c]+WihC[jr*256+128+c]; }
            else     { vn=0.f; vc=0.f; }
        } else {
            int jr=256+d;
            if(c<128){ vn=0.f; vc=0.f; }
            else     { vn=WhhN[jr*128+c-128]; vc=WhhC[jr*128+c-128]; }
        }
        g_W1n[i]=vn; g_W1c[i]=vc;
    } else if(i<163840){                           // W2: row j'=2d+m, 256 x 128
        int o=i-131072, j=o>>7, c=o&127;
        int d=j>>1, m=j&1;
        g_W2n[o] = m==0 ? Wpm[d*128+c] : Wps[d*128+c];
        g_W2c[o] = m==0 ? Wbm[d*128+c] : Wbs[d*128+c];
    } else if(i<164352){                           // b1
        int j=i-163840; int d=j>>2, gate=j&3; float bn,bc;
        if(gate==0||gate==1){ int jr=gate*128+d;
            bn=bihN[jr]+bhhN[jr]; bc=bihC[jr]+bhhC[jr]; }
        else if(gate==2){ bn=bihN[256+d]; bc=bihC[256+d]; }
        else            { bn=bhhN[256+d]; bc=bhhC[256+d]; }
        g_b1n[j]=bn; g_b1c[j]=bc;
    } else if(i<164608){                           // b2
        int j=i-164352; int d=j>>1, m=j&1;
        g_b2n[j] = m==0 ? bpm[d] : bps[d];
        g_b2c[j] = m==0 ? bbm[d] : bbs[d];
    }
}

__global__ void k_initS(const float* Wp,const float* bp,const float* Wb,const float* bb){
    __shared__ float am[DD];
    int tid=threadIdx.x;
    if(tid<DD) am[tid]=g_am[tid];
    __syncthreads();
    int i=blockIdx.x*256+tid; if(i>=ROWS*DD) return;
    const float* wr; float bias;
    if(i<NN*DD){ wr=Wp+(size_t)i*DD; bias=bp[i]; }
    else { int o=i-NN*DD; wr=Wb+(size_t)o*DD; bias=bb[o]; }
    const float4* w4=(const float4*)wr; const float4* a4=(const float4*)am;
    float acc=bias;
    #pragma unroll 8
    for(int q=0;q<32;q++){ float4 w=w4[q],a=a4[q];
        acc+=w.x*a.x+w.y*a.y+w.z*a.z+w.w*a.w; }
    g_s[0][i]=acc; g_h[0][i]=0.f;
}

// GRU GEMM + fused activation. Block tile 32x128, 256 thr, thread tile 4x4.
__global__ __launch_bounds__(256) void k_gru(int pp){
    extern __shared__ float sm[];
    float* As=sm;            // [32][66]
    float* Ws=sm+32*66;      // [128][66]
    int mT=blockIdx.x, pT=blockIdx.y, tid=threadIdx.x;
    if(mT==0&&pT==0&&tid==0) g_Mmax=-1e30f;
    int beta=(mT==64);
    int row0=beta?2048:mT*32, rowsEff=beta?16:32, p0=pT*128;
    const float* W   = beta? g_W1c : g_W1n;
    const float* bias= beta? g_b1c : g_b1n;
    const float* S0=g_s[pp]; const float* H0=g_h[pp];
    float* H1=g_h[1-pp];
    int g=tid&7, cp=(tid>>3)*4;
    ull acc[4][4];
    #pragma unroll
    for(int i=0;i<4;i++)
        #pragma unroll
        for(int j=0;j<4;j++) acc[i][j]=0ull;
    for(int kc=0;kc<4;kc++){
        const float* src = kc<2 ? S0 : H0;
        int kb=(kc&1)*64;
        for(int i=tid;i<32*16;i+=256){
            int r=i>>4, c4=i&15;
            float4 v=make_float4(0.f,0.f,0.f,0.f);
            if(r<rowsEff) v=*(const float4*)(src+(size_t)(row0+r)*DD+kb+c4*4);
            float* dst=As+r*66+c4*4;
            *(float2*)dst=make_float2(v.x,v.y);
            *(float2*)(dst+2)=make_float2(v.z,v.w);
        }
        for(int i=tid;i<128*16;i+=256){
            int r=i>>4, c4=i&15;
            float4 v=*(const float4*)(W+(size_t)(p0+r)*256+kc*64+c4*4);
            float* dst=Ws+r*66+c4*4;
            *(float2*)dst=make_float2(v.x,v.y);
            *(float2*)(dst+2)=make_float2(v.z,v.w);
        }
        __syncthreads();
        const float* Ab=As+g*66;
        const float* Wb=Ws+cp*66;
        #pragma unroll 4
        for(int d2=0;d2<32;d2++){
            int off=2*d2;
            ull w0=*(const ull*)(Wb+0*66+off);
            ull w1=*(const ull*)(Wb+1*66+off);
            ull w2=*(const ull*)(Wb+2*66+off);
            ull w3=*(const ull*)(Wb+3*66+off);
            #pragma unroll
            for(int i=0;i<4;i++){
                ull x=*(const ull*)(Ab+i*8*66+off);
                acc[i][0]=ffma2(x,w0,acc[i][0]);
                acc[i][1]=ffma2(x,w1,acc[i][1]);
                acc[i][2]=ffma2(x,w2,acc[i][2]);
                acc[i][3]=ffma2(x,w3,acc[i][3]);
            }
        }
        __syncthreads();
    }
    int d=(p0+cp)>>2;
    float b0=bias[p0+cp],b1=bias[p0+cp+1],b2=bias[p0+cp+2],b3=bias[p0+cp+3];
    #pragma unroll
    for(int i=0;i<4;i++){
        int r=g+8*i;
        if(r<rowsEff){
            int row=row0+r;
            float q0=upsum(acc[i][0])+b0;
            float q1=upsum(acc[i][1])+b1;
            float q2=upsum(acc[i][2])+b2;
            float q3=upsum(acc[i][3])+b3;
            float rg=fsig(q0), zg=fsig(q1);
            float nn=ftanh(q2+rg*q3);
            float hold=H0[(size_t)row*DD+d];
            H1[(size_t)row*DD+d]=(1.f-zg)*nn+zg*hold;
        }
    }
}

// Head GEMM + fused sampling + KLD. Block tile 32x64, 128 thr, thread 4x4.
__global__ __launch_bounds__(128) void k_head(int pp,const float* ept,const float* ebt){
    extern __shared__ float sm[];
    float* As=sm;            // [32][66]
    float* Ws=sm+32*66;      // [64][66]
    __shared__ double r1[128],r2[128];
    int mT=blockIdx.x, pT=blockIdx.y, tid=threadIdx.x;
    int beta=(mT==64);
    int row0=beta?2048:mT*32, rowsEff=beta?16:32, p0=pT*64;
    const float* W   = beta? g_W2c : g_W2n;
    const float* bias= beta? g_b2c : g_b2n;
    const float* H1=g_h[1-pp];
    const float* Sp=g_s[pp];
    float* Sn=g_s[1-pp];
    int g=tid&7, cp=(tid>>3)*4;
    ull acc[4][4];
    #pragma unroll
    for(int i=0;i<4;i++)
        #pragma unroll
        for(int j=0;j<4;j++) acc[i][j]=0ull;
    for(int kc=0;kc<2;kc++){
        int kb=kc*64;
        for(int i=tid;i<32*16;i+=128){
            int r=i>>4, c4=i&15;
            float4 v=make_float4(0.f,0.f,0.f,0.f);
            if(r<rowsEff) v=*(const float4*)(H1+(size_t)(row0+r)*DD+kb+c4*4);
            float* dst=As+r*66+c4*4;
            *(float2*)dst=make_float2(v.x,v.y);
            *(float2*)(dst+2)=make_float2(v.z,v.w);
        }
        for(int i=tid;i<64*16;i+=128){
            int r=i>>4, c4=i&15;
            float4 v=*(const float4*)(W+(size_t)(p0+r)*DD+kb+c4*4);
            float* dst=Ws+r*66+c4*4;
            *(float2*)dst=make_float2(v.x,v.y);
            *(float2*)(dst+2)=make_float2(v.z,v.w);
        }
        __syncthreads();
        const float* Ab=As+g*66;
        const float* Wb=Ws+cp*66;
        #pragma unroll 4
        for(int d2=0;d2<32;d2++){
            int off=2*d2;
            ull w0=*(const ull*)(Wb+0*66+off);
            ull w1=*(const ull*)(Wb+1*66+off);
            ull w2=*(const ull*)(Wb+2*66+off);
            ull w3=*(const ull*)(Wb+3*66+off);
            #pragma unroll
            for(int i=0;i<4;i++){
                ull x=*(const ull*)(Ab+i*8*66+off);
                acc[i][0]=ffma2(x,w0,acc[i][0]);
                acc[i][1]=ffma2(x,w1,acc[i][1]);
                acc[i][2]=ffma2(x,w2,acc[i][2]);
                acc[i][3]=ffma2(x,w3,acc[i][3]);
            }
        }
        __syncthreads();
    }
    int d0=(p0+cp)>>1;        // cols = mean_d0,std_d0,mean_{d0+1},std_{d0+1}
    float b0=bias[p0+cp],b1=bias[p0+cp+1],b2=bias[p0+cp+2],b3=bias[p0+cp+3];
    double kp=0.0,kb2=0.0;
    #pragma unroll
    for(int i=0;i<4;i++){
        int r=g+8*i;
        if(r<rowsEff){
            int row=row0+r;
            float m0=upsum(acc[i][0])+b0;
            float s0=fsoftplus(upsum(acc[i][1])+b1);
            float m1=upsum(acc[i][2])+b2;
            float s1=fsoftplus(upsum(acc[i][3])+b3);
            float p0v=Sp[(size_t)row*DD+d0], p1v=Sp[(size_t)row*DD+d0+1];
            float e0,e1;
            if(row<NN){ e0=ept[(size_t)row*DD+d0]; e1=ept[(size_t)row*DD+d0+1]; }
            else      { e0=ebt[(size_t)(row-NN)*DD+d0]; e1=ebt[(size_t)(row-NN)*DD+d0+1]; }
            Sn[(size_t)row*DD+d0]  =m0+s0*e0;
            Sn[(size_t)row*DD+d0+1]=m1+s1*e1;
            float dm0=m0-p0v, dm1=m1-p1v;
            if(row<NN){
                kp+=0.5*(-2.0*(double)logf(s0)+(double)s0*s0+(double)dm0*dm0-1.0);
                kp+=0.5*(-2.0*(double)logf(s1)+(double)s1*s1+(double)dm1*dm1-1.0);
            } else {
                kb2+=0.5*(2.0*(-2.302585092994046-(double)logf(s0))
                         +((double)s0*s0+(double)dm0*dm0)*100.0-1.0);
                kb2+=0.5*(2.0*(-2.302585092994046-(double)logf(s1))
                         +((double)s1*s1+(double)dm1*dm1)*100.0-1.0);
            }
        }
    }
    r1[tid]=kp; r2[tid]=kb2;
    __syncthreads();
    for(int o=64;o;o>>=1){ if(tid<o){ r1[tid]+=r1[tid+o]; r2[tid]+=r2[tid+o]; } __syncthreads(); }
    if(tid==0){ if(r1[0]!=0.0) atomicAdd(&g_acc[3],r1[0]);
                if(r2[0]!=0.0) atomicAdd(&g_acc[2],r2[0]); }
}

// Merged: blocks 0..7 = matM (M + Mmax), blocks 8..71 = per-edge logits/z/KL.
__global__ void k_mlog(int pp,const float* Wdec,const int* edt,const float* ut,const float* Wpi){
    int b=blockIdx.x, t=threadIdx.x, po=1-pp;
    if(b<8){
        __shared__ float bs[KK*DD];
        __shared__ float wm[8];
        if(b==0 && t<128) g_scnt[t]=0;
        for(int i=t;i<KK*DD;i+=256) bs[i]=g_s[po][NN*DD+i];
        __syncthreads();
        int n=b*256+t;
        float acc[KK];
        #pragma unroll
        for(int k=0;k<KK;k++) acc[k]=0.f;
        const float4* w4=(const float4*)(Wdec+(size_t)n*DD);
        for(int q=0;q<32;q++){ float4 w=w4[q];
            #pragma unroll
            for(int k=0;k<KK;k++){ float4 bb=((const float4*)(bs+k*DD))[q];
                acc[k]+=w.x*bb.x+w.y*bb.y+w.z*bb.z+w.w*bb.w; } }
        float mx=acc[0];
        #pragma unroll
        for(int k=0;k<KK;k++){ g_M[n*KK+k]=acc[k]; mx=fmaxf(mx,acc[k]); }
        for(int o=16;o;o>>=1) mx=fmaxf(mx,__shfl_xor_sync(0xffffffffu,mx,o));
        if((t&31)==0) wm[t>>5]=mx;
        __syncthreads();
        if(t==0){ float bb=wm[0];
            #pragma unroll
            for(int j=1;j<8;j++) bb=fmaxf(bb,wm[j]);
            atomicMaxF(&g_Mmax,bb); }
        return;
    }
    __shared__ float Pt[DD*KK];   // [d][k]
    __shared__ float Bt[DD*KK];
    __shared__ double rd[256];
    for(int i=t;i<DD*KK;i+=256){ int d=i>>4,k=i&15;
        Pt[i]=Wpi[k*DD+d]; Bt[i]=g_s[po][NN*DD+k*DD+d]; }
    __syncthreads();
    int e=(b-8)*256+t, w,c;
    if(e<EE){ w=edt[2*e]; c=edt[2*e+1]; } else { int e2=e-EE; w=edt[2*e2+1]; c=edt[2*e2]; }
    const float4* pw4=(const float4*)(g_s[po]+(size_t)w*DD);
    const float4* pc4=(const float4*)(g_s[po]+(size_t)c*DD);
    float lq[KK],lp[KK];
    #pragma unroll
    for(int k=0;k<KK;k++){ lq[k]=0.f; lp[k]=0.f; }
    for(int q=0;q<32;q++){
        float4 a=pw4[q], bb=pc4[q];
        float aw[4]={a.x,a.y,a.z,a.w};
        float pr[4]={a.x*bb.x,a.y*bb.y,a.z*bb.z,a.w*bb.w};
        #pragma unroll
        for(int j=0;j<4;j++){ int d=q*4+j;
            const float4* P4=(const float4*)(Pt+d*KK);
            const float4* B4=(const float4*)(Bt+d*KK);
            #pragma unroll
            for(int h=0;h<4;h++){
                float4 P=P4[h], B=B4[h];
                lq[4*h+0]+=pr[j]*P.x; lq[4*h+1]+=pr[j]*P.y;
                lq[4*h+2]+=pr[j]*P.z; lq[4*h+3]+=pr[j]*P.w;
                lp[4*h+0]+=aw[j]*B.x; lp[4*h+1]+=aw[j]*B.y;
                lp[4*h+2]+=aw[j]*B.z; lp[4*h+3]+=aw[j]*B.w;
            }
        }
    }
    float mq=-3e38f,mp=-3e38f;
    #pragma unroll
    for(int k=0;k<KK;k++){ mq=fmaxf(mq,lq[k]); mp=fmaxf(mp,lp[k]); }
    float sq=0,sp=0;
    #pragma unroll
    for(int k=0;k<KK;k++){ sq+=__expf(lq[k]-mq); sp+=__expf(lp[k]-mp); }
    float lsq=__logf(sq), lsp=__logf(sp), kz=0.f;
    #pragma unroll
    for(int k=0;k<KK;k++){ float lpo=lq[k]-mq-lsq;
        kz+=__expf(lpo)*(lpo-(lp[k]-mp-lsp)); }
    const float4* u4=(const float4*)(ut+(size_t)e*KK);
    float ze[KK];
    #pragma unroll
    for(int q=0;q<4;q++){ float4 u=u4[q]; float uu[4]={u.x,u.y,u.z,u.w};
        #pragma unroll
        for(int j=0;j<4;j++)
            ze[q*4+j]=lq[q*4+j]-__logf(-__logf(uu[j]+1e-10f)+1e-10f); }
    float mz=-3e38f;
    #pragma unroll
    for(int k=0;k<KK;k++) mz=fmaxf(mz,ze[k]);
    float sz=0;
    #pragma unroll
    for(int k=0;k<KK;k++){ ze[k]=__expf(ze[k]-mz); sz+=ze[k]; }
    float inv=L2E/sz;                 // z scaled by log2(e)
    float4* zo=(float4*)(g_Z+(size_t)e*KK);
    #pragma unroll
    for(int q=0;q<4;q++){
        float4 v; v.x=ze[q*4]*inv; v.y=ze[q*4+1]*inv;
        v.z=ze[q*4+2]*inv; v.w=ze[q*4+3]*inv; zo[q]=v; }
    g_cE[e]=c; g_sE[e]=0.f;
    rd[t]=(double)kz; __syncthreads();
    for(int o=128;o;o>>=1){ if(t<o) rd[t]+=rd[t+o]; __syncthreads(); }
    if(t==0) atomicAdd(&g_acc[1],rd[0]);
}

// N-scan via tensor cores: warp = 16-edge tile x 512 n, mma.m16n8k8 tf32.
// Row sums only -> C fragment column layout irrelevant; vc stays exact fp32.
__global__ __launch_bounds__(256) void k_scan(){
    __shared__ float Ms[512*KK];
    __shared__ float Zs[128*KK];
    __shared__ double rd[256];
    __shared__ int s_old;
    int tid=threadIdx.x;
    int n0=blockIdx.y*512, e0=blockIdx.x*128;
    for(int i=tid;i<512*KK;i+=256) Ms[i]=g_M[n0*KK+i];
    for(int i=tid;i<128*KK;i+=256) Zs[i]=g_Z[(size_t)e0*KK+i];
    __syncthreads();
    int wp=tid>>5, lane=tid&31;
    int gq=lane>>2, tq=lane&3;
    // A fragments (Z tile of this warp), both k-halves
    const float* Za=Zs+(wp*16)*KK;
    uint a00=ftf32(Za[(gq  )*KK+tq  ]), a01=ftf32(Za[(gq+8)*KK+tq  ]);
    uint a02=ftf32(Za[(gq  )*KK+tq+4]), a03=ftf32(Za[(gq+8)*KK+tq+4]);
    uint a10=ftf32(Za[(gq  )*KK+tq+8]), a11=ftf32(Za[(gq+8)*KK+tq+8]);
    uint a12=ftf32(Za[(gq  )*KK+tq+12]),a13=ftf32(Za[(gq+8)*KK+tq+12]);
    float Mx2=g_Mmax*L2E;
    float sLo=0.f,sHi=0.f;
    #pragma unroll 2
    for(int nt=0;nt<64;nt++){
        const float* Mb=Ms+(nt*8)*KK;
        uint b00=ftf32(Mb[gq*KK+tq   ]), b01=ftf32(Mb[gq*KK+tq+4 ]);
        uint b10=ftf32(Mb[gq*KK+tq+8 ]), b11=ftf32(Mb[gq*KK+tq+12]);
        float c0=-Mx2,c1=-Mx2,c2=-Mx2,c3=-Mx2;
        mma_tf32(c0,c1,c2,c3,a00,a01,a02,a03,b00,b01);
        mma_tf32(c0,c1,c2,c3,a10,a11,a12,a13,b10,b11);
        sLo+=fex2(c0)+fex2(c1);
        sHi+=fex2(c2)+fex2(c3);
    }
    sLo+=__shfl_xor_sync(0xffffffffu,sLo,1);
    sLo+=__shfl_xor_sync(0xffffffffu,sLo,2);
    sHi+=__shfl_xor_sync(0xffffffffu,sHi,1);
    sHi+=__shfl_xor_sync(0xffffffffu,sHi,2);
    if(tq==0){
        atomicAdd(&g_sE[e0+wp*16+gq],  sLo);
        atomicAdd(&g_sE[e0+wp*16+8+gq],sHi);
    }
    __threadfence();
    __syncthreads();
    if(tid==0) s_old=atomicAdd(&g_scnt[blockIdx.x],1);
    __syncthreads();
    if(s_old==3){
        __threadfence();
        double nll=0.0;
        if(tid<128){
            int ee=e0+tid;
            int c=g_cE[ee];
            const float4* mc=(const float4*)(g_M+(size_t)c*KK);
            const float4* zz=(const float4*)(Zs+tid*KK);
            float vc2=0.f;
            #pragma unroll
            for(int q=0;q<4;q++){ float4 z=zz[q], m=mc[q];
                vc2+=z.x*m.x+z.y*m.y+z.z*m.z+z.w*m.w; }
            float vc=vc2*LN2;                       // undo log2e scaling
            nll=(double)(-(vc-g_Mmax-__logf(g_sE[ee])));
        }
        rd[tid]=nll; __syncthreads();
        for(int o=128;o;o>>=1){ if(tid<o) rd[tid]+=rd[tid+o]; __syncthreads(); }
        if(tid==0) atomicAdd(&g_acc[0],rd[0]);
    }
}

__global__ void k_out(float* out){
    out[0]=(float)(g_acc[0]/CNT);
    out[1]=(float)(g_acc[1]/CNT);
    out[2]=(float)(16.0*g_acc[4]/CNT);
    out[3]=(float)(g_acc[2]/CNT);
    out[4]=(float)(g_acc[3]/CNT);
}

extern "C" void kernel_launch(void* const* d_in,const int* in_sizes,int n_in,
                              void* d_out,int out_size){
    const int*   edges=(const int*)d_in[0];
    const int*   sidx =(const int*)d_in[1];
    const float* epp  =(const float*)d_in[2];
    const float* epb  =(const float*)d_in[3];
    const float* ug   =(const float*)d_in[4];
    const float* amean=(const float*)d_in[5];
    const float* astd =(const float*)d_in[6];
    const float* Ws2p =(const float*)d_in[7];  const float* bs2p=(const float*)d_in[8];
    const float* Ws2b =(const float*)d_in[9];  const float* bs2b=(const float*)d_in[10];
    const float* Wbm  =(const float*)d_in[11]; const float* bbm =(const float*)d_in[12];
    const float* Wbs  =(const float*)d_in[13]; const float* bbs =(const float*)d_in[14];
    const float* Wpm  =(const float*)d_in[15]; const float* bpm =(const float*)d_in[16];
    const float* Wps  =(const float*)d_in[17]; const float* bps =(const float*)d_in[18];
    const float* Wpi  =(const float*)d_in[19];
    const float* WihN =(const float*)d_in[20]; const float* WhhN=(const float*)d_in[21];
    const float* bihN =(const float*)d_in[22]; const float* bhhN=(const float*)d_in[23];
    const float* WihC =(const float*)d_in[24]; const float* WhhC=(const float*)d_in[25];
    const float* bihC =(const float*)d_in[26]; const float* bhhC=(const float*)d_in[27];
    const float* Wdec =(const float*)d_in[28];
    float* out=(float*)d_out;

    int smemG = (32*66+128*66)*4;     // 42240
    int smemH = (32*66+64*66)*4;      // 25344
    cudaFuncSetAttribute(k_gru, cudaFuncAttributeMaxDynamicSharedMemorySize,smemG);
    cudaFuncSetAttribute(k_head,cudaFuncAttributeMaxDynamicSharedMemorySize,smemH);

    k_init0<<<1,128>>>(sidx,amean,astd);
    k_initW<<<644,256>>>(WihN,WhhN,bihN,bhhN,WihC,WhhC,bihC,bhhC,
                         Wpm,bpm,Wps,bps,Wbm,bbm,Wbs,bbs);
    k_initS<<<1033,256>>>(Ws2p,bs2p,Ws2b,bs2b);
    for(int t=0;t<16;t++){
        int pp=t&1;
        k_gru<<<dim3(65,4),256,smemG>>>(pp);
        k_head<<<dim3(65,4),128,smemH>>>(pp, epp+(size_t)t*NN*DD, epb+(size_t)t*KK*DD);
        k_mlog<<<72,256>>>(pp, Wdec, edges+(size_t)t*EE*2,
                           ug+(size_t)t*2*EE*KK, Wpi);
        k_scan<<<dim3(128,4),256>>>();
    }
    k_out<<<1,1>>>(out);
}